// round 5
// baseline (speedup 1.0000x reference)
#include <cuda_runtime.h>
#include <cuda_bf16.h>
#include <math.h>
#include <stdint.h>

#define NROWS 65536
#define DD    512
#define NSPLIT 16
static __device__ __constant__ float kInvTemp = 0.1f;

typedef unsigned long long u64;
typedef __nv_bfloat16 bf16;

// ---------------------------------------------------------------------------
// helpers
// ---------------------------------------------------------------------------
__device__ __forceinline__ uint32_t smem_u32(const void* p) {
    uint32_t a;
    asm("{ .reg .u64 t; cvta.to.shared.u64 t, %1; cvt.u32.u64 %0, t; }"
        : "=r"(a) : "l"(p));
    return a;
}
__device__ __forceinline__ void cp16(uint32_t dst, const void* src) {
    asm volatile("cp.async.cg.shared.global [%0], [%1], 16;"
                 :: "r"(dst), "l"(src) : "memory");
}
__device__ __forceinline__ void mma16816(float* c, const uint32_t* a,
                                         const uint32_t* b) {
    asm volatile(
        "mma.sync.aligned.m16n8k16.row.col.f32.bf16.bf16.f32 "
        "{%0,%1,%2,%3}, {%4,%5,%6,%7}, {%8,%9}, {%0,%1,%2,%3};"
        : "+f"(c[0]), "+f"(c[1]), "+f"(c[2]), "+f"(c[3])
        : "r"(a[0]), "r"(a[1]), "r"(a[2]), "r"(a[3]), "r"(b[0]), "r"(b[1]));
}
// swizzled smem byte offset within a [128][32] bf16 tile (8KB)
__device__ __forceinline__ int sw(int r, int k) {
    int s = ((k >> 3) ^ (r & 3) ^ ((r >> 2) & 1)) & 3;
    return r * 64 + s * 16 + (k & 7) * 2;
}
__device__ __forceinline__ void split2(float x, bf16 &hi, bf16 &lo) {
    hi = __float2bfloat16_rn(x);
    lo = __float2bfloat16_rn(x - __bfloat162float(hi));
}
__device__ __forceinline__ uint32_t pack2(bf16 a, bf16 b) {
    __nv_bfloat162 v(a, b);
    return *reinterpret_cast<uint32_t*>(&v);
}
__device__ __forceinline__ void ffma2(u64 &d, u64 a, u64 b) {
    asm("fma.rn.f32x2 %0, %1, %2, %0;" : "+l"(d) : "l"(a), "l"(b));
}
__device__ __forceinline__ float2 upk2(u64 v) {
    float2 r;
    asm("mov.b64 {%0, %1}, %2;" : "=f"(r.x), "=f"(r.y) : "l"(v));
    return r;
}
__device__ __forceinline__ u64 dup2(float x) {
    u64 r;
    asm("mov.b64 %0, {%1, %1};" : "=l"(r) : "f"(x));
    return r;
}

// ---------------------------------------------------------------------------
// scratch
// ---------------------------------------------------------------------------
__device__ float g_colpart[256 * DD];
__device__ float g_mean[DD];
__device__ float g_mc[DD];
__device__ float g_covpart[(size_t)NSPLIT * DD * DD];
__device__ float g_cov[DD * DD];
__device__ float g_P0[DD * DD];
__device__ float g_P1[DD * DD];
__device__ float g_A1[DD * DD];
__device__ float g_A2[DD * DD];
__device__ float g_scal[2];                   // [0]=1/tr [1]=1/sqrt(tr)
__device__ bf16 g_sA0[(size_t)NROWS * DD];    // layer-input splits (A operand)
__device__ bf16 g_sA1[(size_t)NROWS * DD];
__device__ bf16 g_sH0[(size_t)NROWS * DD];    // h splits
__device__ bf16 g_sH1[(size_t)NROWS * DD];
__device__ bf16 g_t0[(size_t)DD * NROWS];     // transposed h splits
__device__ bf16 g_t1[(size_t)DD * NROWS];
__device__ bf16 g_w0[DD * DD];                // W^T / P^T splits
__device__ bf16 g_w1[DD * DD];

__constant__ int cTI[10] = {0,0,0,0,1,1,1,2,2,3};
__constant__ int cTJ[10] = {0,1,2,3,1,2,3,2,3,3};

// ---------------------------------------------------------------------------
// Double-buffered bf16-split mma.sync GEMM, 128x128 CTA tile, BK=32.
// acc += A0*B0 + A0*B1 + A1*B0  (fp32 accumulate)
// MODE 0: emit bf16 splits of result only (h path)
// MODE 1: out = acc*g_scal[1] - g_mc[col] (fp32) + splits for next layer
// MODE 2: Gram split-K partial -> out + z*DD*DD (upper-triangle tiles)
// ---------------------------------------------------------------------------
#define STAGE_BYTES 32768
#define SMEMSZ (2 * STAGE_BYTES)

template <int MODE>
__global__ __launch_bounds__(256, 2)
void mma_gemm(const bf16* __restrict__ a0g, const bf16* __restrict__ a1g,
              const bf16* __restrict__ b0g, const bf16* __restrict__ b1g,
              float* __restrict__ out,
              bf16* __restrict__ so0, bf16* __restrict__ so1) {
    constexpr int LD  = (MODE == 2) ? NROWS : DD;
    constexpr int NCH = (MODE == 2) ? (NROWS / NSPLIT / 32) : (DD / 32);

    extern __shared__ __align__(128) char sm[];
    const uint32_t smb = smem_u32(sm);

    const int tid = threadIdx.x;
    const int lane = tid & 31, wid = tid >> 5;
    const int warpRow = wid & 1;        // 2 x 64 rows
    const int warpCol = wid >> 1;       // 4 x 32 cols
    const int g = lane >> 2, t4 = lane & 3;

    int rowBase, colBase;
    size_t kStart;
    float* outp;
    if (MODE == 2) {
        rowBase = cTI[blockIdx.x] * 128;
        colBase = cTJ[blockIdx.x] * 128;
        kStart  = (size_t)blockIdx.z * (NROWS / NSPLIT);
        outp = out + (size_t)blockIdx.z * DD * DD;
    } else {
        rowBase = blockIdx.y * 128;
        colBase = blockIdx.x * 128;
        kStart = 0;
        outp = out;
    }

    float acc[4][4][4];
#pragma unroll
    for (int mi = 0; mi < 4; mi++)
#pragma unroll
        for (int ni = 0; ni < 4; ni++)
#pragma unroll
            for (int q = 0; q < 4; q++) acc[mi][ni][q] = 0.f;

    const int lr = tid >> 2;            // 0..63 (+64 on second half)
    const int lseg = tid & 3;

    // chunk loader: stage s, k-chunk ch
    auto load_chunk = [&](int ch, int stage) {
        const size_t kpos = kStart + (size_t)ch * 32;
        const uint32_t sb = smb + stage * STAGE_BYTES;
#pragma unroll
        for (int i = 0; i < 2; i++) {
            const int r = lr + i * 64;
            const int soff = sw(r, lseg * 8);
            const size_t ga = (size_t)(rowBase + r) * LD + kpos + lseg * 8;
            const size_t gb = (size_t)(colBase + r) * LD + kpos + lseg * 8;
            cp16(sb + soff,         a0g + ga);
            cp16(sb + 8192 + soff,  a1g + ga);
            cp16(sb + 16384 + soff, b0g + gb);
            cp16(sb + 24576 + soff, b1g + gb);
        }
        asm volatile("cp.async.commit_group;" ::: "memory");
    };

    load_chunk(0, 0);

    for (int ch = 0; ch < NCH; ch++) {
        if (ch + 1 < NCH) {
            load_chunk(ch + 1, (ch + 1) & 1);
            asm volatile("cp.async.wait_group 1;" ::: "memory");
        } else {
            asm volatile("cp.async.wait_group 0;" ::: "memory");
        }
        __syncthreads();

        char* sbase = sm + (ch & 1) * STAGE_BYTES;
        char* smA0 = sbase;
        char* smA1 = sbase + 8192;
        char* smB0 = sbase + 16384;
        char* smB1 = sbase + 24576;

#pragma unroll
        for (int ks = 0; ks < 2; ks++) {
            const int k0 = ks * 16;
            uint32_t fa0[4][4], fa1[4][4];
#pragma unroll
            for (int mi = 0; mi < 4; mi++) {
                const int row = warpRow * 64 + mi * 16 + g;
                fa0[mi][0] = *(const uint32_t*)(smA0 + sw(row,     k0 + t4 * 2));
                fa0[mi][1] = *(const uint32_t*)(smA0 + sw(row + 8, k0 + t4 * 2));
                fa0[mi][2] = *(const uint32_t*)(smA0 + sw(row,     k0 + 8 + t4 * 2));
                fa0[mi][3] = *(const uint32_t*)(smA0 + sw(row + 8, k0 + 8 + t4 * 2));
                fa1[mi][0] = *(const uint32_t*)(smA1 + sw(row,     k0 + t4 * 2));
                fa1[mi][1] = *(const uint32_t*)(smA1 + sw(row + 8, k0 + t4 * 2));
                fa1[mi][2] = *(const uint32_t*)(smA1 + sw(row,     k0 + 8 + t4 * 2));
                fa1[mi][3] = *(const uint32_t*)(smA1 + sw(row + 8, k0 + 8 + t4 * 2));
            }
#pragma unroll
            for (int ni = 0; ni < 4; ni++) {
                const int nr = warpCol * 32 + ni * 8 + g;
                uint32_t fb0[2], fb1[2];
                fb0[0] = *(const uint32_t*)(smB0 + sw(nr, k0 + t4 * 2));
                fb0[1] = *(const uint32_t*)(smB0 + sw(nr, k0 + 8 + t4 * 2));
                fb1[0] = *(const uint32_t*)(smB1 + sw(nr, k0 + t4 * 2));
                fb1[1] = *(const uint32_t*)(smB1 + sw(nr, k0 + 8 + t4 * 2));
#pragma unroll
                for (int mi = 0; mi < 4; mi++) {
                    mma16816(acc[mi][ni], fa0[mi], fb0);
                    mma16816(acc[mi][ni], fa0[mi], fb1);
                    mma16816(acc[mi][ni], fa1[mi], fb0);
                }
            }
        }
        __syncthreads();
    }

    // epilogue
    const float s1 = (MODE == 1) ? g_scal[1] : 1.0f;
#pragma unroll
    for (int mi = 0; mi < 4; mi++) {
        const int row0 = rowBase + warpRow * 64 + mi * 16 + g;
#pragma unroll
        for (int ni = 0; ni < 4; ni++) {
            const int col = colBase + warpCol * 32 + ni * 8 + t4 * 2;
            float v0 = acc[mi][ni][0], v1 = acc[mi][ni][1];
            float v2 = acc[mi][ni][2], v3 = acc[mi][ni][3];
            if (MODE == 1) {
                const float m0 = g_mc[col], m1 = g_mc[col + 1];
                v0 = v0 * s1 - m0; v1 = v1 * s1 - m1;
                v2 = v2 * s1 - m0; v3 = v3 * s1 - m1;
            }
            if (MODE != 0) {
                *(float2*)(outp + (size_t)row0 * DD + col)       = make_float2(v0, v1);
                *(float2*)(outp + (size_t)(row0 + 8) * DD + col) = make_float2(v2, v3);
            }
            if (MODE != 2) {
                bf16 h0, l0, h1, l1, h2, l2, h3, l3;
                split2(v0, h0, l0); split2(v1, h1, l1);
                split2(v2, h2, l2); split2(v3, h3, l3);
                *(uint32_t*)(so0 + (size_t)row0 * DD + col)       = pack2(h0, h1);
                *(uint32_t*)(so1 + (size_t)row0 * DD + col)       = pack2(l0, l1);
                *(uint32_t*)(so0 + (size_t)(row0 + 8) * DD + col) = pack2(h2, h3);
                *(uint32_t*)(so1 + (size_t)(row0 + 8) * DD + col) = pack2(l2, l3);
            }
        }
    }
}

// ---------------------------------------------------------------------------
// split / transpose kernels
// ---------------------------------------------------------------------------
__global__ void split_rows2_kernel(const float* __restrict__ in,
                                   bf16* __restrict__ s0, bf16* __restrict__ s1,
                                   int n4) {
    int idx = blockIdx.x * 256 + threadIdx.x;
    if (idx >= n4) return;
    float4 v = ((const float4*)in)[idx];
    bf16 h0, l0, h1, l1, h2, l2, h3, l3;
    split2(v.x, h0, l0); split2(v.y, h1, l1);
    split2(v.z, h2, l2); split2(v.w, h3, l3);
    ((uint2*)s0)[idx] = make_uint2(pack2(h0, h1), pack2(h2, h3));
    ((uint2*)s1)[idx] = make_uint2(pack2(l0, l1), pack2(l2, l3));
}

// fp32 [n][512] -> transposed bf16 split planes [512][ldout]
__global__ void split_trans2_kernel(const float* __restrict__ src,
                                    bf16* __restrict__ t0, bf16* __restrict__ t1,
                                    int ldout) {
    __shared__ float ts[32][33];
    const int tid = threadIdx.x;
    const int n0 = blockIdx.x * 32;
    const int d0 = blockIdx.y * 32;
    int r = tid >> 3, c = (tid & 7) * 4;
    float4 v = *(const float4*)(src + (size_t)(n0 + r) * DD + d0 + c);
    ts[r][c] = v.x; ts[r][c + 1] = v.y; ts[r][c + 2] = v.z; ts[r][c + 3] = v.w;
    __syncthreads();
    int cc = tid >> 3, rr = (tid & 7) * 4;
    bf16 h[4], l[4];
#pragma unroll
    for (int i = 0; i < 4; i++) split2(ts[rr + i][cc], h[i], l[i]);
    size_t off = (size_t)(d0 + cc) * ldout + n0 + rr;
    *(uint2*)(t0 + off) = make_uint2(pack2(h[0], h[1]), pack2(h[2], h[3]));
    *(uint2*)(t1 + off) = make_uint2(pack2(l[0], l[1]), pack2(l[2], l[3]));
}

// transpose two bf16 planes: [n][512] -> [512][NROWS]
__global__ void trans_bf16_kernel(const bf16* __restrict__ s0,
                                  const bf16* __restrict__ s1,
                                  bf16* __restrict__ t0, bf16* __restrict__ t1) {
    __shared__ __align__(16) bf16 ts[32][36];
    const int tid = threadIdx.x;
    const int n0 = blockIdx.x * 32;
    const int d0 = blockIdx.y * 32;
    const int r = tid >> 3, seg = tid & 7;
    const int cc = tid >> 3, rr = (tid & 7) * 4;
#pragma unroll
    for (int p = 0; p < 2; p++) {
        const bf16* src = p ? s1 : s0;
        bf16* dst = p ? t1 : t0;
        union { uint2 u; bf16 h[4]; } v;
        v.u = *(const uint2*)(src + (size_t)(n0 + r) * DD + d0 + seg * 4);
#pragma unroll
        for (int i = 0; i < 4; i++) ts[seg * 4 + i][r] = v.h[i];
        __syncthreads();
        *(uint2*)(dst + (size_t)(d0 + cc) * NROWS + n0 + rr) = *(uint2*)&ts[cc][rr];
        __syncthreads();
    }
}

// ---------------------------------------------------------------------------
// fp32 small GEMM for Newton-Schulz (round-2 proven)
// ---------------------------------------------------------------------------
__device__ __forceinline__ void small_body(float* __restrict__ C,
                                           const float* __restrict__ A,
                                           const float* __restrict__ B,
                                           const float* __restrict__ Pin,
                                           float sc, bool upd) {
    __shared__ __align__(16) float As[16][68];
    __shared__ __align__(16) float Bs[16][64];
    const int tid = threadIdx.x;
    const int tx = tid & 15;
    const int ty = tid >> 4;
    const int r0 = blockIdx.y * 64;
    const int c0 = blockIdx.x * 64;

    u64 acc[4][2];
#pragma unroll
    for (int r = 0; r < 4; r++)
#pragma unroll
        for (int j = 0; j < 2; j++) acc[r][j] = 0ull;

    for (int k0 = 0; k0 < DD; k0 += 16) {
        {
            int r = tid >> 2, c = (tid & 3) << 2;
            float4 v = *(const float4*)(A + (size_t)(r0 + r) * DD + k0 + c);
            As[c + 0][r] = v.x; As[c + 1][r] = v.y;
            As[c + 2][r] = v.z; As[c + 3][r] = v.w;
        }
        {
            int r = tid >> 4, c = (tid & 15) << 2;
            *(float4*)&Bs[r][c] = *(const float4*)(B + (size_t)(k0 + r) * DD + c0 + c);
        }
        __syncthreads();
#pragma unroll
        for (int kk = 0; kk < 16; kk++) {
            float4 a0 = *(const float4*)&As[kk][ty * 4];
            u64 a2[4];
            a2[0] = dup2(a0.x); a2[1] = dup2(a0.y);
            a2[2] = dup2(a0.z); a2[3] = dup2(a0.w);
            u64 b2[2];
#pragma unroll
            for (int j = 0; j < 2; j++)
                b2[j] = *(const u64*)&Bs[kk][(j * 16 + tx) * 2];
#pragma unroll
            for (int r = 0; r < 4; r++)
#pragma unroll
                for (int j = 0; j < 2; j++) ffma2(acc[r][j], a2[r], b2[j]);
        }
        __syncthreads();
    }
#pragma unroll
    for (int r = 0; r < 4; r++) {
#pragma unroll
        for (int j = 0; j < 2; j++) {
            float2 f = upk2(acc[r][j]);
            const size_t row = r0 + ty * 4 + r;
            const int col = c0 + (j * 16 + tx) * 2;
            if (upd) {
                f.x = 1.5f * Pin[row * DD + col]     - 0.5f * f.x;
                f.y = 1.5f * Pin[row * DD + col + 1] - 0.5f * f.y;
            } else {
                f.x *= sc; f.y *= sc;
            }
            *(float2*)(C + row * DD + col) = f;
        }
    }
}

// z=0: A1 = P@P ; z=1: A2 = (P@cov)*(1/tr)
__global__ __launch_bounds__(256)
void gemm_pair(const float* __restrict__ P) {
    if (blockIdx.z == 0) small_body(g_A1, P, P, nullptr, 1.0f, false);
    else                 small_body(g_A2, P, g_cov, nullptr, g_scal[0], false);
}
// Pn = 1.5*P - 0.5*(A1@A2)
__global__ __launch_bounds__(256)
void gemm_upd(float* __restrict__ Pn, const float* __restrict__ P) {
    small_body(Pn, g_A1, g_A2, P, 1.0f, true);
}

// ---------------------------------------------------------------------------
// reductions
// ---------------------------------------------------------------------------
__global__ void colsum_bf16_kernel(const bf16* __restrict__ s0,
                                   const bf16* __restrict__ s1) {
    const int b = blockIdx.x;
    const int t = threadIdx.x;
    const bf16* p0 = s0 + (size_t)b * 256 * DD + t;
    const bf16* p1 = s1 + (size_t)b * 256 * DD + t;
    float s = 0.f;
#pragma unroll 8
    for (int r = 0; r < 256; r++)
        s += __bfloat162float(p0[(size_t)r * DD]) + __bfloat162float(p1[(size_t)r * DD]);
    g_colpart[b * DD + t] = s;
}

__global__ void mean_final_kernel() {
    const int t = threadIdx.x;
    float s = 0.f;
#pragma unroll 8
    for (int b = 0; b < 256; b++) s += g_colpart[b * DD + t];
    g_mean[t] = s * (1.0f / (float)NROWS);
}

// cov = Gram/N - m_i m_j + I/temp (mirror upper tiles)
__global__ void reduce_cov_kernel() {
    const int idx = blockIdx.x * 1024 + threadIdx.x;
    const int i = idx >> 9, j = idx & (DD - 1);
    const int src = ((i >> 7) <= (j >> 7)) ? (i * DD + j) : (j * DD + i);
    float s = 0.f;
#pragma unroll
    for (int z = 0; z < NSPLIT; z++)
        s += g_covpart[(size_t)z * DD * DD + src];
    g_cov[idx] = s * (1.0f / (float)NROWS) - g_mean[i] * g_mean[j]
               + ((i == j) ? kInvTemp : 0.0f);
}

__global__ void trace_kernel() {
    __shared__ float sm[512];
    const int t = threadIdx.x;
    sm[t] = g_cov[(size_t)t * DD + t];
    __syncthreads();
    for (int s = 256; s > 0; s >>= 1) {
        if (t < s) sm[t] += sm[t + s];
        __syncthreads();
    }
    if (t == 0) {
        float tr = sm[0];
        g_scal[0] = 1.0f / tr;
        g_scal[1] = 1.0f / sqrtf(tr);
    }
}

__global__ void init_P_kernel(float* __restrict__ P) {
    const int idx = blockIdx.x * 1024 + threadIdx.x;
    const int i = idx >> 9, j = idx & (DD - 1);
    P[idx] = ((i == j) ? 1.5f : 0.0f) - 0.5f * g_cov[idx] * g_scal[0];
}

// g_mc[n] = (sum_k mean[k] * P[k][n]) * (1/sqrt(tr))
__global__ void mc_kernel(const float* __restrict__ P) {
    __shared__ float sm[256];
    const int n = blockIdx.x, t = threadIdx.x;
    float s = g_mean[t] * P[(size_t)t * DD + n]
            + g_mean[t + 256] * P[(size_t)(t + 256) * DD + n];
    sm[t] = s;
    __syncthreads();
    for (int k = 128; k > 0; k >>= 1) {
        if (t < k) sm[t] += sm[t + k];
        __syncthreads();
    }
    if (t == 0) g_mc[n] = sm[0] * g_scal[1];
}

// ---------------------------------------------------------------------------
// orchestration
// ---------------------------------------------------------------------------
extern "C" void kernel_launch(void* const* d_in, const int* in_sizes, int n_in,
                              void* d_out, int out_size) {
    (void)in_sizes; (void)n_in; (void)out_size;
    const float* x = (const float*)d_in[0];
    const float* W[3] = {(const float*)d_in[1], (const float*)d_in[2],
                         (const float*)d_in[3]};
    float* out = (float*)d_out;

    float *pcovpart, *pP0, *pP1;
    bf16 *psA0, *psA1, *psH0, *psH1, *pt0, *pt1, *pw0, *pw1;
    cudaGetSymbolAddress((void**)&pcovpart, g_covpart);
    cudaGetSymbolAddress((void**)&pP0, g_P0);
    cudaGetSymbolAddress((void**)&pP1, g_P1);
    cudaGetSymbolAddress((void**)&psA0, g_sA0);
    cudaGetSymbolAddress((void**)&psA1, g_sA1);
    cudaGetSymbolAddress((void**)&psH0, g_sH0);
    cudaGetSymbolAddress((void**)&psH1, g_sH1);
    cudaGetSymbolAddress((void**)&pt0, g_t0);
    cudaGetSymbolAddress((void**)&pt1, g_t1);
    cudaGetSymbolAddress((void**)&pw0, g_w0);
    cudaGetSymbolAddress((void**)&pw1, g_w1);

    cudaFuncSetAttribute(mma_gemm<0>, cudaFuncAttributeMaxDynamicSharedMemorySize, SMEMSZ);
    cudaFuncSetAttribute(mma_gemm<1>, cudaFuncAttributeMaxDynamicSharedMemorySize, SMEMSZ);
    cudaFuncSetAttribute(mma_gemm<2>, cudaFuncAttributeMaxDynamicSharedMemorySize, SMEMSZ);

    const int N4BIG = NROWS * DD / 4;
    const dim3 gact(4, NROWS / 128);
    const dim3 gcov(10, 1, NSPLIT);

    // layer-0 input splits
    split_rows2_kernel<<<N4BIG / 256, 256>>>(x, psA0, psA1, N4BIG);

    for (int l = 0; l < 3; l++) {
        float* O = out + (size_t)l * NROWS * DD;

        // W^T splits, then h = in @ W (emits h splits only)
        split_trans2_kernel<<<dim3(16, 16), 256>>>(W[l], pw0, pw1, DD);
        mma_gemm<0><<<gact, 256, SMEMSZ>>>(psA0, psA1, pw0, pw1, nullptr, psH0, psH1);

        // mean from splits
        colsum_bf16_kernel<<<256, 512>>>(psH0, psH1);
        mean_final_kernel<<<1, 512>>>();

        // transposed h splits -> Gram -> cov
        trans_bf16_kernel<<<dim3(NROWS / 32, 16), 256>>>(psH0, psH1, pt0, pt1);
        mma_gemm<2><<<gcov, 256, SMEMSZ>>>(pt0, pt1, pt0, pt1, pcovpart, nullptr, nullptr);
        reduce_cov_kernel<<<256, 1024>>>();
        trace_kernel<<<1, 512>>>();
        init_P_kernel<<<256, 1024>>>(pP0);

        // Newton-Schulz iterations 1..9 (fp32)
        float* P = pP0;
        float* Pn = pP1;
        for (int it = 1; it < 10; it++) {
            gemm_pair<<<dim3(8, 8, 2), 256>>>(P);
            gemm_upd<<<dim3(8, 8), 256>>>(Pn, P);
            float* t = P; P = Pn; Pn = t;
        }

        // O = h@P * 1/sqrt(tr) - mc  (emits O + splits as next layer's input)
        split_trans2_kernel<<<dim3(16, 16), 256>>>(P, pw0, pw1, DD);
        mc_kernel<<<512, 256>>>(P);
        mma_gemm<1><<<gact, 256, SMEMSZ>>>(psH0, psH1, pw0, pw1, O, psA0, psA1);
    }
}

// round 6
// speedup vs baseline: 1.2893x; 1.2893x over previous
#include <cuda_runtime.h>
#include <cuda_bf16.h>
#include <math.h>
#include <stdint.h>

#define NROWS 65536
#define DD    512
#define NSPLIT 16
static __device__ __constant__ float kInvTemp = 0.1f;

typedef unsigned long long u64;
typedef __nv_bfloat16 bf16;

// ---------------------------------------------------------------------------
// helpers
// ---------------------------------------------------------------------------
__device__ __forceinline__ uint32_t smem_u32(const void* p) {
    uint32_t a;
    asm("{ .reg .u64 t; cvta.to.shared.u64 t, %1; cvt.u32.u64 %0, t; }"
        : "=r"(a) : "l"(p));
    return a;
}
__device__ __forceinline__ void cp16(uint32_t dst, const void* src) {
    asm volatile("cp.async.cg.shared.global [%0], [%1], 16;"
                 :: "r"(dst), "l"(src) : "memory");
}
__device__ __forceinline__ void mma16816(float* c, const uint32_t* a,
                                         const uint32_t* b) {
    asm volatile(
        "mma.sync.aligned.m16n8k16.row.col.f32.bf16.bf16.f32 "
        "{%0,%1,%2,%3}, {%4,%5,%6,%7}, {%8,%9}, {%0,%1,%2,%3};"
        : "+f"(c[0]), "+f"(c[1]), "+f"(c[2]), "+f"(c[3])
        : "r"(a[0]), "r"(a[1]), "r"(a[2]), "r"(a[3]), "r"(b[0]), "r"(b[1]));
}
// swizzled smem byte offset within a [128][32] bf16 tile (8KB)
__device__ __forceinline__ int sw(int r, int k) {
    int s = ((k >> 3) ^ (r & 3) ^ ((r >> 2) & 1)) & 3;
    return r * 64 + s * 16 + (k & 7) * 2;
}
__device__ __forceinline__ void split2(float x, bf16 &hi, bf16 &lo) {
    hi = __float2bfloat16_rn(x);
    lo = __float2bfloat16_rn(x - __bfloat162float(hi));
}
__device__ __forceinline__ uint32_t pack2(bf16 a, bf16 b) {
    __nv_bfloat162 v(a, b);
    return *reinterpret_cast<uint32_t*>(&v);
}
__device__ __forceinline__ void ffma2(u64 &d, u64 a, u64 b) {
    asm("fma.rn.f32x2 %0, %1, %2, %0;" : "+l"(d) : "l"(a), "l"(b));
}
__device__ __forceinline__ float2 upk2(u64 v) {
    float2 r;
    asm("mov.b64 {%0, %1}, %2;" : "=f"(r.x), "=f"(r.y) : "l"(v));
    return r;
}
__device__ __forceinline__ u64 dup2(float x) {
    u64 r;
    asm("mov.b64 %0, {%1, %1};" : "=l"(r) : "f"(x));
    return r;
}

// ---------------------------------------------------------------------------
// scratch
// ---------------------------------------------------------------------------
__device__ float g_colpart[256 * DD];
__device__ float g_mean[DD];          // column mean of x
__device__ float g_mc[DD];            // rank-1 correction vector
__device__ float g_covpart[(size_t)NSPLIT * DD * DD];
__device__ float g_sig[DD * DD];      // centered 2nd moment (propagated)
__device__ float g_cov[DD * DD];
__device__ float g_T1[DD * DD];
__device__ float g_M[DD * DD];        // M = W @ C
__device__ float g_P0[DD * DD];
__device__ float g_P1[DD * DD];
__device__ float g_A1[DD * DD];
__device__ float g_A2[DD * DD];
__device__ float g_scal[2];           // [0]=1/tr [1]=1/sqrt(tr)
__device__ bf16 g_sA0[(size_t)NROWS * DD];   // operand splits ping
__device__ bf16 g_sA1[(size_t)NROWS * DD];
__device__ bf16 g_sB0[(size_t)NROWS * DD];   // operand splits pong
__device__ bf16 g_sB1[(size_t)NROWS * DD];
__device__ bf16 g_t0[(size_t)DD * NROWS];    // transposed x splits
__device__ bf16 g_t1[(size_t)DD * NROWS];
__device__ bf16 g_w0[DD * DD];               // M^T splits
__device__ bf16 g_w1[DD * DD];

__constant__ int cTI[10] = {0,0,0,0,1,1,1,2,2,3};
__constant__ int cTJ[10] = {0,1,2,3,1,2,3,2,3,3};

// ---------------------------------------------------------------------------
// Double-buffered bf16-split mma.sync GEMM, 128x128 CTA tile, BK=32.
// acc += A0*B0 + A0*B1 + A1*B0  (fp32 accumulate)
// MODE 1: out = acc - g_mc[col] (fp32) + bf16 splits of result
// MODE 2: Gram split-K partial -> out + z*DD*DD (upper-triangle tiles)
// ---------------------------------------------------------------------------
#define STAGE_BYTES 32768
#define SMEMSZ (2 * STAGE_BYTES)

template <int MODE>
__global__ __launch_bounds__(256, 2)
void mma_gemm(const bf16* __restrict__ a0g, const bf16* __restrict__ a1g,
              const bf16* __restrict__ b0g, const bf16* __restrict__ b1g,
              float* __restrict__ out,
              bf16* __restrict__ so0, bf16* __restrict__ so1) {
    constexpr int LD  = (MODE == 2) ? NROWS : DD;
    constexpr int NCH = (MODE == 2) ? (NROWS / NSPLIT / 32) : (DD / 32);

    extern __shared__ __align__(128) char sm[];
    const uint32_t smb = smem_u32(sm);

    const int tid = threadIdx.x;
    const int lane = tid & 31, wid = tid >> 5;
    const int warpRow = wid & 1;
    const int warpCol = wid >> 1;
    const int g = lane >> 2, t4 = lane & 3;

    int rowBase, colBase;
    size_t kStart;
    float* outp;
    if (MODE == 2) {
        rowBase = cTI[blockIdx.x] * 128;
        colBase = cTJ[blockIdx.x] * 128;
        kStart  = (size_t)blockIdx.z * (NROWS / NSPLIT);
        outp = out + (size_t)blockIdx.z * DD * DD;
    } else {
        rowBase = blockIdx.y * 128;
        colBase = blockIdx.x * 128;
        kStart = 0;
        outp = out;
    }

    float acc[4][4][4];
#pragma unroll
    for (int mi = 0; mi < 4; mi++)
#pragma unroll
        for (int ni = 0; ni < 4; ni++)
#pragma unroll
            for (int q = 0; q < 4; q++) acc[mi][ni][q] = 0.f;

    const int lr = tid >> 2;
    const int lseg = tid & 3;

    auto load_chunk = [&](int ch, int stage) {
        const size_t kpos = kStart + (size_t)ch * 32;
        const uint32_t sb = smb + stage * STAGE_BYTES;
#pragma unroll
        for (int i = 0; i < 2; i++) {
            const int r = lr + i * 64;
            const int soff = sw(r, lseg * 8);
            const size_t ga = (size_t)(rowBase + r) * LD + kpos + lseg * 8;
            const size_t gb = (size_t)(colBase + r) * LD + kpos + lseg * 8;
            cp16(sb + soff,         a0g + ga);
            cp16(sb + 8192 + soff,  a1g + ga);
            cp16(sb + 16384 + soff, b0g + gb);
            cp16(sb + 24576 + soff, b1g + gb);
        }
        asm volatile("cp.async.commit_group;" ::: "memory");
    };

    load_chunk(0, 0);

    for (int ch = 0; ch < NCH; ch++) {
        if (ch + 1 < NCH) {
            load_chunk(ch + 1, (ch + 1) & 1);
            asm volatile("cp.async.wait_group 1;" ::: "memory");
        } else {
            asm volatile("cp.async.wait_group 0;" ::: "memory");
        }
        __syncthreads();

        char* sbase = sm + (ch & 1) * STAGE_BYTES;
        char* smA0 = sbase;
        char* smA1 = sbase + 8192;
        char* smB0 = sbase + 16384;
        char* smB1 = sbase + 24576;

#pragma unroll
        for (int ks = 0; ks < 2; ks++) {
            const int k0 = ks * 16;
            uint32_t fa0[4][4], fa1[4][4];
#pragma unroll
            for (int mi = 0; mi < 4; mi++) {
                const int row = warpRow * 64 + mi * 16 + g;
                fa0[mi][0] = *(const uint32_t*)(smA0 + sw(row,     k0 + t4 * 2));
                fa0[mi][1] = *(const uint32_t*)(smA0 + sw(row + 8, k0 + t4 * 2));
                fa0[mi][2] = *(const uint32_t*)(smA0 + sw(row,     k0 + 8 + t4 * 2));
                fa0[mi][3] = *(const uint32_t*)(smA0 + sw(row + 8, k0 + 8 + t4 * 2));
                fa1[mi][0] = *(const uint32_t*)(smA1 + sw(row,     k0 + t4 * 2));
                fa1[mi][1] = *(const uint32_t*)(smA1 + sw(row + 8, k0 + t4 * 2));
                fa1[mi][2] = *(const uint32_t*)(smA1 + sw(row,     k0 + 8 + t4 * 2));
                fa1[mi][3] = *(const uint32_t*)(smA1 + sw(row + 8, k0 + 8 + t4 * 2));
            }
#pragma unroll
            for (int ni = 0; ni < 4; ni++) {
                const int nr = warpCol * 32 + ni * 8 + g;
                uint32_t fb0[2], fb1[2];
                fb0[0] = *(const uint32_t*)(smB0 + sw(nr, k0 + t4 * 2));
                fb0[1] = *(const uint32_t*)(smB0 + sw(nr, k0 + 8 + t4 * 2));
                fb1[0] = *(const uint32_t*)(smB1 + sw(nr, k0 + t4 * 2));
                fb1[1] = *(const uint32_t*)(smB1 + sw(nr, k0 + 8 + t4 * 2));
#pragma unroll
                for (int mi = 0; mi < 4; mi++) {
                    mma16816(acc[mi][ni], fa0[mi], fb0);
                    mma16816(acc[mi][ni], fa0[mi], fb1);
                    mma16816(acc[mi][ni], fa1[mi], fb0);
                }
            }
        }
        __syncthreads();
    }

    // epilogue
#pragma unroll
    for (int mi = 0; mi < 4; mi++) {
        const int row0 = rowBase + warpRow * 64 + mi * 16 + g;
#pragma unroll
        for (int ni = 0; ni < 4; ni++) {
            const int col = colBase + warpCol * 32 + ni * 8 + t4 * 2;
            float v0 = acc[mi][ni][0], v1 = acc[mi][ni][1];
            float v2 = acc[mi][ni][2], v3 = acc[mi][ni][3];
            if (MODE == 1) {
                const float m0 = g_mc[col], m1 = g_mc[col + 1];
                v0 -= m0; v1 -= m1; v2 -= m0; v3 -= m1;
            }
            *(float2*)(outp + (size_t)row0 * DD + col)       = make_float2(v0, v1);
            *(float2*)(outp + (size_t)(row0 + 8) * DD + col) = make_float2(v2, v3);
            if (MODE == 1) {
                bf16 h0, l0, h1, l1, h2, l2, h3, l3;
                split2(v0, h0, l0); split2(v1, h1, l1);
                split2(v2, h2, l2); split2(v3, h3, l3);
                *(uint32_t*)(so0 + (size_t)row0 * DD + col)       = pack2(h0, h1);
                *(uint32_t*)(so1 + (size_t)row0 * DD + col)       = pack2(l0, l1);
                *(uint32_t*)(so0 + (size_t)(row0 + 8) * DD + col) = pack2(h2, h3);
                *(uint32_t*)(so1 + (size_t)(row0 + 8) * DD + col) = pack2(l2, l3);
            }
        }
    }
}

// ---------------------------------------------------------------------------
// split / transpose kernels
// ---------------------------------------------------------------------------
__global__ void split_rows2_kernel(const float* __restrict__ in,
                                   bf16* __restrict__ s0, bf16* __restrict__ s1,
                                   int n4) {
    int idx = blockIdx.x * 256 + threadIdx.x;
    if (idx >= n4) return;
    float4 v = ((const float4*)in)[idx];
    bf16 h0, l0, h1, l1, h2, l2, h3, l3;
    split2(v.x, h0, l0); split2(v.y, h1, l1);
    split2(v.z, h2, l2); split2(v.w, h3, l3);
    ((uint2*)s0)[idx] = make_uint2(pack2(h0, h1), pack2(h2, h3));
    ((uint2*)s1)[idx] = make_uint2(pack2(l0, l1), pack2(l2, l3));
}

// fp32 [n][512] -> transposed bf16 split planes [512][ldout]
__global__ void split_trans2_kernel(const float* __restrict__ src,
                                    bf16* __restrict__ t0, bf16* __restrict__ t1,
                                    int ldout) {
    __shared__ float ts[32][33];
    const int tid = threadIdx.x;
    const int n0 = blockIdx.x * 32;
    const int d0 = blockIdx.y * 32;
    int r = tid >> 3, c = (tid & 7) * 4;
    float4 v = *(const float4*)(src + (size_t)(n0 + r) * DD + d0 + c);
    ts[r][c] = v.x; ts[r][c + 1] = v.y; ts[r][c + 2] = v.z; ts[r][c + 3] = v.w;
    __syncthreads();
    int cc = tid >> 3, rr = (tid & 7) * 4;
    bf16 h[4], l[4];
#pragma unroll
    for (int i = 0; i < 4; i++) split2(ts[rr + i][cc], h[i], l[i]);
    size_t off = (size_t)(d0 + cc) * ldout + n0 + rr;
    *(uint2*)(t0 + off) = make_uint2(pack2(h[0], h[1]), pack2(h[2], h[3]));
    *(uint2*)(t1 + off) = make_uint2(pack2(l[0], l[1]), pack2(l[2], l[3]));
}

// ---------------------------------------------------------------------------
// fp32 small GEMM (64x64 tile, grid 8x8) — shared body
// ---------------------------------------------------------------------------
template <int TA>
__device__ __forceinline__ void load_tiles(float (&As)[16][68], float (&Bs)[16][64],
                                           const float* A, const float* B,
                                           int r0, int c0, int k0, int tid) {
    if (TA == 0) {
        int r = tid >> 2, c = (tid & 3) << 2;
        float4 v = *(const float4*)(A + (size_t)(r0 + r) * DD + k0 + c);
        As[c + 0][r] = v.x; As[c + 1][r] = v.y;
        As[c + 2][r] = v.z; As[c + 3][r] = v.w;
    } else {
        int r = tid >> 4, c = (tid & 15) << 2;   // As[k][m] = A[k0+k][r0+m]
        float4 v = *(const float4*)(A + (size_t)(k0 + r) * DD + r0 + c);
        *(float4*)&As[r][c] = v;
    }
    {
        int r = tid >> 4, c = (tid & 15) << 2;
        *(float4*)&Bs[r][c] = *(const float4*)(B + (size_t)(k0 + r) * DD + c0 + c);
    }
}

// EPI: 0 = C = acc*sc ; 1 = C = acc + I/temp (cov) ; 2 = C = 1.5*Pin - 0.5*acc ;
//      3 = C = acc - (kInvTemp*g_scal[0])*Pin  (sigma update)
template <int TA, int EPI>
__device__ __forceinline__ void small_body(float* __restrict__ C,
                                           const float* __restrict__ A,
                                           const float* __restrict__ B,
                                           const float* __restrict__ Pin,
                                           float sc) {
    __shared__ __align__(16) float As[16][68];
    __shared__ __align__(16) float Bs[16][64];
    const int tid = threadIdx.x;
    const int tx = tid & 15;
    const int ty = tid >> 4;
    const int r0 = blockIdx.y * 64;
    const int c0 = blockIdx.x * 64;

    u64 acc[4][2];
#pragma unroll
    for (int r = 0; r < 4; r++)
#pragma unroll
        for (int j = 0; j < 2; j++) acc[r][j] = 0ull;

    for (int k0 = 0; k0 < DD; k0 += 16) {
        load_tiles<TA>(As, Bs, A, B, r0, c0, k0, tid);
        __syncthreads();
#pragma unroll
        for (int kk = 0; kk < 16; kk++) {
            float4 a0 = *(const float4*)&As[kk][ty * 4];
            u64 a2[4];
            a2[0] = dup2(a0.x); a2[1] = dup2(a0.y);
            a2[2] = dup2(a0.z); a2[3] = dup2(a0.w);
            u64 b2[2];
#pragma unroll
            for (int j = 0; j < 2; j++)
                b2[j] = *(const u64*)&Bs[kk][(j * 16 + tx) * 2];
#pragma unroll
            for (int r = 0; r < 4; r++)
#pragma unroll
                for (int j = 0; j < 2; j++) ffma2(acc[r][j], a2[r], b2[j]);
        }
        __syncthreads();
    }
#pragma unroll
    for (int r = 0; r < 4; r++) {
#pragma unroll
        for (int j = 0; j < 2; j++) {
            float2 f = upk2(acc[r][j]);
            const size_t row = r0 + ty * 4 + r;
            const int col = c0 + (j * 16 + tx) * 2;
            if (EPI == 0) {
                f.x *= sc; f.y *= sc;
            } else if (EPI == 1) {
                if ((int)row == col)     f.x += kInvTemp;
                if ((int)row == col + 1) f.y += kInvTemp;
            } else if (EPI == 2) {
                f.x = 1.5f * Pin[row * DD + col]     - 0.5f * f.x;
                f.y = 1.5f * Pin[row * DD + col + 1] - 0.5f * f.y;
            } else if (EPI == 3) {
                const float cc2 = kInvTemp * g_scal[0];
                f.x -= cc2 * Pin[row * DD + col];
                f.y -= cc2 * Pin[row * DD + col + 1];
            }
            *(float2*)(C + row * DD + col) = f;
        }
    }
}

// scalesel: 0 -> 1.0, 1 -> g_scal[0], 2 -> g_scal[1]
template <int TA, int EPI>
__global__ __launch_bounds__(256)
void gemm512(float* __restrict__ C, const float* __restrict__ A,
             const float* __restrict__ B, const float* __restrict__ Pin,
             int scalesel) {
    float sc = (scalesel == 1) ? g_scal[0] : (scalesel == 2) ? g_scal[1] : 1.0f;
    small_body<TA, EPI>(C, A, B, Pin, sc);
}

// z=0: A1 = P@P ; z=1: A2 = (P@cov)*(1/tr)
__global__ __launch_bounds__(256)
void gemm_pair(const float* __restrict__ P) {
    if (blockIdx.z == 0) small_body<0, 0>(g_A1, P, P, nullptr, 1.0f);
    else                 small_body<0, 0>(g_A2, P, g_cov, nullptr, g_scal[0]);
}
// Pn = 1.5*P - 0.5*(A1@A2)
__global__ __launch_bounds__(256)
void gemm_upd(float* __restrict__ Pn, const float* __restrict__ P) {
    small_body<0, 2>(Pn, g_A1, g_A2, P, 1.0f);
}

// ---------------------------------------------------------------------------
// reductions / vectors
// ---------------------------------------------------------------------------
__global__ void colsum_kernel(const float* __restrict__ H) {
    const int b = blockIdx.x;
    const int t = threadIdx.x;
    const float* p = H + (size_t)b * 256 * DD + t;
    float s = 0.f;
#pragma unroll 8
    for (int r = 0; r < 256; r++) s += p[(size_t)r * DD];
    g_colpart[b * DD + t] = s;
}

__global__ void mean_final_kernel() {
    const int t = threadIdx.x;
    float s = 0.f;
#pragma unroll 8
    for (int b = 0; b < 256; b++) s += g_colpart[b * DD + t];
    g_mean[t] = s * (1.0f / (float)NROWS);
}

// Sigma_c(x) = Gram/N - xm_i xm_j  (mirror upper tiles)
__global__ void reduce_sig_kernel() {
    const int idx = blockIdx.x * 1024 + threadIdx.x;
    const int i = idx >> 9, j = idx & (DD - 1);
    const int src = ((i >> 7) <= (j >> 7)) ? (i * DD + j) : (j * DD + i);
    float s = 0.f;
#pragma unroll
    for (int z = 0; z < NSPLIT; z++)
        s += g_covpart[(size_t)z * DD * DD + src];
    g_sig[idx] = s * (1.0f / (float)NROWS) - g_mean[i] * g_mean[j];
}

__global__ void trace_kernel() {
    __shared__ float sm[512];
    const int t = threadIdx.x;
    sm[t] = g_cov[(size_t)t * DD + t];
    __syncthreads();
    for (int s = 256; s > 0; s >>= 1) {
        if (t < s) sm[t] += sm[t + s];
        __syncthreads();
    }
    if (t == 0) {
        float tr = sm[0];
        g_scal[0] = 1.0f / tr;
        g_scal[1] = 1.0f / sqrtf(tr);
    }
}

__global__ void init_P_kernel(float* __restrict__ P) {
    const int idx = blockIdx.x * 1024 + threadIdx.x;
    const int i = idx >> 9, j = idx & (DD - 1);
    P[idx] = ((i == j) ? 1.5f : 0.0f) - 0.5f * g_cov[idx] * g_scal[0];
}

// g_mc[n] = sum_k g_mean[k] * M[k][n]   (M already includes 1/sqrt(tr))
__global__ void mc_kernel(const float* __restrict__ M) {
    __shared__ float sm[256];
    const int n = blockIdx.x, t = threadIdx.x;
    float s = g_mean[t] * M[(size_t)t * DD + n]
            + g_mean[t + 256] * M[(size_t)(t + 256) * DD + n];
    sm[t] = s;
    __syncthreads();
    for (int k = 128; k > 0; k >>= 1) {
        if (t < k) sm[t] += sm[t + k];
        __syncthreads();
    }
    if (t == 0) g_mc[n] = sm[0];
}

__global__ void zero_mc_kernel() { g_mc[threadIdx.x] = 0.f; }

// ---------------------------------------------------------------------------
// orchestration
// ---------------------------------------------------------------------------
extern "C" void kernel_launch(void* const* d_in, const int* in_sizes, int n_in,
                              void* d_out, int out_size) {
    (void)in_sizes; (void)n_in; (void)out_size;
    const float* x = (const float*)d_in[0];
    const float* W[3] = {(const float*)d_in[1], (const float*)d_in[2],
                         (const float*)d_in[3]};
    float* out = (float*)d_out;

    float *pcovpart, *psig, *pcov, *pT1, *pM, *pP0, *pP1, *pA1, *pA2;
    bf16 *psA0, *psA1, *psB0, *psB1, *pt0, *pt1, *pw0, *pw1;
    cudaGetSymbolAddress((void**)&pcovpart, g_covpart);
    cudaGetSymbolAddress((void**)&psig, g_sig);
    cudaGetSymbolAddress((void**)&pcov, g_cov);
    cudaGetSymbolAddress((void**)&pT1, g_T1);
    cudaGetSymbolAddress((void**)&pM, g_M);
    cudaGetSymbolAddress((void**)&pP0, g_P0);
    cudaGetSymbolAddress((void**)&pP1, g_P1);
    cudaGetSymbolAddress((void**)&pA1, g_A1);
    cudaGetSymbolAddress((void**)&pA2, g_A2);
    cudaGetSymbolAddress((void**)&psA0, g_sA0);
    cudaGetSymbolAddress((void**)&psA1, g_sA1);
    cudaGetSymbolAddress((void**)&psB0, g_sB0);
    cudaGetSymbolAddress((void**)&psB1, g_sB1);
    cudaGetSymbolAddress((void**)&pt0, g_t0);
    cudaGetSymbolAddress((void**)&pt1, g_t1);
    cudaGetSymbolAddress((void**)&pw0, g_w0);
    cudaGetSymbolAddress((void**)&pw1, g_w1);

    cudaFuncSetAttribute(mma_gemm<1>, cudaFuncAttributeMaxDynamicSharedMemorySize, SMEMSZ);
    cudaFuncSetAttribute(mma_gemm<2>, cudaFuncAttributeMaxDynamicSharedMemorySize, SMEMSZ);

    const int N4BIG = NROWS * DD / 4;
    const dim3 gact(4, NROWS / 128);
    const dim3 gcov(10, 1, NSPLIT);
    const dim3 gsm(8, 8);

    // ---- once: x statistics + x splits ----
    split_rows2_kernel<<<N4BIG / 256, 256>>>(x, psA0, psA1, N4BIG);
    colsum_kernel<<<256, 512>>>(x);
    mean_final_kernel<<<1, 512>>>();
    split_trans2_kernel<<<dim3(NROWS / 32, 16), 256>>>(x, pt0, pt1, NROWS);
    mma_gemm<2><<<gcov, 256, SMEMSZ>>>(pt0, pt1, pt0, pt1, pcovpart, nullptr, nullptr);
    reduce_sig_kernel<<<256, 1024>>>();   // g_sig = Sigma_c(x)

    bf16* in0 = psA0; bf16* in1 = psA1;
    bf16* ot0 = psB0; bf16* ot1 = psB1;

    for (int l = 0; l < 3; l++) {
        float* O = out + (size_t)l * NROWS * DD;

        // cov = W^T Sigma_c W + I/temp
        gemm512<0, 0><<<gsm, 256>>>(pT1, psig, W[l], nullptr, 0);       // T1 = Sigma_c @ W
        gemm512<1, 1><<<gsm, 256>>>(pcov, W[l], pT1, nullptr, 0);       // cov = W^T T1 + I/temp
        trace_kernel<<<1, 512>>>();
        init_P_kernel<<<256, 1024>>>(pP0);

        // Newton-Schulz iterations 1..9
        float* P = pP0;
        float* Pn = pP1;
        for (int it = 1; it < 10; it++) {
            gemm_pair<<<dim3(8, 8, 2), 256>>>(P);
            gemm_upd<<<gsm, 256>>>(Pn, P);
            float* t = P; P = Pn; Pn = t;
        }

        // Sigma_c' = (P cov P)/tr - (1/(tr*temp)) P^2  ;  M = W @ P * (1/sqrt(tr))
        gemm_pair<<<dim3(8, 8, 2), 256>>>(P);                            // A1=P@P, A2=(P@cov)/tr
        gemm512<0, 3><<<gsm, 256>>>(psig, pA2, P, pA1, 0);               // Sigma_c' (next layer)
        gemm512<0, 0><<<gsm, 256>>>(pM, W[l], P, nullptr, 2);            // M = W@P*scal1
        split_trans2_kernel<<<dim3(16, 16), 256>>>(pM, pw0, pw1, DD);
        if (l == 0) mc_kernel<<<512, 256>>>(pM);
        else        zero_mc_kernel<<<1, 512>>>();

        // O = in @ M - 1*mc  (also emits bf16 splits of O for next layer)
        mma_gemm<1><<<gact, 256, SMEMSZ>>>(in0, in1, pw0, pw1, O, ot0, ot1);

        bf16* t0s = in0; in0 = ot0; ot0 = t0s;
        bf16* t1s = in1; in1 = ot1; ot1 = t1s;
    }
}

// round 7
// speedup vs baseline: 1.3397x; 1.0390x over previous
#include <cuda_runtime.h>
#include <cuda_bf16.h>
#include <math.h>
#include <stdint.h>

#define NROWS 65536
#define DD    512
#define NSPLIT 16
static __device__ __constant__ float kInvTemp = 0.1f;

typedef unsigned long long u64;
typedef __nv_bfloat16 bf16;

// ---------------------------------------------------------------------------
// helpers
// ---------------------------------------------------------------------------
__device__ __forceinline__ uint32_t smem_u32(const void* p) {
    uint32_t a;
    asm("{ .reg .u64 t; cvta.to.shared.u64 t, %1; cvt.u32.u64 %0, t; }"
        : "=r"(a) : "l"(p));
    return a;
}
__device__ __forceinline__ void cp16(uint32_t dst, const void* src) {
    asm volatile("cp.async.cg.shared.global [%0], [%1], 16;"
                 :: "r"(dst), "l"(src) : "memory");
}
__device__ __forceinline__ void mma16816(float* c, const uint32_t* a,
                                         const uint32_t* b) {
    asm volatile(
        "mma.sync.aligned.m16n8k16.row.col.f32.bf16.bf16.f32 "
        "{%0,%1,%2,%3}, {%4,%5,%6,%7}, {%8,%9}, {%0,%1,%2,%3};"
        : "+f"(c[0]), "+f"(c[1]), "+f"(c[2]), "+f"(c[3])
        : "r"(a[0]), "r"(a[1]), "r"(a[2]), "r"(a[3]), "r"(b[0]), "r"(b[1]));
}
__device__ __forceinline__ void ldsm4(uint32_t* r, uint32_t addr) {
    asm volatile("ldmatrix.sync.aligned.m8n8.x4.shared.b16 {%0,%1,%2,%3}, [%4];"
                 : "=r"(r[0]), "=r"(r[1]), "=r"(r[2]), "=r"(r[3]) : "r"(addr));
}
// swizzled smem byte offset within a [128][32] bf16 tile (8KB)
__device__ __forceinline__ int sw(int r, int k) {
    int s = ((k >> 3) ^ (r & 3) ^ ((r >> 2) & 1)) & 3;
    return r * 64 + s * 16 + (k & 7) * 2;
}
__device__ __forceinline__ void split2(float x, bf16 &hi, bf16 &lo) {
    hi = __float2bfloat16_rn(x);
    lo = __float2bfloat16_rn(x - __bfloat162float(hi));
}
__device__ __forceinline__ uint32_t pack2(bf16 a, bf16 b) {
    __nv_bfloat162 v(a, b);
    return *reinterpret_cast<uint32_t*>(&v);
}
__device__ __forceinline__ void ffma2(u64 &d, u64 a, u64 b) {
    asm("fma.rn.f32x2 %0, %1, %2, %0;" : "+l"(d) : "l"(a), "l"(b));
}
__device__ __forceinline__ float2 upk2(u64 v) {
    float2 r;
    asm("mov.b64 {%0, %1}, %2;" : "=f"(r.x), "=f"(r.y) : "l"(v));
    return r;
}
__device__ __forceinline__ u64 dup2(float x) {
    u64 r;
    asm("mov.b64 %0, {%1, %1};" : "=l"(r) : "f"(x));
    return r;
}

// ---------------------------------------------------------------------------
// scratch
// ---------------------------------------------------------------------------
__device__ float g_colpart[256 * DD];
__device__ float g_mean[DD];
__device__ float g_mcv[3 * DD];              // per-layer rank-1 correction
__device__ float g_covpart[(size_t)NSPLIT * DD * DD];
__device__ float g_sig[DD * DD];
__device__ float g_cov[DD * DD];
__device__ float g_T1[DD * DD];
__device__ float g_M[DD * DD];
__device__ float g_P0[DD * DD];
__device__ float g_P1[DD * DD];
__device__ float g_A1[DD * DD];
__device__ float g_A2[DD * DD];
__device__ float g_scal[2];
__device__ bf16 g_sA0[(size_t)NROWS * DD];
__device__ bf16 g_sA1[(size_t)NROWS * DD];
__device__ bf16 g_sB0[(size_t)NROWS * DD];
__device__ bf16 g_sB1[(size_t)NROWS * DD];
__device__ bf16 g_t0[(size_t)DD * NROWS];
__device__ bf16 g_t1[(size_t)DD * NROWS];
__device__ bf16 g_w0[3 * DD * DD];           // per-layer M^T splits
__device__ bf16 g_w1[3 * DD * DD];

__constant__ int cTI[10] = {0,0,0,0,1,1,1,2,2,3};
__constant__ int cTJ[10] = {0,1,2,3,1,2,3,2,3,3};

// ---------------------------------------------------------------------------
// Double-buffered bf16-split mma.sync GEMM with ldmatrix fragment loads.
// 128x128 CTA tile, BK=32. acc += A0*B0 + A0*B1 + A1*B0.
// MODE 1: out = acc - mc[col] (fp32) + bf16 splits of result
// MODE 2: Gram split-K partial -> out + z*DD*DD (upper-triangle tiles)
// ---------------------------------------------------------------------------
#define STAGE_BYTES 32768
#define SMEMSZ (2 * STAGE_BYTES)

template <int MODE>
__global__ __launch_bounds__(256, 2)
void mma_gemm(const bf16* __restrict__ a0g, const bf16* __restrict__ a1g,
              const bf16* __restrict__ b0g, const bf16* __restrict__ b1g,
              float* __restrict__ out, const float* __restrict__ mc,
              bf16* __restrict__ so0, bf16* __restrict__ so1) {
    constexpr int LD  = (MODE == 2) ? NROWS : DD;
    constexpr int NCH = (MODE == 2) ? (NROWS / NSPLIT / 32) : (DD / 32);

    extern __shared__ __align__(128) char sm[];
    const uint32_t smb = smem_u32(sm);

    const int tid = threadIdx.x;
    const int lane = tid & 31, wid = tid >> 5;
    const int warpRow = wid & 1;
    const int warpCol = wid >> 1;
    const int g = lane >> 2, t4 = lane & 3;
    const int laneRow = lane & 7, grp = lane >> 3;

    int rowBase, colBase;
    size_t kStart;
    float* outp;
    if (MODE == 2) {
        rowBase = cTI[blockIdx.x] * 128;
        colBase = cTJ[blockIdx.x] * 128;
        kStart  = (size_t)blockIdx.z * (NROWS / NSPLIT);
        outp = out + (size_t)blockIdx.z * DD * DD;
    } else {
        rowBase = blockIdx.y * 128;
        colBase = blockIdx.x * 128;
        kStart = 0;
        outp = out;
    }

    float acc[4][4][4];
#pragma unroll
    for (int mi = 0; mi < 4; mi++)
#pragma unroll
        for (int ni = 0; ni < 4; ni++)
#pragma unroll
            for (int q = 0; q < 4; q++) acc[mi][ni][q] = 0.f;

    // ldmatrix per-lane offsets within a tile (XOR 32 flips to ks=1)
    uint32_t aOff[4], bOff[2];
#pragma unroll
    for (int mi = 0; mi < 4; mi++)
        aOff[mi] = sw(warpRow * 64 + mi * 16 + (grp & 1) * 8 + laneRow, (grp >> 1) * 8);
#pragma unroll
    for (int p = 0; p < 2; p++)
        bOff[p] = sw(warpCol * 32 + p * 16 + (grp >> 1) * 8 + laneRow, (grp & 1) * 8);

    const int lr = tid >> 2;
    const int lseg = tid & 3;

    auto load_chunk = [&](int ch, int stage) {
        const size_t kpos = kStart + (size_t)ch * 32;
        const uint32_t sb = smb + stage * STAGE_BYTES;
#pragma unroll
        for (int i = 0; i < 2; i++) {
            const int r = lr + i * 64;
            const int soff = sw(r, lseg * 8);
            const size_t ga = (size_t)(rowBase + r) * LD + kpos + lseg * 8;
            const size_t gb = (size_t)(colBase + r) * LD + kpos + lseg * 8;
            cp16(sb + soff,         a0g + ga);
            cp16(sb + 8192 + soff,  a1g + ga);
            cp16(sb + 16384 + soff, b0g + gb);
            cp16(sb + 24576 + soff, b1g + gb);
        }
        asm volatile("cp.async.commit_group;" ::: "memory");
    };

    load_chunk(0, 0);

    for (int ch = 0; ch < NCH; ch++) {
        if (ch + 1 < NCH) {
            load_chunk(ch + 1, (ch + 1) & 1);
            asm volatile("cp.async.wait_group 1;" ::: "memory");
        } else {
            asm volatile("cp.async.wait_group 0;" ::: "memory");
        }
        __syncthreads();

        const uint32_t sA0 = smb + (ch & 1) * STAGE_BYTES;
        const uint32_t sA1 = sA0 + 8192;
        const uint32_t sB0 = sA0 + 16384;
        const uint32_t sB1 = sA0 + 24576;

#pragma unroll
        for (int ks = 0; ks < 2; ks++) {
            const uint32_t kx = ks * 32;
            uint32_t fa0[4][4], fa1[4][4], fb0[2][4], fb1[2][4];
#pragma unroll
            for (int mi = 0; mi < 4; mi++) {
                ldsm4(fa0[mi], sA0 + (aOff[mi] ^ kx));
                ldsm4(fa1[mi], sA1 + (aOff[mi] ^ kx));
            }
#pragma unroll
            for (int p = 0; p < 2; p++) {
                ldsm4(fb0[p], sB0 + (bOff[p] ^ kx));
                ldsm4(fb1[p], sB1 + (bOff[p] ^ kx));
            }
#pragma unroll
            for (int ni = 0; ni < 4; ni++) {
                const uint32_t* b0 = &fb0[ni >> 1][(ni & 1) * 2];
                const uint32_t* b1 = &fb1[ni >> 1][(ni & 1) * 2];
#pragma unroll
                for (int mi = 0; mi < 4; mi++) {
                    mma16816(acc[mi][ni], fa0[mi], b0);
                    mma16816(acc[mi][ni], fa0[mi], b1);
                    mma16816(acc[mi][ni], fa1[mi], b0);
                }
            }
        }
        __syncthreads();
    }

    // epilogue
#pragma unroll
    for (int mi = 0; mi < 4; mi++) {
        const int row0 = rowBase + warpRow * 64 + mi * 16 + g;
#pragma unroll
        for (int ni = 0; ni < 4; ni++) {
            const int col = colBase + warpCol * 32 + ni * 8 + t4 * 2;
            float v0 = acc[mi][ni][0], v1 = acc[mi][ni][1];
            float v2 = acc[mi][ni][2], v3 = acc[mi][ni][3];
            if (MODE == 1) {
                const float m0 = mc[col], m1 = mc[col + 1];
                v0 -= m0; v1 -= m1; v2 -= m0; v3 -= m1;
            }
            *(float2*)(outp + (size_t)row0 * DD + col)       = make_float2(v0, v1);
            *(float2*)(outp + (size_t)(row0 + 8) * DD + col) = make_float2(v2, v3);
            if (MODE == 1) {
                bf16 h0, l0, h1, l1, h2, l2, h3, l3;
                split2(v0, h0, l0); split2(v1, h1, l1);
                split2(v2, h2, l2); split2(v3, h3, l3);
                *(uint32_t*)(so0 + (size_t)row0 * DD + col)       = pack2(h0, h1);
                *(uint32_t*)(so1 + (size_t)row0 * DD + col)       = pack2(l0, l1);
                *(uint32_t*)(so0 + (size_t)(row0 + 8) * DD + col) = pack2(h2, h3);
                *(uint32_t*)(so1 + (size_t)(row0 + 8) * DD + col) = pack2(l2, l3);
            }
        }
    }
}

// ---------------------------------------------------------------------------
// split / transpose kernels
// ---------------------------------------------------------------------------
__global__ void split_rows2_kernel(const float* __restrict__ in,
                                   bf16* __restrict__ s0, bf16* __restrict__ s1,
                                   int n4) {
    int idx = blockIdx.x * 256 + threadIdx.x;
    if (idx >= n4) return;
    float4 v = ((const float4*)in)[idx];
    bf16 h0, l0, h1, l1, h2, l2, h3, l3;
    split2(v.x, h0, l0); split2(v.y, h1, l1);
    split2(v.z, h2, l2); split2(v.w, h3, l3);
    ((uint2*)s0)[idx] = make_uint2(pack2(h0, h1), pack2(h2, h3));
    ((uint2*)s1)[idx] = make_uint2(pack2(l0, l1), pack2(l2, l3));
}

// fp32 [n][512] -> transposed bf16 split planes [512][ldout]
__global__ void split_trans2_kernel(const float* __restrict__ src,
                                    bf16* __restrict__ t0, bf16* __restrict__ t1,
                                    int ldout) {
    __shared__ float ts[32][33];
    const int tid = threadIdx.x;
    const int n0 = blockIdx.x * 32;
    const int d0 = blockIdx.y * 32;
    int r = tid >> 3, c = (tid & 7) * 4;
    float4 v = *(const float4*)(src + (size_t)(n0 + r) * DD + d0 + c);
    ts[r][c] = v.x; ts[r][c + 1] = v.y; ts[r][c + 2] = v.z; ts[r][c + 3] = v.w;
    __syncthreads();
    int cc = tid >> 3, rr = (tid & 7) * 4;
    bf16 h[4], l[4];
#pragma unroll
    for (int i = 0; i < 4; i++) split2(ts[rr + i][cc], h[i], l[i]);
    size_t off = (size_t)(d0 + cc) * ldout + n0 + rr;
    *(uint2*)(t0 + off) = make_uint2(pack2(h[0], h[1]), pack2(h[2], h[3]));
    *(uint2*)(t1 + off) = make_uint2(pack2(l[0], l[1]), pack2(l[2], l[3]));
}

// ---------------------------------------------------------------------------
// fp32 small GEMM (64x64 tile, grid 8x8)
// ---------------------------------------------------------------------------
template <int TA>
__device__ __forceinline__ void load_tiles(float (&As)[16][68], float (&Bs)[16][64],
                                           const float* A, const float* B,
                                           int r0, int c0, int k0, int tid) {
    if (TA == 0) {
        int r = tid >> 2, c = (tid & 3) << 2;
        float4 v = *(const float4*)(A + (size_t)(r0 + r) * DD + k0 + c);
        As[c + 0][r] = v.x; As[c + 1][r] = v.y;
        As[c + 2][r] = v.z; As[c + 3][r] = v.w;
    } else {
        int r = tid >> 4, c = (tid & 15) << 2;
        float4 v = *(const float4*)(A + (size_t)(k0 + r) * DD + r0 + c);
        *(float4*)&As[r][c] = v;
    }
    {
        int r = tid >> 4, c = (tid & 15) << 2;
        *(float4*)&Bs[r][c] = *(const float4*)(B + (size_t)(k0 + r) * DD + c0 + c);
    }
}

// EPI: 0 = C = acc*sc ; 1 = C = acc + I/temp ; 2 = C = 1.5*Pin - 0.5*acc ;
//      3 = C = acc - (kInvTemp*g_scal[0])*Pin
template <int TA, int EPI>
__device__ __forceinline__ void small_body(float* __restrict__ C,
                                           const float* __restrict__ A,
                                           const float* __restrict__ B,
                                           const float* __restrict__ Pin,
                                           float sc) {
    __shared__ __align__(16) float As[16][68];
    __shared__ __align__(16) float Bs[16][64];
    const int tid = threadIdx.x;
    const int tx = tid & 15;
    const int ty = tid >> 4;
    const int r0 = blockIdx.y * 64;
    const int c0 = blockIdx.x * 64;

    u64 acc[4][2];
#pragma unroll
    for (int r = 0; r < 4; r++)
#pragma unroll
        for (int j = 0; j < 2; j++) acc[r][j] = 0ull;

    for (int k0 = 0; k0 < DD; k0 += 16) {
        load_tiles<TA>(As, Bs, A, B, r0, c0, k0, tid);
        __syncthreads();
#pragma unroll
        for (int kk = 0; kk < 16; kk++) {
            float4 a0 = *(const float4*)&As[kk][ty * 4];
            u64 a2[4];
            a2[0] = dup2(a0.x); a2[1] = dup2(a0.y);
            a2[2] = dup2(a0.z); a2[3] = dup2(a0.w);
            u64 b2[2];
#pragma unroll
            for (int j = 0; j < 2; j++)
                b2[j] = *(const u64*)&Bs[kk][(j * 16 + tx) * 2];
#pragma unroll
            for (int r = 0; r < 4; r++)
#pragma unroll
                for (int j = 0; j < 2; j++) ffma2(acc[r][j], a2[r], b2[j]);
        }
        __syncthreads();
    }
#pragma unroll
    for (int r = 0; r < 4; r++) {
#pragma unroll
        for (int j = 0; j < 2; j++) {
            float2 f = upk2(acc[r][j]);
            const size_t row = r0 + ty * 4 + r;
            const int col = c0 + (j * 16 + tx) * 2;
            if (EPI == 0) {
                f.x *= sc; f.y *= sc;
            } else if (EPI == 1) {
                if ((int)row == col)     f.x += kInvTemp;
                if ((int)row == col + 1) f.y += kInvTemp;
            } else if (EPI == 2) {
                f.x = 1.5f * Pin[row * DD + col]     - 0.5f * f.x;
                f.y = 1.5f * Pin[row * DD + col + 1] - 0.5f * f.y;
            } else if (EPI == 3) {
                const float cc2 = kInvTemp * g_scal[0];
                f.x -= cc2 * Pin[row * DD + col];
                f.y -= cc2 * Pin[row * DD + col + 1];
            }
            *(float2*)(C + row * DD + col) = f;
        }
    }
}

template <int TA, int EPI>
__global__ __launch_bounds__(256)
void gemm512(float* __restrict__ C, const float* __restrict__ A,
             const float* __restrict__ B, const float* __restrict__ Pin,
             int scalesel) {
    float sc = (scalesel == 1) ? g_scal[0] : (scalesel == 2) ? g_scal[1] : 1.0f;
    small_body<TA, EPI>(C, A, B, Pin, sc);
}

__global__ __launch_bounds__(256)
void gemm_pair(const float* __restrict__ P) {
    if (blockIdx.z == 0) small_body<0, 0>(g_A1, P, P, nullptr, 1.0f);
    else                 small_body<0, 0>(g_A2, P, g_cov, nullptr, g_scal[0]);
}
__global__ __launch_bounds__(256)
void gemm_upd(float* __restrict__ Pn, const float* __restrict__ P) {
    small_body<0, 2>(Pn, g_A1, g_A2, P, 1.0f);
}

// ---------------------------------------------------------------------------
// reductions / vectors
// ---------------------------------------------------------------------------
__global__ void colsum_kernel(const float* __restrict__ H) {
    const int b = blockIdx.x;
    const int t = threadIdx.x;
    const float* p = H + (size_t)b * 256 * DD + t;
    float s = 0.f;
#pragma unroll 8
    for (int r = 0; r < 256; r++) s += p[(size_t)r * DD];
    g_colpart[b * DD + t] = s;
}

__global__ void mean_final_kernel() {
    const int t = threadIdx.x;
    float s = 0.f;
#pragma unroll 8
    for (int b = 0; b < 256; b++) s += g_colpart[b * DD + t];
    g_mean[t] = s * (1.0f / (float)NROWS);
}

__global__ void reduce_sig_kernel() {
    const int idx = blockIdx.x * 1024 + threadIdx.x;
    const int i = idx >> 9, j = idx & (DD - 1);
    const int src = ((i >> 7) <= (j >> 7)) ? (i * DD + j) : (j * DD + i);
    float s = 0.f;
#pragma unroll
    for (int z = 0; z < NSPLIT; z++)
        s += g_covpart[(size_t)z * DD * DD + src];
    g_sig[idx] = s * (1.0f / (float)NROWS) - g_mean[i] * g_mean[j];
}

__global__ void trace_kernel() {
    __shared__ float sm[512];
    const int t = threadIdx.x;
    sm[t] = g_cov[(size_t)t * DD + t];
    __syncthreads();
    for (int s = 256; s > 0; s >>= 1) {
        if (t < s) sm[t] += sm[t + s];
        __syncthreads();
    }
    if (t == 0) {
        float tr = sm[0];
        g_scal[0] = 1.0f / tr;
        g_scal[1] = 1.0f / sqrtf(tr);
    }
}

__global__ void init_P_kernel(float* __restrict__ P) {
    const int idx = blockIdx.x * 1024 + threadIdx.x;
    const int i = idx >> 9, j = idx & (DD - 1);
    P[idx] = ((i == j) ? 1.5f : 0.0f) - 0.5f * g_cov[idx] * g_scal[0];
}

// mc[n] = sum_k mean[k] * M[k][n]   (M includes 1/sqrt(tr))
__global__ void mc_kernel(const float* __restrict__ M, float* __restrict__ mc) {
    __shared__ float sm[256];
    const int n = blockIdx.x, t = threadIdx.x;
    float s = g_mean[t] * M[(size_t)t * DD + n]
            + g_mean[t + 256] * M[(size_t)(t + 256) * DD + n];
    sm[t] = s;
    __syncthreads();
    for (int k = 128; k > 0; k >>= 1) {
        if (t < k) sm[t] += sm[t + k];
        __syncthreads();
    }
    if (t == 0) mc[n] = sm[0];
}

__global__ void zero_mc12_kernel() { g_mcv[DD + threadIdx.x] = 0.f; }  // layers 1,2

// ---------------------------------------------------------------------------
// orchestration — two-stream fork/join inside graph capture
// ---------------------------------------------------------------------------
extern "C" void kernel_launch(void* const* d_in, const int* in_sizes, int n_in,
                              void* d_out, int out_size) {
    (void)in_sizes; (void)n_in; (void)out_size;
    const float* x = (const float*)d_in[0];
    const float* W[3] = {(const float*)d_in[1], (const float*)d_in[2],
                         (const float*)d_in[3]};
    float* out = (float*)d_out;

    float *pcovpart, *psig, *pcov, *pT1, *pM, *pP0, *pP1, *pA1, *pA2, *pmc;
    bf16 *psA0, *psA1, *psB0, *psB1, *pt0, *pt1, *pw0, *pw1;
    cudaGetSymbolAddress((void**)&pcovpart, g_covpart);
    cudaGetSymbolAddress((void**)&psig, g_sig);
    cudaGetSymbolAddress((void**)&pcov, g_cov);
    cudaGetSymbolAddress((void**)&pT1, g_T1);
    cudaGetSymbolAddress((void**)&pM, g_M);
    cudaGetSymbolAddress((void**)&pP0, g_P0);
    cudaGetSymbolAddress((void**)&pP1, g_P1);
    cudaGetSymbolAddress((void**)&pA1, g_A1);
    cudaGetSymbolAddress((void**)&pA2, g_A2);
    cudaGetSymbolAddress((void**)&pmc, g_mcv);
    cudaGetSymbolAddress((void**)&psA0, g_sA0);
    cudaGetSymbolAddress((void**)&psA1, g_sA1);
    cudaGetSymbolAddress((void**)&psB0, g_sB0);
    cudaGetSymbolAddress((void**)&psB1, g_sB1);
    cudaGetSymbolAddress((void**)&pt0, g_t0);
    cudaGetSymbolAddress((void**)&pt1, g_t1);
    cudaGetSymbolAddress((void**)&pw0, g_w0);
    cudaGetSymbolAddress((void**)&pw1, g_w1);

    cudaFuncSetAttribute(mma_gemm<1>, cudaFuncAttributeMaxDynamicSharedMemorySize, SMEMSZ);
    cudaFuncSetAttribute(mma_gemm<2>, cudaFuncAttributeMaxDynamicSharedMemorySize, SMEMSZ);

    cudaStream_t s2;
    cudaStreamCreateWithFlags(&s2, cudaStreamNonBlocking);
    cudaEvent_t evGram, evM[3];
    cudaEventCreateWithFlags(&evGram, cudaEventDisableTiming);
    for (int i = 0; i < 3; i++) cudaEventCreateWithFlags(&evM[i], cudaEventDisableTiming);

    const int N4BIG = NROWS * DD / 4;
    const dim3 gact(4, NROWS / 128);
    const dim3 gcov(10, 1, NSPLIT);
    const dim3 gsm(8, 8);

    // ---- stream 0: x prep + Gram (launch #6 = Gram MMA kernel for ncu) ----
    split_rows2_kernel<<<N4BIG / 256, 256>>>(x, psA0, psA1, N4BIG);                 // 1
    split_trans2_kernel<<<dim3(NROWS / 32, 16), 256>>>(x, pt0, pt1, NROWS);         // 2
    colsum_kernel<<<256, 512>>>(x);                                                 // 3
    mean_final_kernel<<<1, 512>>>();                                                // 4
    zero_mc12_kernel<<<1, 1024>>>();                                                // 5
    mma_gemm<2><<<gcov, 256, SMEMSZ>>>(pt0, pt1, pt0, pt1, pcovpart,
                                       nullptr, nullptr, nullptr);                  // 6
    reduce_sig_kernel<<<256, 1024>>>();                                             // 7
    cudaEventRecord(evGram, 0);

    // ---- stream s2: whole small-matrix chain for all 3 layers ----
    cudaStreamWaitEvent(s2, evGram, 0);
    for (int l = 0; l < 3; l++) {
        gemm512<0, 0><<<gsm, 256, 0, s2>>>(pT1, psig, W[l], nullptr, 0);   // T1 = Sig @ W
        gemm512<1, 1><<<gsm, 256, 0, s2>>>(pcov, W[l], pT1, nullptr, 0);   // cov = W^T T1 + I/temp
        trace_kernel<<<1, 512, 0, s2>>>();
        init_P_kernel<<<256, 1024, 0, s2>>>(pP0);

        float* P = pP0;
        float* Pn = pP1;
        for (int it = 1; it < 10; it++) {
            gemm_pair<<<dim3(8, 8, 2), 256, 0, s2>>>(P);
            gemm_upd<<<gsm, 256, 0, s2>>>(Pn, P);
            float* t = P; P = Pn; Pn = t;
        }

        gemm_pair<<<dim3(8, 8, 2), 256, 0, s2>>>(P);                        // A1=P@P, A2=(P@cov)/tr
        gemm512<0, 0><<<gsm, 256, 0, s2>>>(pM, W[l], P, nullptr, 2);        // M = W@P*scal1
        gemm512<0, 3><<<gsm, 256, 0, s2>>>(psig, pA2, P, pA1, 0);           // Sig' for next layer
        split_trans2_kernel<<<dim3(16, 16), 256, 0, s2>>>(pM, pw0 + (size_t)l * DD * DD,
                                                          pw1 + (size_t)l * DD * DD, DD);
        if (l == 0) mc_kernel<<<512, 256, 0, s2>>>(pM, pmc);
        cudaEventRecord(evM[l], s2);
    }

    // ---- stream 0: the three big out-GEMMs, each gated on its M ----
    bf16* in0 = psA0; bf16* in1 = psA1;
    bf16* ot0 = psB0; bf16* ot1 = psB1;
    for (int l = 0; l < 3; l++) {
        float* O = out + (size_t)l * NROWS * DD;
        cudaStreamWaitEvent(0, evM[l], 0);
        mma_gemm<1><<<gact, 256, SMEMSZ>>>(in0, in1,
                                           pw0 + (size_t)l * DD * DD,
                                           pw1 + (size_t)l * DD * DD,
                                           O, pmc + l * DD, ot0, ot1);
        bf16* t0s = in0; in0 = ot0; ot0 = t0s;
        bf16* t1s = in1; in1 = ot1; ot1 = t1s;
    }
}

// round 9
// speedup vs baseline: 1.3833x; 1.0326x over previous
#include <cuda_runtime.h>
#include <cuda_bf16.h>
#include <math.h>
#include <stdint.h>

#define NROWS 65536
#define DD    512
#define NSPLIT 32
static __device__ __constant__ float kInvTemp = 0.1f;

typedef unsigned long long u64;
typedef __nv_bfloat16 bf16;

// ---------------------------------------------------------------------------
// helpers
// ---------------------------------------------------------------------------
__device__ __forceinline__ uint32_t smem_u32(const void* p) {
    uint32_t a;
    asm("{ .reg .u64 t; cvta.to.shared.u64 t, %1; cvt.u32.u64 %0, t; }"
        : "=r"(a) : "l"(p));
    return a;
}
__device__ __forceinline__ void cp16(uint32_t dst, const void* src) {
    asm volatile("cp.async.cg.shared.global [%0], [%1], 16;"
                 :: "r"(dst), "l"(src) : "memory");
}
__device__ __forceinline__ void mma16816(float* c, const uint32_t* a,
                                         const uint32_t* b) {
    asm volatile(
        "mma.sync.aligned.m16n8k16.row.col.f32.bf16.bf16.f32 "
        "{%0,%1,%2,%3}, {%4,%5,%6,%7}, {%8,%9}, {%0,%1,%2,%3};"
        : "+f"(c[0]), "+f"(c[1]), "+f"(c[2]), "+f"(c[3])
        : "r"(a[0]), "r"(a[1]), "r"(a[2]), "r"(a[3]), "r"(b[0]), "r"(b[1]));
}
__device__ __forceinline__ void ldsm4(uint32_t* r, uint32_t addr) {
    asm volatile("ldmatrix.sync.aligned.m8n8.x4.shared.b16 {%0,%1,%2,%3}, [%4];"
                 : "=r"(r[0]), "=r"(r[1]), "=r"(r[2]), "=r"(r[3]) : "r"(addr));
}
// swizzled smem byte offset within a [128][32] bf16 tile (8KB)
__device__ __forceinline__ int sw(int r, int k) {
    int s = ((k >> 3) ^ (r & 3) ^ ((r >> 2) & 1)) & 3;
    return r * 64 + s * 16 + (k & 7) * 2;
}
__device__ __forceinline__ void split2(float x, bf16 &hi, bf16 &lo) {
    hi = __float2bfloat16_rn(x);
    lo = __float2bfloat16_rn(x - __bfloat162float(hi));
}
__device__ __forceinline__ uint32_t pack2(bf16 a, bf16 b) {
    __nv_bfloat162 v(a, b);
    return *reinterpret_cast<uint32_t*>(&v);
}
__device__ __forceinline__ void ffma2(u64 &d, u64 a, u64 b) {
    asm("fma.rn.f32x2 %0, %1, %2, %0;" : "+l"(d) : "l"(a), "l"(b));
}
__device__ __forceinline__ float2 upk2(u64 v) {
    float2 r;
    asm("mov.b64 {%0, %1}, %2;" : "=f"(r.x), "=f"(r.y) : "l"(v));
    return r;
}
__device__ __forceinline__ u64 dup2(float x) {
    u64 r;
    asm("mov.b64 %0, {%1, %1};" : "=l"(r) : "f"(x));
    return r;
}

// ---------------------------------------------------------------------------
// scratch
// ---------------------------------------------------------------------------
__device__ float g_colpart[256 * DD];
__device__ float g_mean[DD];
__device__ float g_mcv[3 * DD];
__device__ float g_covpart[(size_t)NSPLIT * DD * DD];
__device__ float g_sig[DD * DD];
__device__ float g_cov[DD * DD];
__device__ float g_T1[DD * DD];
__device__ float g_M[DD * DD];
__device__ float g_P0[DD * DD];
__device__ float g_P1[DD * DD];
__device__ float g_A1[DD * DD];
__device__ float g_A2[DD * DD];
__device__ float g_scal[2];
__device__ bf16 g_sA0[(size_t)NROWS * DD];
__device__ bf16 g_sA1[(size_t)NROWS * DD];
__device__ bf16 g_sB0[(size_t)NROWS * DD];
__device__ bf16 g_sB1[(size_t)NROWS * DD];
__device__ bf16 g_t0[(size_t)DD * NROWS];
__device__ bf16 g_t1[(size_t)DD * NROWS];
__device__ bf16 g_w0[3 * DD * DD];
__device__ bf16 g_w1[3 * DD * DD];

__constant__ int cTI[10] = {0,0,0,0,1,1,1,2,2,3};
__constant__ int cTJ[10] = {0,1,2,3,1,2,3,2,3,3};

// ---------------------------------------------------------------------------
// Double-buffered bf16-split mma.sync GEMM with ldmatrix fragment loads.
// 128x128 CTA tile, BK=32. acc += A0*B0 + A0*B1 + A1*B0.
// MODE 1: out = acc - mc[col] (fp32) + bf16 splits of result
// MODE 2: Gram split-K partial -> out + z*DD*DD (upper-triangle tiles)
// ---------------------------------------------------------------------------
#define STAGE_BYTES 32768
#define SMEMSZ (2 * STAGE_BYTES)

template <int MODE>
__global__ __launch_bounds__(256, 2)
void mma_gemm(const bf16* __restrict__ a0g, const bf16* __restrict__ a1g,
              const bf16* __restrict__ b0g, const bf16* __restrict__ b1g,
              float* __restrict__ out, const float* __restrict__ mc,
              bf16* __restrict__ so0, bf16* __restrict__ so1) {
    constexpr int LD  = (MODE == 2) ? NROWS : DD;
    constexpr int NCH = (MODE == 2) ? (NROWS / NSPLIT / 32) : (DD / 32);

    extern __shared__ __align__(128) char sm[];
    const uint32_t smb = smem_u32(sm);

    const int tid = threadIdx.x;
    const int lane = tid & 31, wid = tid >> 5;
    const int warpRow = wid & 1;
    const int warpCol = wid >> 1;
    const int g = lane >> 2, t4 = lane & 3;
    const int laneRow = lane & 7, grp = lane >> 3;

    int rowBase, colBase;
    size_t kStart;
    float* outp;
    if (MODE == 2) {
        rowBase = cTI[blockIdx.x] * 128;
        colBase = cTJ[blockIdx.x] * 128;
        kStart  = (size_t)blockIdx.z * (NROWS / NSPLIT);
        outp = out + (size_t)blockIdx.z * DD * DD;
    } else {
        rowBase = blockIdx.y * 128;
        colBase = blockIdx.x * 128;
        kStart = 0;
        outp = out;
    }

    float acc[4][4][4];
#pragma unroll
    for (int mi = 0; mi < 4; mi++)
#pragma unroll
        for (int ni = 0; ni < 4; ni++)
#pragma unroll
            for (int q = 0; q < 4; q++) acc[mi][ni][q] = 0.f;

    uint32_t aOff[4], bOff[2];
#pragma unroll
    for (int mi = 0; mi < 4; mi++)
        aOff[mi] = sw(warpRow * 64 + mi * 16 + (grp & 1) * 8 + laneRow, (grp >> 1) * 8);
#pragma unroll
    for (int p = 0; p < 2; p++)
        bOff[p] = sw(warpCol * 32 + p * 16 + (grp >> 1) * 8 + laneRow, (grp & 1) * 8);

    const int lr = tid >> 2;
    const int lseg = tid & 3;

    auto load_chunk = [&](int ch, int stage) {
        const size_t kpos = kStart + (size_t)ch * 32;
        const uint32_t sb = smb + stage * STAGE_BYTES;
#pragma unroll
        for (int i = 0; i < 2; i++) {
            const int r = lr + i * 64;
            const int soff = sw(r, lseg * 8);
            const size_t ga = (size_t)(rowBase + r) * LD + kpos + lseg * 8;
            const size_t gb = (size_t)(colBase + r) * LD + kpos + lseg * 8;
            cp16(sb + soff,         a0g + ga);
            cp16(sb + 8192 + soff,  a1g + ga);
            cp16(sb + 16384 + soff, b0g + gb);
            cp16(sb + 24576 + soff, b1g + gb);
        }
        asm volatile("cp.async.commit_group;" ::: "memory");
    };

    load_chunk(0, 0);

    for (int ch = 0; ch < NCH; ch++) {
        if (ch + 1 < NCH) {
            load_chunk(ch + 1, (ch + 1) & 1);
            asm volatile("cp.async.wait_group 1;" ::: "memory");
        } else {
            asm volatile("cp.async.wait_group 0;" ::: "memory");
        }
        __syncthreads();

        const uint32_t sA0 = smb + (ch & 1) * STAGE_BYTES;
        const uint32_t sA1 = sA0 + 8192;
        const uint32_t sB0 = sA0 + 16384;
        const uint32_t sB1 = sA0 + 24576;

#pragma unroll
        for (int ks = 0; ks < 2; ks++) {
            const uint32_t kx = ks * 32;
            uint32_t fa0[4][4], fa1[4][4], fb0[2][4], fb1[2][4];
#pragma unroll
            for (int mi = 0; mi < 4; mi++) {
                ldsm4(fa0[mi], sA0 + (aOff[mi] ^ kx));
                ldsm4(fa1[mi], sA1 + (aOff[mi] ^ kx));
            }
#pragma unroll
            for (int p = 0; p < 2; p++) {
                ldsm4(fb0[p], sB0 + (bOff[p] ^ kx));
                ldsm4(fb1[p], sB1 + (bOff[p] ^ kx));
            }
#pragma unroll
            for (int ni = 0; ni < 4; ni++) {
                const uint32_t* b0 = &fb0[ni >> 1][(ni & 1) * 2];
                const uint32_t* b1 = &fb1[ni >> 1][(ni & 1) * 2];
#pragma unroll
                for (int mi = 0; mi < 4; mi++) {
                    mma16816(acc[mi][ni], fa0[mi], b0);
                    mma16816(acc[mi][ni], fa0[mi], b1);
                    mma16816(acc[mi][ni], fa1[mi], b0);
                }
            }
        }
        __syncthreads();
    }

    // epilogue
#pragma unroll
    for (int mi = 0; mi < 4; mi++) {
        const int row0 = rowBase + warpRow * 64 + mi * 16 + g;
#pragma unroll
        for (int ni = 0; ni < 4; ni++) {
            const int col = colBase + warpCol * 32 + ni * 8 + t4 * 2;
            float v0 = acc[mi][ni][0], v1 = acc[mi][ni][1];
            float v2 = acc[mi][ni][2], v3 = acc[mi][ni][3];
            if (MODE == 1) {
                const float m0 = mc[col], m1 = mc[col + 1];
                v0 -= m0; v1 -= m1; v2 -= m0; v3 -= m1;
            }
            *(float2*)(outp + (size_t)row0 * DD + col)       = make_float2(v0, v1);
            *(float2*)(outp + (size_t)(row0 + 8) * DD + col) = make_float2(v2, v3);
            if (MODE == 1) {
                bf16 h0, l0, h1, l1, h2, l2, h3, l3;
                split2(v0, h0, l0); split2(v1, h1, l1);
                split2(v2, h2, l2); split2(v3, h3, l3);
                *(uint32_t*)(so0 + (size_t)row0 * DD + col)       = pack2(h0, h1);
                *(uint32_t*)(so1 + (size_t)row0 * DD + col)       = pack2(l0, l1);
                *(uint32_t*)(so0 + (size_t)(row0 + 8) * DD + col) = pack2(h2, h3);
                *(uint32_t*)(so1 + (size_t)(row0 + 8) * DD + col) = pack2(l2, l3);
            }
        }
    }
}

// ---------------------------------------------------------------------------
// split / transpose kernels
// ---------------------------------------------------------------------------
__global__ void split_rows2_kernel(const float* __restrict__ in,
                                   bf16* __restrict__ s0, bf16* __restrict__ s1,
                                   int n4) {
    int idx = blockIdx.x * 256 + threadIdx.x;
    if (idx >= n4) return;
    float4 v = ((const float4*)in)[idx];
    bf16 h0, l0, h1, l1, h2, l2, h3, l3;
    split2(v.x, h0, l0); split2(v.y, h1, l1);
    split2(v.z, h2, l2); split2(v.w, h3, l3);
    ((uint2*)s0)[idx] = make_uint2(pack2(h0, h1), pack2(h2, h3));
    ((uint2*)s1)[idx] = make_uint2(pack2(l0, l1), pack2(l2, l3));
}

// fp32 [n][512] -> transposed bf16 split planes [512][ldout]
__global__ void split_trans2_kernel(const float* __restrict__ src,
                                    bf16* __restrict__ t0, bf16* __restrict__ t1,
                                    int ldout) {
    __shared__ float ts[32][33];
    const int tid = threadIdx.x;
    const int n0 = blockIdx.x * 32;
    const int d0 = blockIdx.y * 32;
    int r = tid >> 3, c = (tid & 7) * 4;
    float4 v = *(const float4*)(src + (size_t)(n0 + r) * DD + d0 + c);
    ts[r][c] = v.x; ts[r][c + 1] = v.y; ts[r][c + 2] = v.z; ts[r][c + 3] = v.w;
    __syncthreads();
    int cc = tid >> 3, rr = (tid & 7) * 4;
    bf16 h[4], l[4];
#pragma unroll
    for (int i = 0; i < 4; i++) split2(ts[rr + i][cc], h[i], l[i]);
    size_t off = (size_t)(d0 + cc) * ldout + n0 + rr;
    *(uint2*)(t0 + off) = make_uint2(pack2(h[0], h[1]), pack2(h[2], h[3]));
    *(uint2*)(t1 + off) = make_uint2(pack2(l[0], l[1]), pack2(l[2], l[3]));
}

// ---------------------------------------------------------------------------
// fp32 small GEMM (64x64 tile, grid 8x8)
// ---------------------------------------------------------------------------
template <int TA>
__device__ __forceinline__ void load_tiles(float (&As)[16][68], float (&Bs)[16][64],
                                           const float* A, const float* B,
                                           int r0, int c0, int k0, int tid) {
    if (TA == 0) {
        int r = tid >> 2, c = (tid & 3) << 2;
        float4 v = *(const float4*)(A + (size_t)(r0 + r) * DD + k0 + c);
        As[c + 0][r] = v.x; As[c + 1][r] = v.y;
        As[c + 2][r] = v.z; As[c + 3][r] = v.w;
    } else {
        int r = tid >> 4, c = (tid & 15) << 2;
        float4 v = *(const float4*)(A + (size_t)(k0 + r) * DD + r0 + c);
        *(float4*)&As[r][c] = v;
    }
    {
        int r = tid >> 4, c = (tid & 15) << 2;
        *(float4*)&Bs[r][c] = *(const float4*)(B + (size_t)(k0 + r) * DD + c0 + c);
    }
}

// EPI: 0 = C = acc*sc ; 1 = C = acc + I/temp ; 2 = C = 1.5*Pin - 0.5*acc ;
//      3 = C = acc - (kInvTemp*g_scal[0])*Pin
template <int TA, int EPI>
__device__ __forceinline__ void small_body(float* __restrict__ C,
                                           const float* __restrict__ A,
                                           const float* __restrict__ B,
                                           const float* __restrict__ Pin,
                                           float sc) {
    __shared__ __align__(16) float As[16][68];
    __shared__ __align__(16) float Bs[16][64];
    const int tid = threadIdx.x;
    const int tx = tid & 15;
    const int ty = tid >> 4;
    const int r0 = blockIdx.y * 64;
    const int c0 = blockIdx.x * 64;

    u64 acc[4][2];
#pragma unroll
    for (int r = 0; r < 4; r++)
#pragma unroll
        for (int j = 0; j < 2; j++) acc[r][j] = 0ull;

    for (int k0 = 0; k0 < DD; k0 += 16) {
        load_tiles<TA>(As, Bs, A, B, r0, c0, k0, tid);
        __syncthreads();
#pragma unroll
        for (int kk = 0; kk < 16; kk++) {
            float4 a0 = *(const float4*)&As[kk][ty * 4];
            u64 a2[4];
            a2[0] = dup2(a0.x); a2[1] = dup2(a0.y);
            a2[2] = dup2(a0.z); a2[3] = dup2(a0.w);
            u64 b2[2];
#pragma unroll
            for (int j = 0; j < 2; j++)
                b2[j] = *(const u64*)&Bs[kk][(j * 16 + tx) * 2];
#pragma unroll
            for (int r = 0; r < 4; r++)
#pragma unroll
                for (int j = 0; j < 2; j++) ffma2(acc[r][j], a2[r], b2[j]);
        }
        __syncthreads();
    }
#pragma unroll
    for (int r = 0; r < 4; r++) {
#pragma unroll
        for (int j = 0; j < 2; j++) {
            float2 f = upk2(acc[r][j]);
            const size_t row = r0 + ty * 4 + r;
            const int col = c0 + (j * 16 + tx) * 2;
            if (EPI == 0) {
                f.x *= sc; f.y *= sc;
            } else if (EPI == 1) {
                if ((int)row == col)     f.x += kInvTemp;
                if ((int)row == col + 1) f.y += kInvTemp;
            } else if (EPI == 2) {
                f.x = 1.5f * Pin[row * DD + col]     - 0.5f * f.x;
                f.y = 1.5f * Pin[row * DD + col + 1] - 0.5f * f.y;
            } else if (EPI == 3) {
                const float cc2 = kInvTemp * g_scal[0];
                f.x -= cc2 * Pin[row * DD + col];
                f.y -= cc2 * Pin[row * DD + col + 1];
            }
            *(float2*)(C + row * DD + col) = f;
        }
    }
}

template <int TA, int EPI>
__global__ __launch_bounds__(256)
void gemm512(float* __restrict__ C, const float* __restrict__ A,
             const float* __restrict__ B, const float* __restrict__ Pin,
             int scalesel) {
    float sc = (scalesel == 1) ? g_scal[0] : (scalesel == 2) ? g_scal[1] : 1.0f;
    small_body<TA, EPI>(C, A, B, Pin, sc);
}

__global__ __launch_bounds__(256)
void gemm_pair(const float* __restrict__ P) {
    if (blockIdx.z == 0) small_body<0, 0>(g_A1, P, P, nullptr, 1.0f);
    else                 small_body<0, 0>(g_A2, P, g_cov, nullptr, g_scal[0]);
}
__global__ __launch_bounds__(256)
void gemm_upd(float* __restrict__ Pn, const float* __restrict__ P) {
    small_body<0, 2>(Pn, g_A1, g_A2, P, 1.0f);
}

// ---------------------------------------------------------------------------
// reductions / vectors
// ---------------------------------------------------------------------------
__global__ void colsum_kernel(const float* __restrict__ H) {
    const int b = blockIdx.x;
    const int t = threadIdx.x;
    const float* p = H + (size_t)b * 256 * DD + t;
    float s = 0.f;
#pragma unroll 8
    for (int r = 0; r < 256; r++) s += p[(size_t)r * DD];
    g_colpart[b * DD + t] = s;
}

__global__ void mean_final_kernel() {
    const int t = threadIdx.x;
    float s = 0.f;
#pragma unroll 8
    for (int b = 0; b < 256; b++) s += g_colpart[b * DD + t];
    g_mean[t] = s * (1.0f / (float)NROWS);
}

__global__ void reduce_sig_kernel() {
    const int idx = blockIdx.x * 1024 + threadIdx.x;
    const int i = idx >> 9, j = idx & (DD - 1);
    const int src = ((i >> 7) <= (j >> 7)) ? (i * DD + j) : (j * DD + i);
    float s = 0.f;
#pragma unroll
    for (int z = 0; z < NSPLIT; z++)
        s += g_covpart[(size_t)z * DD * DD + src];
    g_sig[idx] = s * (1.0f / (float)NROWS) - g_mean[i] * g_mean[j];
}

__global__ void trace_kernel() {
    __shared__ float sm[512];
    const int t = threadIdx.x;
    sm[t] = g_cov[(size_t)t * DD + t];
    __syncthreads();
    for (int s = 256; s > 0; s >>= 1) {
        if (t < s) sm[t] += sm[t + s];
        __syncthreads();
    }
    if (t == 0) {
        float tr = sm[0];
        g_scal[0] = 1.0f / tr;
        g_scal[1] = 1.0f / sqrtf(tr);
    }
}

__global__ void init_P_kernel(float* __restrict__ P) {
    const int idx = blockIdx.x * 1024 + threadIdx.x;
    const int i = idx >> 9, j = idx & (DD - 1);
    P[idx] = ((i == j) ? 1.5f : 0.0f) - 0.5f * g_cov[idx] * g_scal[0];
}

__global__ void mc_kernel(const float* __restrict__ M, float* __restrict__ mc) {
    __shared__ float sm[256];
    const int n = blockIdx.x, t = threadIdx.x;
    float s = g_mean[t] * M[(size_t)t * DD + n]
            + g_mean[t + 256] * M[(size_t)(t + 256) * DD + n];
    sm[t] = s;
    __syncthreads();
    for (int k = 128; k > 0; k >>= 1) {
        if (t < k) sm[t] += sm[t + k];
        __syncthreads();
    }
    if (t == 0) mc[n] = sm[0];
}

__global__ void zero_mc12_kernel() { g_mcv[DD + threadIdx.x] = 0.f; }

// ---------------------------------------------------------------------------
// orchestration — two-stream fork/join; s2 joins capture via evRoot BEFORE
// any s2 launch (round-8 capture failure fix). Gram = our 4th launch (ncu).
// ---------------------------------------------------------------------------
extern "C" void kernel_launch(void* const* d_in, const int* in_sizes, int n_in,
                              void* d_out, int out_size) {
    (void)in_sizes; (void)n_in; (void)out_size;
    const float* x = (const float*)d_in[0];
    const float* W[3] = {(const float*)d_in[1], (const float*)d_in[2],
                         (const float*)d_in[3]};
    float* out = (float*)d_out;

    float *pcovpart, *psig, *pcov, *pT1, *pM, *pP0, *pP1, *pA1, *pA2, *pmc;
    bf16 *psA0, *psA1, *psB0, *psB1, *pt0, *pt1, *pw0, *pw1;
    cudaGetSymbolAddress((void**)&pcovpart, g_covpart);
    cudaGetSymbolAddress((void**)&psig, g_sig);
    cudaGetSymbolAddress((void**)&pcov, g_cov);
    cudaGetSymbolAddress((void**)&pT1, g_T1);
    cudaGetSymbolAddress((void**)&pM, g_M);
    cudaGetSymbolAddress((void**)&pP0, g_P0);
    cudaGetSymbolAddress((void**)&pP1, g_P1);
    cudaGetSymbolAddress((void**)&pA1, g_A1);
    cudaGetSymbolAddress((void**)&pA2, g_A2);
    cudaGetSymbolAddress((void**)&pmc, g_mcv);
    cudaGetSymbolAddress((void**)&psA0, g_sA0);
    cudaGetSymbolAddress((void**)&psA1, g_sA1);
    cudaGetSymbolAddress((void**)&psB0, g_sB0);
    cudaGetSymbolAddress((void**)&psB1, g_sB1);
    cudaGetSymbolAddress((void**)&pt0, g_t0);
    cudaGetSymbolAddress((void**)&pt1, g_t1);
    cudaGetSymbolAddress((void**)&pw0, g_w0);
    cudaGetSymbolAddress((void**)&pw1, g_w1);

    cudaFuncSetAttribute(mma_gemm<1>, cudaFuncAttributeMaxDynamicSharedMemorySize, SMEMSZ);
    cudaFuncSetAttribute(mma_gemm<2>, cudaFuncAttributeMaxDynamicSharedMemorySize, SMEMSZ);

    cudaStream_t s2;
    cudaStreamCreateWithFlags(&s2, cudaStreamNonBlocking);
    cudaEvent_t evRoot, evMean, evSig, evM[3];
    cudaEventCreateWithFlags(&evRoot, cudaEventDisableTiming);
    cudaEventCreateWithFlags(&evMean, cudaEventDisableTiming);
    cudaEventCreateWithFlags(&evSig, cudaEventDisableTiming);
    for (int i = 0; i < 3; i++) cudaEventCreateWithFlags(&evM[i], cudaEventDisableTiming);

    const int N4BIG = NROWS * DD / 4;
    const dim3 gact(4, NROWS / 128);
    const dim3 gcov(10, 1, NSPLIT);
    const dim3 gsm(8, 8);

    // #1 on origin stream, then fork s2 via evRoot (capture-legal)
    split_trans2_kernel<<<dim3(NROWS / 32, 16), 256>>>(x, pt0, pt1, NROWS);     // #1
    cudaEventRecord(evRoot, 0);
    cudaStreamWaitEvent(s2, evRoot, 0);

    split_rows2_kernel<<<N4BIG / 256, 256, 0, s2>>>(x, psA0, psA1, N4BIG);      // #2
    colsum_kernel<<<256, 512, 0, s2>>>(x);                                      // #3
    mma_gemm<2><<<gcov, 256, SMEMSZ>>>(pt0, pt1, pt0, pt1, pcovpart,
                                       nullptr, nullptr, nullptr);              // #4 (ncu)
    mean_final_kernel<<<1, 512, 0, s2>>>();                                     // #5
    zero_mc12_kernel<<<1, 1024, 0, s2>>>();                                     // #6
    cudaEventRecord(evMean, s2);

    cudaStreamWaitEvent(0, evMean, 0);
    reduce_sig_kernel<<<256, 1024>>>();                                         // #7
    cudaEventRecord(evSig, 0);

    // ---- stream s2: whole small-matrix chain for all 3 layers ----
    cudaStreamWaitEvent(s2, evSig, 0);
    for (int l = 0; l < 3; l++) {
        gemm512<0, 0><<<gsm, 256, 0, s2>>>(pT1, psig, W[l], nullptr, 0);
        gemm512<1, 1><<<gsm, 256, 0, s2>>>(pcov, W[l], pT1, nullptr, 0);
        trace_kernel<<<1, 512, 0, s2>>>();
        init_P_kernel<<<256, 1024, 0, s2>>>(pP0);

        float* P = pP0;
        float* Pn = pP1;
        for (int it = 1; it < 10; it++) {
            gemm_pair<<<dim3(8, 8, 2), 256, 0, s2>>>(P);
            gemm_upd<<<gsm, 256, 0, s2>>>(Pn, P);
            float* t = P; P = Pn; Pn = t;
        }

        gemm_pair<<<dim3(8, 8, 2), 256, 0, s2>>>(P);
        gemm512<0, 0><<<gsm, 256, 0, s2>>>(pM, W[l], P, nullptr, 2);
        gemm512<0, 3><<<gsm, 256, 0, s2>>>(psig, pA2, P, pA1, 0);
        split_trans2_kernel<<<dim3(16, 16), 256, 0, s2>>>(pM, pw0 + (size_t)l * DD * DD,
                                                          pw1 + (size_t)l * DD * DD, DD);
        if (l == 0) mc_kernel<<<512, 256, 0, s2>>>(pM, pmc);
        cudaEventRecord(evM[l], s2);
    }

    // ---- stream 0: three big out-GEMMs, each gated on its M ----
    bf16* in0 = psA0; bf16* in1 = psA1;
    bf16* ot0 = psB0; bf16* ot1 = psB1;
    for (int l = 0; l < 3; l++) {
        float* O = out + (size_t)l * NROWS * DD;
        cudaStreamWaitEvent(0, evM[l], 0);
        mma_gemm<1><<<gact, 256, SMEMSZ>>>(in0, in1,
                                           pw0 + (size_t)l * DD * DD,
                                           pw1 + (size_t)l * DD * DD,
                                           O, pmc + l * DD, ot0, ot1);
        bf16* t0s = in0; in0 = ot0; ot0 = t0s;
        bf16* t1s = in1; in1 = ot1; ot1 = t1s;
    }
}

// round 10
// speedup vs baseline: 1.3921x; 1.0064x over previous
#include <cuda_runtime.h>
#include <cuda_bf16.h>
#include <math.h>
#include <stdint.h>

#define NROWS 65536
#define DD    512
#define NSPLIT 29            // 10*29=290 CTAs <= 296 slots -> single wave
#define KCHTOT 2048          // total 32-row k-chunks for Gram
static __device__ __constant__ float kInvTemp = 0.1f;

typedef unsigned long long u64;
typedef __nv_bfloat16 bf16;

// ---------------------------------------------------------------------------
// helpers
// ---------------------------------------------------------------------------
__device__ __forceinline__ uint32_t smem_u32(const void* p) {
    uint32_t a;
    asm("{ .reg .u64 t; cvta.to.shared.u64 t, %1; cvt.u32.u64 %0, t; }"
        : "=r"(a) : "l"(p));
    return a;
}
__device__ __forceinline__ void cp16(uint32_t dst, const void* src) {
    asm volatile("cp.async.cg.shared.global [%0], [%1], 16;"
                 :: "r"(dst), "l"(src) : "memory");
}
__device__ __forceinline__ void mma16816(float* c, const uint32_t* a,
                                         const uint32_t* b) {
    asm volatile(
        "mma.sync.aligned.m16n8k16.row.col.f32.bf16.bf16.f32 "
        "{%0,%1,%2,%3}, {%4,%5,%6,%7}, {%8,%9}, {%0,%1,%2,%3};"
        : "+f"(c[0]), "+f"(c[1]), "+f"(c[2]), "+f"(c[3])
        : "r"(a[0]), "r"(a[1]), "r"(a[2]), "r"(a[3]), "r"(b[0]), "r"(b[1]));
}
__device__ __forceinline__ void ldsm4(uint32_t* r, uint32_t addr) {
    asm volatile("ldmatrix.sync.aligned.m8n8.x4.shared.b16 {%0,%1,%2,%3}, [%4];"
                 : "=r"(r[0]), "=r"(r[1]), "=r"(r[2]), "=r"(r[3]) : "r"(addr));
}
// swizzled smem byte offset within a [128][32] bf16 tile (8KB)
__device__ __forceinline__ int sw(int r, int k) {
    int s = ((k >> 3) ^ (r & 3) ^ ((r >> 2) & 1)) & 3;
    return r * 64 + s * 16 + (k & 7) * 2;
}
__device__ __forceinline__ void split2(float x, bf16 &hi, bf16 &lo) {
    hi = __float2bfloat16_rn(x);
    lo = __float2bfloat16_rn(x - __bfloat162float(hi));
}
__device__ __forceinline__ uint32_t pack2(bf16 a, bf16 b) {
    __nv_bfloat162 v(a, b);
    return *reinterpret_cast<uint32_t*>(&v);
}
__device__ __forceinline__ void ffma2(u64 &d, u64 a, u64 b) {
    asm("fma.rn.f32x2 %0, %1, %2, %0;" : "+l"(d) : "l"(a), "l"(b));
}
__device__ __forceinline__ float2 upk2(u64 v) {
    float2 r;
    asm("mov.b64 {%0, %1}, %2;" : "=f"(r.x), "=f"(r.y) : "l"(v));
    return r;
}
__device__ __forceinline__ u64 dup2(float x) {
    u64 r;
    asm("mov.b64 %0, {%1, %1};" : "=l"(r) : "f"(x));
    return r;
}

// ---------------------------------------------------------------------------
// scratch
// ---------------------------------------------------------------------------
__device__ float g_colpart[256 * DD];
__device__ float g_mean[DD];
__device__ float g_mcv[3 * DD];
__device__ float g_covpart[(size_t)NSPLIT * DD * DD];
__device__ float g_sig[DD * DD];
__device__ float g_cov[DD * DD];
__device__ float g_T1[DD * DD];
__device__ float g_M[DD * DD];
__device__ float g_P0[DD * DD];
__device__ float g_P1[DD * DD];
__device__ float g_A1[DD * DD];
__device__ float g_A2[DD * DD];
__device__ float g_scal[2];
__device__ bf16 g_sA0[(size_t)NROWS * DD];
__device__ bf16 g_sA1[(size_t)NROWS * DD];
__device__ bf16 g_sB0[(size_t)NROWS * DD];
__device__ bf16 g_sB1[(size_t)NROWS * DD];
__device__ bf16 g_t0[(size_t)DD * NROWS];
__device__ bf16 g_t1[(size_t)DD * NROWS];
__device__ bf16 g_w0[3 * DD * DD];
__device__ bf16 g_w1[3 * DD * DD];

__constant__ int cTI[10] = {0,0,0,0,1,1,1,2,2,3};
__constant__ int cTJ[10] = {0,1,2,3,1,2,3,2,3,3};

// ---------------------------------------------------------------------------
// Double-buffered bf16-split mma.sync GEMM, ldmatrix loads, product-outer
// MMA ordering (16 independent accumulators between same-acc reuses).
// MODE 1: out = acc - mc[col] + bf16 splits of result
// MODE 2: Gram split-K partial, balanced k-ranges over NSPLIT CTAs
// MODE 3: out = acc - mc[col], no splits (last layer)
// ---------------------------------------------------------------------------
#define STAGE_BYTES 32768
#define SMEMSZ (2 * STAGE_BYTES)

template <int MODE>
__global__ __launch_bounds__(256, 2)
void mma_gemm(const bf16* __restrict__ a0g, const bf16* __restrict__ a1g,
              const bf16* __restrict__ b0g, const bf16* __restrict__ b1g,
              float* __restrict__ out, const float* __restrict__ mc,
              bf16* __restrict__ so0, bf16* __restrict__ so1) {
    constexpr int LD = (MODE == 2) ? NROWS : DD;
    constexpr bool WS = (MODE == 1);

    extern __shared__ __align__(128) char sm[];
    const uint32_t smb = smem_u32(sm);

    const int tid = threadIdx.x;
    const int lane = tid & 31, wid = tid >> 5;
    const int warpRow = wid & 1;
    const int warpCol = wid >> 1;
    const int g = lane >> 2, t4 = lane & 3;
    const int laneRow = lane & 7, grp = lane >> 3;

    int rowBase, colBase, nch;
    size_t kStart;
    float* outp;
    if (MODE == 2) {
        rowBase = cTI[blockIdx.x] * 128;
        colBase = cTJ[blockIdx.x] * 128;
        int c0 = (int)((size_t)blockIdx.z * KCHTOT / NSPLIT);
        int c1 = (int)((size_t)(blockIdx.z + 1) * KCHTOT / NSPLIT);
        kStart = (size_t)c0 * 32;
        nch = c1 - c0;
        outp = out + (size_t)blockIdx.z * DD * DD;
    } else {
        rowBase = blockIdx.y * 128;
        colBase = blockIdx.x * 128;
        kStart = 0;
        nch = DD / 32;
        outp = out;
    }

    float acc[4][4][4];
#pragma unroll
    for (int mi = 0; mi < 4; mi++)
#pragma unroll
        for (int ni = 0; ni < 4; ni++)
#pragma unroll
            for (int q = 0; q < 4; q++) acc[mi][ni][q] = 0.f;

    uint32_t aOff[4], bOff[2];
#pragma unroll
    for (int mi = 0; mi < 4; mi++)
        aOff[mi] = sw(warpRow * 64 + mi * 16 + (grp & 1) * 8 + laneRow, (grp >> 1) * 8);
#pragma unroll
    for (int p = 0; p < 2; p++)
        bOff[p] = sw(warpCol * 32 + p * 16 + (grp >> 1) * 8 + laneRow, (grp & 1) * 8);

    const int lr = tid >> 2;
    const int lseg = tid & 3;

    auto load_chunk = [&](int ch, int stage) {
        const size_t kpos = kStart + (size_t)ch * 32;
        const uint32_t sb = smb + stage * STAGE_BYTES;
#pragma unroll
        for (int i = 0; i < 2; i++) {
            const int r = lr + i * 64;
            const int soff = sw(r, lseg * 8);
            const size_t ga = (size_t)(rowBase + r) * LD + kpos + lseg * 8;
            const size_t gb = (size_t)(colBase + r) * LD + kpos + lseg * 8;
            cp16(sb + soff,         a0g + ga);
            cp16(sb + 8192 + soff,  a1g + ga);
            cp16(sb + 16384 + soff, b0g + gb);
            cp16(sb + 24576 + soff, b1g + gb);
        }
        asm volatile("cp.async.commit_group;" ::: "memory");
    };

    load_chunk(0, 0);

    for (int ch = 0; ch < nch; ch++) {
        if (ch + 1 < nch) {
            load_chunk(ch + 1, (ch + 1) & 1);
            asm volatile("cp.async.wait_group 1;" ::: "memory");
        } else {
            asm volatile("cp.async.wait_group 0;" ::: "memory");
        }
        __syncthreads();

        const uint32_t sA0 = smb + (ch & 1) * STAGE_BYTES;
        const uint32_t sA1 = sA0 + 8192;
        const uint32_t sB0 = sA0 + 16384;
        const uint32_t sB1 = sA0 + 24576;

#pragma unroll
        for (int ks = 0; ks < 2; ks++) {
            const uint32_t kx = ks * 32;
            uint32_t fa0[4][4], fa1[4][4], fb0[2][4], fb1[2][4];
#pragma unroll
            for (int mi = 0; mi < 4; mi++) {
                ldsm4(fa0[mi], sA0 + (aOff[mi] ^ kx));
                ldsm4(fa1[mi], sA1 + (aOff[mi] ^ kx));
            }
#pragma unroll
            for (int p = 0; p < 2; p++) {
                ldsm4(fb0[p], sB0 + (bOff[p] ^ kx));
                ldsm4(fb1[p], sB1 + (bOff[p] ^ kx));
            }
            // product-outer ordering: 16 independent accumulators between
            // successive MMAs on the same acc -> no RAW stalls on tensor pipe
#pragma unroll
            for (int t = 0; t < 3; t++) {
#pragma unroll
                for (int ni = 0; ni < 4; ni++) {
                    const uint32_t* bb =
                        (t == 1) ? &fb1[ni >> 1][(ni & 1) * 2]
                                 : &fb0[ni >> 1][(ni & 1) * 2];
#pragma unroll
                    for (int mi = 0; mi < 4; mi++) {
                        const uint32_t* aa = (t == 2) ? fa1[mi] : fa0[mi];
                        mma16816(acc[mi][ni], aa, bb);
                    }
                }
            }
        }
        __syncthreads();
    }

    // epilogue
#pragma unroll
    for (int mi = 0; mi < 4; mi++) {
        const int row0 = rowBase + warpRow * 64 + mi * 16 + g;
#pragma unroll
        for (int ni = 0; ni < 4; ni++) {
            const int col = colBase + warpCol * 32 + ni * 8 + t4 * 2;
            float v0 = acc[mi][ni][0], v1 = acc[mi][ni][1];
            float v2 = acc[mi][ni][2], v3 = acc[mi][ni][3];
            if (MODE != 2) {
                const float m0 = mc[col], m1 = mc[col + 1];
                v0 -= m0; v1 -= m1; v2 -= m0; v3 -= m1;
            }
            *(float2*)(outp + (size_t)row0 * DD + col)       = make_float2(v0, v1);
            *(float2*)(outp + (size_t)(row0 + 8) * DD + col) = make_float2(v2, v3);
            if (WS) {
                bf16 h0, l0, h1, l1, h2, l2, h3, l3;
                split2(v0, h0, l0); split2(v1, h1, l1);
                split2(v2, h2, l2); split2(v3, h3, l3);
                *(uint32_t*)(so0 + (size_t)row0 * DD + col)       = pack2(h0, h1);
                *(uint32_t*)(so1 + (size_t)row0 * DD + col)       = pack2(l0, l1);
                *(uint32_t*)(so0 + (size_t)(row0 + 8) * DD + col) = pack2(h2, h3);
                *(uint32_t*)(so1 + (size_t)(row0 + 8) * DD + col) = pack2(l2, l3);
            }
        }
    }
}

// ---------------------------------------------------------------------------
// split / transpose kernels
// ---------------------------------------------------------------------------
__global__ void split_rows2_kernel(const float* __restrict__ in,
                                   bf16* __restrict__ s0, bf16* __restrict__ s1,
                                   int n4) {
    int idx = blockIdx.x * 256 + threadIdx.x;
    if (idx >= n4) return;
    float4 v = ((const float4*)in)[idx];
    bf16 h0, l0, h1, l1, h2, l2, h3, l3;
    split2(v.x, h0, l0); split2(v.y, h1, l1);
    split2(v.z, h2, l2); split2(v.w, h3, l3);
    ((uint2*)s0)[idx] = make_uint2(pack2(h0, h1), pack2(h2, h3));
    ((uint2*)s1)[idx] = make_uint2(pack2(l0, l1), pack2(l2, l3));
}

// fp32 [n][512] -> transposed bf16 split planes [512][ldout]
__global__ void split_trans2_kernel(const float* __restrict__ src,
                                    bf16* __restrict__ t0, bf16* __restrict__ t1,
                                    int ldout) {
    __shared__ float ts[32][33];
    const int tid = threadIdx.x;
    const int n0 = blockIdx.x * 32;
    const int d0 = blockIdx.y * 32;
    int r = tid >> 3, c = (tid & 7) * 4;
    float4 v = *(const float4*)(src + (size_t)(n0 + r) * DD + d0 + c);
    ts[r][c] = v.x; ts[r][c + 1] = v.y; ts[r][c + 2] = v.z; ts[r][c + 3] = v.w;
    __syncthreads();
    int cc = tid >> 3, rr = (tid & 7) * 4;
    bf16 h[4], l[4];
#pragma unroll
    for (int i = 0; i < 4; i++) split2(ts[rr + i][cc], h[i], l[i]);
    size_t off = (size_t)(d0 + cc) * ldout + n0 + rr;
    *(uint2*)(t0 + off) = make_uint2(pack2(h[0], h[1]), pack2(h[2], h[3]));
    *(uint2*)(t1 + off) = make_uint2(pack2(l[0], l[1]), pack2(l[2], l[3]));
}

// ---------------------------------------------------------------------------
// fp32 small GEMM (64x64 tile, grid 8x8)
// ---------------------------------------------------------------------------
template <int TA>
__device__ __forceinline__ void load_tiles(float (&As)[16][68], float (&Bs)[16][64],
                                           const float* A, const float* B,
                                           int r0, int c0, int k0, int tid) {
    if (TA == 0) {
        int r = tid >> 2, c = (tid & 3) << 2;
        float4 v = *(const float4*)(A + (size_t)(r0 + r) * DD + k0 + c);
        As[c + 0][r] = v.x; As[c + 1][r] = v.y;
        As[c + 2][r] = v.z; As[c + 3][r] = v.w;
    } else {
        int r = tid >> 4, c = (tid & 15) << 2;
        float4 v = *(const float4*)(A + (size_t)(k0 + r) * DD + r0 + c);
        *(float4*)&As[r][c] = v;
    }
    {
        int r = tid >> 4, c = (tid & 15) << 2;
        *(float4*)&Bs[r][c] = *(const float4*)(B + (size_t)(k0 + r) * DD + c0 + c);
    }
}

// EPI: 0 = C = acc*sc ; 1 = C = acc + I/temp ; 2 = C = 1.5*Pin - 0.5*acc ;
//      3 = C = acc - (kInvTemp*g_scal[0])*Pin
template <int TA, int EPI>
__device__ __forceinline__ void small_body(float* __restrict__ C,
                                           const float* __restrict__ A,
                                           const float* __restrict__ B,
                                           const float* __restrict__ Pin,
                                           float sc) {
    __shared__ __align__(16) float As[16][68];
    __shared__ __align__(16) float Bs[16][64];
    const int tid = threadIdx.x;
    const int tx = tid & 15;
    const int ty = tid >> 4;
    const int r0 = blockIdx.y * 64;
    const int c0 = blockIdx.x * 64;

    u64 acc[4][2];
#pragma unroll
    for (int r = 0; r < 4; r++)
#pragma unroll
        for (int j = 0; j < 2; j++) acc[r][j] = 0ull;

    for (int k0 = 0; k0 < DD; k0 += 16) {
        load_tiles<TA>(As, Bs, A, B, r0, c0, k0, tid);
        __syncthreads();
#pragma unroll
        for (int kk = 0; kk < 16; kk++) {
            float4 a0 = *(const float4*)&As[kk][ty * 4];
            u64 a2[4];
            a2[0] = dup2(a0.x); a2[1] = dup2(a0.y);
            a2[2] = dup2(a0.z); a2[3] = dup2(a0.w);
            u64 b2[2];
#pragma unroll
            for (int j = 0; j < 2; j++)
                b2[j] = *(const u64*)&Bs[kk][(j * 16 + tx) * 2];
#pragma unroll
            for (int r = 0; r < 4; r++)
#pragma unroll
                for (int j = 0; j < 2; j++) ffma2(acc[r][j], a2[r], b2[j]);
        }
        __syncthreads();
    }
#pragma unroll
    for (int r = 0; r < 4; r++) {
#pragma unroll
        for (int j = 0; j < 2; j++) {
            float2 f = upk2(acc[r][j]);
            const size_t row = r0 + ty * 4 + r;
            const int col = c0 + (j * 16 + tx) * 2;
            if (EPI == 0) {
                f.x *= sc; f.y *= sc;
            } else if (EPI == 1) {
                if ((int)row == col)     f.x += kInvTemp;
                if ((int)row == col + 1) f.y += kInvTemp;
            } else if (EPI == 2) {
                f.x = 1.5f * Pin[row * DD + col]     - 0.5f * f.x;
                f.y = 1.5f * Pin[row * DD + col + 1] - 0.5f * f.y;
            } else if (EPI == 3) {
                const float cc2 = kInvTemp * g_scal[0];
                f.x -= cc2 * Pin[row * DD + col];
                f.y -= cc2 * Pin[row * DD + col + 1];
            }
            *(float2*)(C + row * DD + col) = f;
        }
    }
}

template <int TA, int EPI>
__global__ __launch_bounds__(256)
void gemm512(float* __restrict__ C, const float* __restrict__ A,
             const float* __restrict__ B, const float* __restrict__ Pin,
             int scalesel) {
    float sc = (scalesel == 1) ? g_scal[0] : (scalesel == 2) ? g_scal[1] : 1.0f;
    small_body<TA, EPI>(C, A, B, Pin, sc);
}

__global__ __launch_bounds__(256)
void gemm_pair(const float* __restrict__ P) {
    if (blockIdx.z == 0) small_body<0, 0>(g_A1, P, P, nullptr, 1.0f);
    else                 small_body<0, 0>(g_A2, P, g_cov, nullptr, g_scal[0]);
}
__global__ __launch_bounds__(256)
void gemm_upd(float* __restrict__ Pn, const float* __restrict__ P) {
    small_body<0, 2>(Pn, g_A1, g_A2, P, 1.0f);
}

// ---------------------------------------------------------------------------
// reductions / vectors
// ---------------------------------------------------------------------------
__global__ void colsum_kernel(const float* __restrict__ H) {
    const int b = blockIdx.x;
    const int t = threadIdx.x;
    const float* p = H + (size_t)b * 256 * DD + t;
    float s = 0.f;
#pragma unroll 8
    for (int r = 0; r < 256; r++) s += p[(size_t)r * DD];
    g_colpart[b * DD + t] = s;
}

__global__ void mean_final_kernel() {
    const int t = threadIdx.x;
    float s = 0.f;
#pragma unroll 8
    for (int b = 0; b < 256; b++) s += g_colpart[b * DD + t];
    g_mean[t] = s * (1.0f / (float)NROWS);
}

__global__ void reduce_sig_kernel() {
    const int idx = blockIdx.x * 1024 + threadIdx.x;
    const int i = idx >> 9, j = idx & (DD - 1);
    const int src = ((i >> 7) <= (j >> 7)) ? (i * DD + j) : (j * DD + i);
    float s = 0.f;
#pragma unroll
    for (int z = 0; z < NSPLIT; z++)
        s += g_covpart[(size_t)z * DD * DD + src];
    g_sig[idx] = s * (1.0f / (float)NROWS) - g_mean[i] * g_mean[j];
}

__global__ void trace_kernel() {
    __shared__ float sm[512];
    const int t = threadIdx.x;
    sm[t] = g_cov[(size_t)t * DD + t];
    __syncthreads();
    for (int s = 256; s > 0; s >>= 1) {
        if (t < s) sm[t] += sm[t + s];
        __syncthreads();
    }
    if (t == 0) {
        float tr = sm[0];
        g_scal[0] = 1.0f / tr;
        g_scal[1] = 1.0f / sqrtf(tr);
    }
}

__global__ void init_P_kernel(float* __restrict__ P) {
    const int idx = blockIdx.x * 1024 + threadIdx.x;
    const int i = idx >> 9, j = idx & (DD - 1);
    P[idx] = ((i == j) ? 1.5f : 0.0f) - 0.5f * g_cov[idx] * g_scal[0];
}

__global__ void mc_kernel(const float* __restrict__ M, float* __restrict__ mc) {
    __shared__ float sm[256];
    const int n = blockIdx.x, t = threadIdx.x;
    float s = g_mean[t] * M[(size_t)t * DD + n]
            + g_mean[t + 256] * M[(size_t)(t + 256) * DD + n];
    sm[t] = s;
    __syncthreads();
    for (int k = 128; k > 0; k >>= 1) {
        if (t < k) sm[t] += sm[t + k];
        __syncthreads();
    }
    if (t == 0) mc[n] = sm[0];
}

__global__ void zero_mc12_kernel() { g_mcv[DD + threadIdx.x] = 0.f; }

// ---------------------------------------------------------------------------
// orchestration — two-stream fork/join (capture-legal fork via evRoot);
// Gram = our 4th launch so ncu -s 5 profiles it.
// ---------------------------------------------------------------------------
extern "C" void kernel_launch(void* const* d_in, const int* in_sizes, int n_in,
                              void* d_out, int out_size) {
    (void)in_sizes; (void)n_in; (void)out_size;
    const float* x = (const float*)d_in[0];
    const float* W[3] = {(const float*)d_in[1], (const float*)d_in[2],
                         (const float*)d_in[3]};
    float* out = (float*)d_out;

    float *pcovpart, *psig, *pcov, *pT1, *pM, *pP0, *pP1, *pA1, *pA2, *pmc;
    bf16 *psA0, *psA1, *psB0, *psB1, *pt0, *pt1, *pw0, *pw1;
    cudaGetSymbolAddress((void**)&pcovpart, g_covpart);
    cudaGetSymbolAddress((void**)&psig, g_sig);
    cudaGetSymbolAddress((void**)&pcov, g_cov);
    cudaGetSymbolAddress((void**)&pT1, g_T1);
    cudaGetSymbolAddress((void**)&pM, g_M);
    cudaGetSymbolAddress((void**)&pP0, g_P0);
    cudaGetSymbolAddress((void**)&pP1, g_P1);
    cudaGetSymbolAddress((void**)&pA1, g_A1);
    cudaGetSymbolAddress((void**)&pA2, g_A2);
    cudaGetSymbolAddress((void**)&pmc, g_mcv);
    cudaGetSymbolAddress((void**)&psA0, g_sA0);
    cudaGetSymbolAddress((void**)&psA1, g_sA1);
    cudaGetSymbolAddress((void**)&psB0, g_sB0);
    cudaGetSymbolAddress((void**)&psB1, g_sB1);
    cudaGetSymbolAddress((void**)&pt0, g_t0);
    cudaGetSymbolAddress((void**)&pt1, g_t1);
    cudaGetSymbolAddress((void**)&pw0, g_w0);
    cudaGetSymbolAddress((void**)&pw1, g_w1);

    cudaFuncSetAttribute(mma_gemm<1>, cudaFuncAttributeMaxDynamicSharedMemorySize, SMEMSZ);
    cudaFuncSetAttribute(mma_gemm<2>, cudaFuncAttributeMaxDynamicSharedMemorySize, SMEMSZ);
    cudaFuncSetAttribute(mma_gemm<3>, cudaFuncAttributeMaxDynamicSharedMemorySize, SMEMSZ);

    cudaStream_t s2;
    cudaStreamCreateWithFlags(&s2, cudaStreamNonBlocking);
    cudaEvent_t evRoot, evMean, evSig, evM[3];
    cudaEventCreateWithFlags(&evRoot, cudaEventDisableTiming);
    cudaEventCreateWithFlags(&evMean, cudaEventDisableTiming);
    cudaEventCreateWithFlags(&evSig, cudaEventDisableTiming);
    for (int i = 0; i < 3; i++) cudaEventCreateWithFlags(&evM[i], cudaEventDisableTiming);

    const int N4BIG = NROWS * DD / 4;
    const dim3 gact(4, NROWS / 128);
    const dim3 gcov(10, 1, NSPLIT);
    const dim3 gsm(8, 8);

    // #1 on origin stream, then fork s2 via evRoot (capture-legal)
    split_trans2_kernel<<<dim3(NROWS / 32, 16), 256>>>(x, pt0, pt1, NROWS);     // #1
    cudaEventRecord(evRoot, 0);
    cudaStreamWaitEvent(s2, evRoot, 0);

    split_rows2_kernel<<<N4BIG / 256, 256, 0, s2>>>(x, psA0, psA1, N4BIG);      // #2
    colsum_kernel<<<256, 512, 0, s2>>>(x);                                      // #3
    mma_gemm<2><<<gcov, 256, SMEMSZ>>>(pt0, pt1, pt0, pt1, pcovpart,
                                       nullptr, nullptr, nullptr);              // #4 (ncu)
    mean_final_kernel<<<1, 512, 0, s2>>>();                                     // #5
    zero_mc12_kernel<<<1, 1024, 0, s2>>>();                                     // #6
    cudaEventRecord(evMean, s2);

    cudaStreamWaitEvent(0, evMean, 0);
    reduce_sig_kernel<<<256, 1024>>>();                                         // #7
    cudaEventRecord(evSig, 0);

    // ---- stream s2: whole small-matrix chain for all 3 layers ----
    cudaStreamWaitEvent(s2, evSig, 0);
    for (int l = 0; l < 3; l++) {
        gemm512<0, 0><<<gsm, 256, 0, s2>>>(pT1, psig, W[l], nullptr, 0);
        gemm512<1, 1><<<gsm, 256, 0, s2>>>(pcov, W[l], pT1, nullptr, 0);
        trace_kernel<<<1, 512, 0, s2>>>();
        init_P_kernel<<<256, 1024, 0, s2>>>(pP0);

        float* P = pP0;
        float* Pn = pP1;
        for (int it = 1; it < 10; it++) {
            gemm_pair<<<dim3(8, 8, 2), 256, 0, s2>>>(P);
            gemm_upd<<<gsm, 256, 0, s2>>>(Pn, P);
            float* t = P; P = Pn; Pn = t;
        }

        gemm_pair<<<dim3(8, 8, 2), 256, 0, s2>>>(P);
        gemm512<0, 0><<<gsm, 256, 0, s2>>>(pM, W[l], P, nullptr, 2);
        gemm512<0, 3><<<gsm, 256, 0, s2>>>(psig, pA2, P, pA1, 0);
        split_trans2_kernel<<<dim3(16, 16), 256, 0, s2>>>(pM, pw0 + (size_t)l * DD * DD,
                                                          pw1 + (size_t)l * DD * DD, DD);
        if (l == 0) mc_kernel<<<512, 256, 0, s2>>>(pM, pmc);
        cudaEventRecord(evM[l], s2);
    }

    // ---- stream 0: three big out-GEMMs, each gated on its M ----
    bf16* in0 = psA0; bf16* in1 = psA1;
    bf16* ot0 = psB0; bf16* ot1 = psB1;
    for (int l = 0; l < 3; l++) {
        float* O = out + (size_t)l * NROWS * DD;
        cudaStreamWaitEvent(0, evM[l], 0);
        if (l < 2)
            mma_gemm<1><<<gact, 256, SMEMSZ>>>(in0, in1,
                                               pw0 + (size_t)l * DD * DD,
                                               pw1 + (size_t)l * DD * DD,
                                               O, pmc + l * DD, ot0, ot1);
        else
            mma_gemm<3><<<gact, 256, SMEMSZ>>>(in0, in1,
                                               pw0 + (size_t)l * DD * DD,
                                               pw1 + (size_t)l * DD * DD,
                                               O, pmc + l * DD, nullptr, nullptr);
        bf16* t0s = in0; in0 = ot0; ot0 = t0s;
        bf16* t1s = in1; in1 = ot1; ot1 = t1s;
    }
}

// round 11
// speedup vs baseline: 1.4083x; 1.0116x over previous
#include <cuda_runtime.h>
#include <cuda_bf16.h>
#include <math.h>
#include <stdint.h>

#define NROWS 65536
#define DD    512
#define NSPLIT 29            // 10*29=290 CTAs -> single wave for Gram
#define KCHTOT 2048
#define PCTAS 128            // persistent-chain grid (<=148 -> co-resident)
static __device__ __constant__ float kInvTemp = 0.1f;

typedef unsigned long long u64;
typedef __nv_bfloat16 bf16;

// ---------------------------------------------------------------------------
// helpers
// ---------------------------------------------------------------------------
__device__ __forceinline__ uint32_t smem_u32(const void* p) {
    uint32_t a;
    asm("{ .reg .u64 t; cvta.to.shared.u64 t, %1; cvt.u32.u64 %0, t; }"
        : "=r"(a) : "l"(p));
    return a;
}
__device__ __forceinline__ void cp16(uint32_t dst, const void* src) {
    asm volatile("cp.async.cg.shared.global [%0], [%1], 16;"
                 :: "r"(dst), "l"(src) : "memory");
}
__device__ __forceinline__ void mma16816(float* c, const uint32_t* a,
                                         const uint32_t* b) {
    asm volatile(
        "mma.sync.aligned.m16n8k16.row.col.f32.bf16.bf16.f32 "
        "{%0,%1,%2,%3}, {%4,%5,%6,%7}, {%8,%9}, {%0,%1,%2,%3};"
        : "+f"(c[0]), "+f"(c[1]), "+f"(c[2]), "+f"(c[3])
        : "r"(a[0]), "r"(a[1]), "r"(a[2]), "r"(a[3]), "r"(b[0]), "r"(b[1]));
}
__device__ __forceinline__ void ldsm4(uint32_t* r, uint32_t addr) {
    asm volatile("ldmatrix.sync.aligned.m8n8.x4.shared.b16 {%0,%1,%2,%3}, [%4];"
                 : "=r"(r[0]), "=r"(r[1]), "=r"(r[2]), "=r"(r[3]) : "r"(addr));
}
__device__ __forceinline__ int sw(int r, int k) {
    int s = ((k >> 3) ^ (r & 3) ^ ((r >> 2) & 1)) & 3;
    return r * 64 + s * 16 + (k & 7) * 2;
}
__device__ __forceinline__ void split2(float x, bf16 &hi, bf16 &lo) {
    hi = __float2bfloat16_rn(x);
    lo = __float2bfloat16_rn(x - __bfloat162float(hi));
}
__device__ __forceinline__ uint32_t pack2(bf16 a, bf16 b) {
    __nv_bfloat162 v(a, b);
    return *reinterpret_cast<uint32_t*>(&v);
}
__device__ __forceinline__ void ffma2(u64 &d, u64 a, u64 b) {
    asm("fma.rn.f32x2 %0, %1, %2, %0;" : "+l"(d) : "l"(a), "l"(b));
}
__device__ __forceinline__ float2 upk2(u64 v) {
    float2 r;
    asm("mov.b64 {%0, %1}, %2;" : "=f"(r.x), "=f"(r.y) : "l"(v));
    return r;
}
__device__ __forceinline__ u64 dup2(float x) {
    u64 r;
    asm("mov.b64 %0, {%1, %1};" : "=l"(r) : "f"(x));
    return r;
}

// ---------------------------------------------------------------------------
// scratch
// ---------------------------------------------------------------------------
__device__ float g_colpart[256 * DD];
__device__ float g_mean[DD];
__device__ float g_mcv[3 * DD];
__device__ float g_covpart[(size_t)NSPLIT * DD * DD];
__device__ float g_sig[DD * DD];
__device__ float g_cov[DD * DD];
__device__ float g_T1[DD * DD];
__device__ float g_M[DD * DD];
__device__ float g_P0[DD * DD];
__device__ float g_P1[DD * DD];
__device__ float g_A1[DD * DD];
__device__ float g_A2[DD * DD];
__device__ float g_scal[2];
__device__ unsigned g_barCount;
__device__ unsigned g_barGen;
__device__ bf16 g_sA0[(size_t)NROWS * DD];
__device__ bf16 g_sA1[(size_t)NROWS * DD];
__device__ bf16 g_sB0[(size_t)NROWS * DD];
__device__ bf16 g_sB1[(size_t)NROWS * DD];
__device__ bf16 g_t0[(size_t)DD * NROWS];
__device__ bf16 g_t1[(size_t)DD * NROWS];
__device__ bf16 g_w0[3 * DD * DD];
__device__ bf16 g_w1[3 * DD * DD];

__constant__ int cTI[10] = {0,0,0,0,1,1,1,2,2,3};
__constant__ int cTJ[10] = {0,1,2,3,1,2,3,2,3,3};

// ---------------------------------------------------------------------------
// Big bf16-split mma.sync GEMM (unchanged from round 10)
// MODE 1: out = acc - mc[col] + bf16 splits ; MODE 2: Gram partial ;
// MODE 3: out = acc - mc[col], no splits
// ---------------------------------------------------------------------------
#define STAGE_BYTES 32768
#define SMEMSZ (2 * STAGE_BYTES)

template <int MODE>
__global__ __launch_bounds__(256, 2)
void mma_gemm(const bf16* __restrict__ a0g, const bf16* __restrict__ a1g,
              const bf16* __restrict__ b0g, const bf16* __restrict__ b1g,
              float* __restrict__ out, const float* __restrict__ mc,
              bf16* __restrict__ so0, bf16* __restrict__ so1) {
    constexpr int LD = (MODE == 2) ? NROWS : DD;
    constexpr bool WS = (MODE == 1);

    extern __shared__ __align__(128) char sm[];
    const uint32_t smb = smem_u32(sm);

    const int tid = threadIdx.x;
    const int lane = tid & 31, wid = tid >> 5;
    const int warpRow = wid & 1;
    const int warpCol = wid >> 1;
    const int g = lane >> 2, t4 = lane & 3;
    const int laneRow = lane & 7, grp = lane >> 3;

    int rowBase, colBase, nch;
    size_t kStart;
    float* outp;
    if (MODE == 2) {
        rowBase = cTI[blockIdx.x] * 128;
        colBase = cTJ[blockIdx.x] * 128;
        int c0 = (int)((size_t)blockIdx.z * KCHTOT / NSPLIT);
        int c1 = (int)((size_t)(blockIdx.z + 1) * KCHTOT / NSPLIT);
        kStart = (size_t)c0 * 32;
        nch = c1 - c0;
        outp = out + (size_t)blockIdx.z * DD * DD;
    } else {
        rowBase = blockIdx.y * 128;
        colBase = blockIdx.x * 128;
        kStart = 0;
        nch = DD / 32;
        outp = out;
    }

    float acc[4][4][4];
#pragma unroll
    for (int mi = 0; mi < 4; mi++)
#pragma unroll
        for (int ni = 0; ni < 4; ni++)
#pragma unroll
            for (int q = 0; q < 4; q++) acc[mi][ni][q] = 0.f;

    uint32_t aOff[4], bOff[2];
#pragma unroll
    for (int mi = 0; mi < 4; mi++)
        aOff[mi] = sw(warpRow * 64 + mi * 16 + (grp & 1) * 8 + laneRow, (grp >> 1) * 8);
#pragma unroll
    for (int p = 0; p < 2; p++)
        bOff[p] = sw(warpCol * 32 + p * 16 + (grp >> 1) * 8 + laneRow, (grp & 1) * 8);

    const int lr = tid >> 2;
    const int lseg = tid & 3;

    auto load_chunk = [&](int ch, int stage) {
        const size_t kpos = kStart + (size_t)ch * 32;
        const uint32_t sb = smb + stage * STAGE_BYTES;
#pragma unroll
        for (int i = 0; i < 2; i++) {
            const int r = lr + i * 64;
            const int soff = sw(r, lseg * 8);
            const size_t ga = (size_t)(rowBase + r) * LD + kpos + lseg * 8;
            const size_t gb = (size_t)(colBase + r) * LD + kpos + lseg * 8;
            cp16(sb + soff,         a0g + ga);
            cp16(sb + 8192 + soff,  a1g + ga);
            cp16(sb + 16384 + soff, b0g + gb);
            cp16(sb + 24576 + soff, b1g + gb);
        }
        asm volatile("cp.async.commit_group;" ::: "memory");
    };

    load_chunk(0, 0);

    for (int ch = 0; ch < nch; ch++) {
        if (ch + 1 < nch) {
            load_chunk(ch + 1, (ch + 1) & 1);
            asm volatile("cp.async.wait_group 1;" ::: "memory");
        } else {
            asm volatile("cp.async.wait_group 0;" ::: "memory");
        }
        __syncthreads();

        const uint32_t sA0 = smb + (ch & 1) * STAGE_BYTES;
        const uint32_t sA1 = sA0 + 8192;
        const uint32_t sB0 = sA0 + 16384;
        const uint32_t sB1 = sA0 + 24576;

#pragma unroll
        for (int ks = 0; ks < 2; ks++) {
            const uint32_t kx = ks * 32;
            uint32_t fa0[4][4], fa1[4][4], fb0[2][4], fb1[2][4];
#pragma unroll
            for (int mi = 0; mi < 4; mi++) {
                ldsm4(fa0[mi], sA0 + (aOff[mi] ^ kx));
                ldsm4(fa1[mi], sA1 + (aOff[mi] ^ kx));
            }
#pragma unroll
            for (int p = 0; p < 2; p++) {
                ldsm4(fb0[p], sB0 + (bOff[p] ^ kx));
                ldsm4(fb1[p], sB1 + (bOff[p] ^ kx));
            }
#pragma unroll
            for (int t = 0; t < 3; t++) {
#pragma unroll
                for (int ni = 0; ni < 4; ni++) {
                    const uint32_t* bb =
                        (t == 1) ? &fb1[ni >> 1][(ni & 1) * 2]
                                 : &fb0[ni >> 1][(ni & 1) * 2];
#pragma unroll
                    for (int mi = 0; mi < 4; mi++) {
                        const uint32_t* aa = (t == 2) ? fa1[mi] : fa0[mi];
                        mma16816(acc[mi][ni], aa, bb);
                    }
                }
            }
        }
        __syncthreads();
    }

#pragma unroll
    for (int mi = 0; mi < 4; mi++) {
        const int row0 = rowBase + warpRow * 64 + mi * 16 + g;
#pragma unroll
        for (int ni = 0; ni < 4; ni++) {
            const int col = colBase + warpCol * 32 + ni * 8 + t4 * 2;
            float v0 = acc[mi][ni][0], v1 = acc[mi][ni][1];
            float v2 = acc[mi][ni][2], v3 = acc[mi][ni][3];
            if (MODE != 2) {
                const float m0 = mc[col], m1 = mc[col + 1];
                v0 -= m0; v1 -= m1; v2 -= m0; v3 -= m1;
            }
            *(float2*)(outp + (size_t)row0 * DD + col)       = make_float2(v0, v1);
            *(float2*)(outp + (size_t)(row0 + 8) * DD + col) = make_float2(v2, v3);
            if (WS) {
                bf16 h0, l0, h1, l1, h2, l2, h3, l3;
                split2(v0, h0, l0); split2(v1, h1, l1);
                split2(v2, h2, l2); split2(v3, h3, l3);
                *(uint32_t*)(so0 + (size_t)row0 * DD + col)       = pack2(h0, h1);
                *(uint32_t*)(so1 + (size_t)row0 * DD + col)       = pack2(l0, l1);
                *(uint32_t*)(so0 + (size_t)(row0 + 8) * DD + col) = pack2(h2, h3);
                *(uint32_t*)(so1 + (size_t)(row0 + 8) * DD + col) = pack2(l2, l3);
            }
        }
    }
}

// ---------------------------------------------------------------------------
// split / transpose / reduction kernels
// ---------------------------------------------------------------------------
__global__ void split_rows2_kernel(const float* __restrict__ in,
                                   bf16* __restrict__ s0, bf16* __restrict__ s1,
                                   int n4) {
    int idx = blockIdx.x * 256 + threadIdx.x;
    if (idx >= n4) return;
    float4 v = ((const float4*)in)[idx];
    bf16 h0, l0, h1, l1, h2, l2, h3, l3;
    split2(v.x, h0, l0); split2(v.y, h1, l1);
    split2(v.z, h2, l2); split2(v.w, h3, l3);
    ((uint2*)s0)[idx] = make_uint2(pack2(h0, h1), pack2(h2, h3));
    ((uint2*)s1)[idx] = make_uint2(pack2(l0, l1), pack2(l2, l3));
}

__global__ void split_trans2_kernel(const float* __restrict__ src,
                                    bf16* __restrict__ t0, bf16* __restrict__ t1,
                                    int ldout) {
    __shared__ float ts[32][33];
    const int tid = threadIdx.x;
    const int n0 = blockIdx.x * 32;
    const int d0 = blockIdx.y * 32;
    int r = tid >> 3, c = (tid & 7) * 4;
    float4 v = *(const float4*)(src + (size_t)(n0 + r) * DD + d0 + c);
    ts[r][c] = v.x; ts[r][c + 1] = v.y; ts[r][c + 2] = v.z; ts[r][c + 3] = v.w;
    __syncthreads();
    int cc = tid >> 3, rr = (tid & 7) * 4;
    bf16 h[4], l[4];
#pragma unroll
    for (int i = 0; i < 4; i++) split2(ts[rr + i][cc], h[i], l[i]);
    size_t off = (size_t)(d0 + cc) * ldout + n0 + rr;
    *(uint2*)(t0 + off) = make_uint2(pack2(h[0], h[1]), pack2(h[2], h[3]));
    *(uint2*)(t1 + off) = make_uint2(pack2(l[0], l[1]), pack2(l[2], l[3]));
}

__global__ void colsum_kernel(const float* __restrict__ H) {
    const int b = blockIdx.x;
    const int t = threadIdx.x;
    const float* p = H + (size_t)b * 256 * DD + t;
    float s = 0.f;
#pragma unroll 8
    for (int r = 0; r < 256; r++) s += p[(size_t)r * DD];
    g_colpart[b * DD + t] = s;
}

__global__ void mean_final_kernel() {
    const int t = threadIdx.x;
    float s = 0.f;
#pragma unroll 8
    for (int b = 0; b < 256; b++) s += g_colpart[b * DD + t];
    g_mean[t] = s * (1.0f / (float)NROWS);
}

__global__ void reduce_sig_kernel() {
    const int idx = blockIdx.x * 1024 + threadIdx.x;
    const int i = idx >> 9, j = idx & (DD - 1);
    const int src = ((i >> 7) <= (j >> 7)) ? (i * DD + j) : (j * DD + i);
    float s = 0.f;
#pragma unroll
    for (int z = 0; z < NSPLIT; z++)
        s += g_covpart[(size_t)z * DD * DD + src];
    g_sig[idx] = s * (1.0f / (float)NROWS) - g_mean[i] * g_mean[j];
}

__global__ void zero_mc12_kernel() { g_mcv[DD + threadIdx.x] = 0.f; }

// ---------------------------------------------------------------------------
// Persistent small-matrix chain: one launch per layer.
// Grid = 128 CTAs (co-resident), generation-counter grid barrier.
// ---------------------------------------------------------------------------
__device__ __forceinline__ void gridbar() {
    __syncthreads();
    if (threadIdx.x == 0) {
        unsigned g = atomicAdd(&g_barGen, 0u);
        __threadfence();
        if (atomicAdd(&g_barCount, 1u) == PCTAS - 1) {
            g_barCount = 0;
            __threadfence();
            atomicAdd(&g_barGen, 1u);
        } else {
            while (atomicAdd(&g_barGen, 0u) == g) __nanosleep(64);
        }
    }
    __syncthreads();
    __threadfence();   // gpu-scope fence -> CCTL.IVALL: invalidate L1 for new stage
}

// EPI: 0 = C=acc*sc ; 1 = C=acc+I/temp ; 2 = C=1.5*Pin-0.5*acc ; 3 = C=acc-(kInvTemp*sc)*Pin
__device__ void tile_gemm(float* __restrict__ C, const float* __restrict__ A,
                          const float* __restrict__ B, const float* __restrict__ Pin,
                          float sc, int epi, int ta, int tile,
                          float (*As)[68], float (*Bs)[64]) {
    const int tid = threadIdx.x;
    const int tx = tid & 15;
    const int ty = tid >> 4;
    const int r0 = (tile >> 3) * 64;
    const int c0 = (tile & 7) * 64;

    u64 acc[4][2];
#pragma unroll
    for (int r = 0; r < 4; r++)
#pragma unroll
        for (int j = 0; j < 2; j++) acc[r][j] = 0ull;

    for (int k0 = 0; k0 < DD; k0 += 16) {
        if (ta == 0) {
            int r = tid >> 2, c = (tid & 3) << 2;
            float4 v = *(const float4*)(A + (size_t)(r0 + r) * DD + k0 + c);
            As[c + 0][r] = v.x; As[c + 1][r] = v.y;
            As[c + 2][r] = v.z; As[c + 3][r] = v.w;
        } else {
            int r = tid >> 4, c = (tid & 15) << 2;
            float4 v = *(const float4*)(A + (size_t)(k0 + r) * DD + r0 + c);
            *(float4*)&As[r][c] = v;
        }
        {
            int r = tid >> 4, c = (tid & 15) << 2;
            *(float4*)&Bs[r][c] = *(const float4*)(B + (size_t)(k0 + r) * DD + c0 + c);
        }
        __syncthreads();
#pragma unroll
        for (int kk = 0; kk < 16; kk++) {
            float4 a0 = *(const float4*)&As[kk][ty * 4];
            u64 a2[4];
            a2[0] = dup2(a0.x); a2[1] = dup2(a0.y);
            a2[2] = dup2(a0.z); a2[3] = dup2(a0.w);
            u64 b2[2];
#pragma unroll
            for (int j = 0; j < 2; j++)
                b2[j] = *(const u64*)&Bs[kk][(j * 16 + tx) * 2];
#pragma unroll
            for (int r = 0; r < 4; r++)
#pragma unroll
                for (int j = 0; j < 2; j++) ffma2(acc[r][j], a2[r], b2[j]);
        }
        __syncthreads();
    }
#pragma unroll
    for (int r = 0; r < 4; r++) {
#pragma unroll
        for (int j = 0; j < 2; j++) {
            float2 f = upk2(acc[r][j]);
            const int row = r0 + ty * 4 + r;
            const int col = c0 + (j * 16 + tx) * 2;
            if (epi == 0) {
                f.x *= sc; f.y *= sc;
            } else if (epi == 1) {
                if (row == col)     f.x += kInvTemp;
                if (row == col + 1) f.y += kInvTemp;
            } else if (epi == 2) {
                f.x = 1.5f * Pin[(size_t)row * DD + col]     - 0.5f * f.x;
                f.y = 1.5f * Pin[(size_t)row * DD + col + 1] - 0.5f * f.y;
            } else {
                const float cc2 = kInvTemp * sc;
                f.x -= cc2 * Pin[(size_t)row * DD + col];
                f.y -= cc2 * Pin[(size_t)row * DD + col + 1];
            }
            *(float2*)(C + (size_t)row * DD + col) = f;
        }
    }
}

__global__ __launch_bounds__(256)
void persist_chain(const float* __restrict__ W, bf16* __restrict__ w0,
                   bf16* __restrict__ w1, float* __restrict__ mc, int isL0) {
    __shared__ __align__(16) float As[16][68];
    __shared__ __align__(16) float Bs[16][64];
    __shared__ float red[256];
    float (*tsub)[33] = (float(*)[33])&As[0][0];   // 32x33 floats = 4224B <= As

    const int tile = blockIdx.x;
    const int tid = threadIdx.x;

    // s0: T1 = Sig @ W
    if (tile < 64) tile_gemm(g_T1, g_sig, W, nullptr, 1.0f, 0, 0, tile, As, Bs);
    gridbar();
    // s1: cov = W^T @ T1 + I/temp
    if (tile < 64) tile_gemm(g_cov, W, g_T1, nullptr, 1.0f, 1, 1, tile, As, Bs);
    gridbar();
    // s2: trace -> scal (CTA 0)
    if (tile == 0) {
        float s = g_cov[(size_t)(2 * tid) * (DD + 1)]
                + g_cov[(size_t)(2 * tid + 1) * (DD + 1)];
        red[tid] = s;
        __syncthreads();
        for (int k = 128; k > 0; k >>= 1) {
            if (tid < k) red[tid] += red[tid + k];
            __syncthreads();
        }
        if (tid == 0) {
            float tr = red[0];
            g_scal[0] = 1.0f / tr;
            g_scal[1] = 1.0f / sqrtf(tr);
        }
    }
    gridbar();
    // s3: P0 = 1.5 I - 0.5 cov/tr
    {
        const float s0 = g_scal[0];
#pragma unroll
        for (int q = 0; q < 8; q++) {
            int idx = tile * 2048 + q * 256 + tid;
            int i = idx >> 9, j = idx & (DD - 1);
            g_P0[idx] = ((i == j) ? 1.5f : 0.0f) - 0.5f * g_cov[idx] * s0;
        }
    }
    gridbar();

    float* P = g_P0;
    float* Pn = g_P1;
    for (int it = 1; it < 10; it++) {
        if (tile < 64) tile_gemm(g_A1, P, P, nullptr, 1.0f, 0, 0, tile, As, Bs);
        else           tile_gemm(g_A2, P, g_cov, nullptr, g_scal[0], 0, 0, tile - 64, As, Bs);
        gridbar();
        if (tile < 64) tile_gemm(Pn, g_A1, g_A2, P, 1.0f, 2, 0, tile, As, Bs);
        gridbar();
        float* t = P; P = Pn; Pn = t;
    }

    // f1: A1 = P@P ; A2 = (P@cov)/tr
    if (tile < 64) tile_gemm(g_A1, P, P, nullptr, 1.0f, 0, 0, tile, As, Bs);
    else           tile_gemm(g_A2, P, g_cov, nullptr, g_scal[0], 0, 0, tile - 64, As, Bs);
    gridbar();
    // f2: Sig' = A2@P - (1/(tr*temp)) A1 ; M = (W@P) * 1/sqrt(tr)
    if (tile < 64) tile_gemm(g_sig, g_A2, P, g_A1, g_scal[0], 3, 0, tile, As, Bs);
    else           tile_gemm(g_M, W, P, nullptr, g_scal[1], 0, 0, tile - 64, As, Bs);
    gridbar();
    // f3: M^T split -> w0/w1 (tiles 0-63, 64x64 blocks via 32x32 sub-transposes);
    //     mc[n] = sum_k mean[k]*M[k][n] (tiles 64-127, layer 0 only)
    if (tile < 64) {
        const int br = tile >> 3, bc = tile & 7;
#pragma unroll
        for (int sj = 0; sj < 2; sj++)
#pragma unroll
            for (int si = 0; si < 2; si++) {
                int r = tid >> 3, c = (tid & 7) * 4;
                float4 v = *(const float4*)(g_M + (size_t)(br * 64 + si * 32 + r) * DD
                                            + bc * 64 + sj * 32 + c);
                tsub[r][c] = v.x; tsub[r][c + 1] = v.y;
                tsub[r][c + 2] = v.z; tsub[r][c + 3] = v.w;
                __syncthreads();
                int cc = tid >> 3, rr = (tid & 7) * 4;
                bf16 h[4], l[4];
#pragma unroll
                for (int i = 0; i < 4; i++) split2(tsub[rr + i][cc], h[i], l[i]);
                size_t off = (size_t)(bc * 64 + sj * 32 + cc) * DD + br * 64 + si * 32 + rr;
                *(uint2*)(w0 + off) = make_uint2(pack2(h[0], h[1]), pack2(h[2], h[3]));
                *(uint2*)(w1 + off) = make_uint2(pack2(l[0], l[1]), pack2(l[2], l[3]));
                __syncthreads();
            }
    } else if (isL0) {
        const int col = (tile - 64) * 8 + (tid >> 5);
        const int lane = tid & 31;
        float s = 0.f;
        for (int k = lane; k < DD; k += 32)
            s += g_mean[k] * g_M[(size_t)k * DD + col];
#pragma unroll
        for (int o = 16; o > 0; o >>= 1)
            s += __shfl_down_sync(0xffffffffu, s, o);
        if (lane == 0) mc[col] = s;
    }
}

// ---------------------------------------------------------------------------
// orchestration — two-stream fork/join; Gram = our 4th launch (ncu)
// ---------------------------------------------------------------------------
extern "C" void kernel_launch(void* const* d_in, const int* in_sizes, int n_in,
                              void* d_out, int out_size) {
    (void)in_sizes; (void)n_in; (void)out_size;
    const float* x = (const float*)d_in[0];
    const float* W[3] = {(const float*)d_in[1], (const float*)d_in[2],
                         (const float*)d_in[3]};
    float* out = (float*)d_out;

    float *pcovpart, *pmc;
    bf16 *psA0, *psA1, *psB0, *psB1, *pt0, *pt1, *pw0, *pw1;
    cudaGetSymbolAddress((void**)&pcovpart, g_covpart);
    cudaGetSymbolAddress((void**)&pmc, g_mcv);
    cudaGetSymbolAddress((void**)&psA0, g_sA0);
    cudaGetSymbolAddress((void**)&psA1, g_sA1);
    cudaGetSymbolAddress((void**)&psB0, g_sB0);
    cudaGetSymbolAddress((void**)&psB1, g_sB1);
    cudaGetSymbolAddress((void**)&pt0, g_t0);
    cudaGetSymbolAddress((void**)&pt1, g_t1);
    cudaGetSymbolAddress((void**)&pw0, g_w0);
    cudaGetSymbolAddress((void**)&pw1, g_w1);

    cudaFuncSetAttribute(mma_gemm<1>, cudaFuncAttributeMaxDynamicSharedMemorySize, SMEMSZ);
    cudaFuncSetAttribute(mma_gemm<2>, cudaFuncAttributeMaxDynamicSharedMemorySize, SMEMSZ);
    cudaFuncSetAttribute(mma_gemm<3>, cudaFuncAttributeMaxDynamicSharedMemorySize, SMEMSZ);

    cudaStream_t s2;
    cudaStreamCreateWithFlags(&s2, cudaStreamNonBlocking);
    cudaEvent_t evRoot, evMean, evSig, evM[3];
    cudaEventCreateWithFlags(&evRoot, cudaEventDisableTiming);
    cudaEventCreateWithFlags(&evMean, cudaEventDisableTiming);
    cudaEventCreateWithFlags(&evSig, cudaEventDisableTiming);
    for (int i = 0; i < 3; i++) cudaEventCreateWithFlags(&evM[i], cudaEventDisableTiming);

    const int N4BIG = NROWS * DD / 4;
    const dim3 gact(4, NROWS / 128);
    const dim3 gcov(10, 1, NSPLIT);

    // #1 on origin stream, then fork s2 via evRoot (capture-legal)
    split_trans2_kernel<<<dim3(NROWS / 32, 16), 256>>>(x, pt0, pt1, NROWS);     // #1
    cudaEventRecord(evRoot, 0);
    cudaStreamWaitEvent(s2, evRoot, 0);

    split_rows2_kernel<<<N4BIG / 256, 256, 0, s2>>>(x, psA0, psA1, N4BIG);      // #2
    colsum_kernel<<<256, 512, 0, s2>>>(x);                                      // #3
    mma_gemm<2><<<gcov, 256, SMEMSZ>>>(pt0, pt1, pt0, pt1, pcovpart,
                                       nullptr, nullptr, nullptr);              // #4 (ncu)
    mean_final_kernel<<<1, 512, 0, s2>>>();                                     // #5
    zero_mc12_kernel<<<1, 1024, 0, s2>>>();                                     // #6
    cudaEventRecord(evMean, s2);

    cudaStreamWaitEvent(0, evMean, 0);
    reduce_sig_kernel<<<256, 1024>>>();                                         // #7
    cudaEventRecord(evSig, 0);

    // ---- stream s2: one persistent chain kernel per layer ----
    cudaStreamWaitEvent(s2, evSig, 0);
    for (int l = 0; l < 3; l++) {
        persist_chain<<<PCTAS, 256, 0, s2>>>(W[l],
                                             pw0 + (size_t)l * DD * DD,
                                             pw1 + (size_t)l * DD * DD,
                                             pmc + l * DD, l == 0);
        cudaEventRecord(evM[l], s2);
    }

    // ---- stream 0: three big out-GEMMs, each gated on its M ----
    bf16* in0 = psA0; bf16* in1 = psA1;
    bf16* ot0 = psB0; bf16* ot1 = psB1;
    for (int l = 0; l < 3; l++) {
        float* O = out + (size_t)l * NROWS * DD;
        cudaStreamWaitEvent(0, evM[l], 0);
        if (l < 2)
            mma_gemm<1><<<gact, 256, SMEMSZ>>>(in0, in1,
                                               pw0 + (size_t)l * DD * DD,
                                               pw1 + (size_t)l * DD * DD,
                                               O, pmc + l * DD, ot0, ot1);
        else
            mma_gemm<3><<<gact, 256, SMEMSZ>>>(in0, in1,
                                               pw0 + (size_t)l * DD * DD,
                                               pw1 + (size_t)l * DD * DD,
                                               O, pmc + l * DD, nullptr, nullptr);
        bf16* t0s = in0; in0 = ot0; ot0 = t0s;
        bf16* t1s = in1; in1 = ot1; ot1 = t1s;
    }
}

// round 13
// speedup vs baseline: 1.5037x; 1.0678x over previous
#include <cuda_runtime.h>
#include <cuda_bf16.h>
#include <math.h>
#include <stdint.h>

#define NROWS 65536
#define DD    512
#define NSPLIT 29            // 10*29=290 CTAs -> single wave for Gram
#define KCHTOT 2048
#define PCTAS 128            // persistent-chain grid (co-resident)
static __device__ __constant__ float kInvTemp = 0.1f;

typedef unsigned long long u64;
typedef __nv_bfloat16 bf16;

// ---------------------------------------------------------------------------
// helpers
// ---------------------------------------------------------------------------
__device__ __forceinline__ uint32_t smem_u32(const void* p) {
    uint32_t a;
    asm("{ .reg .u64 t; cvta.to.shared.u64 t, %1; cvt.u32.u64 %0, t; }"
        : "=r"(a) : "l"(p));
    return a;
}
__device__ __forceinline__ void cp16(uint32_t dst, const void* src) {
    asm volatile("cp.async.cg.shared.global [%0], [%1], 16;"
                 :: "r"(dst), "l"(src) : "memory");
}
__device__ __forceinline__ void mma16816(float* c, const uint32_t* a,
                                         const uint32_t* b) {
    asm volatile(
        "mma.sync.aligned.m16n8k16.row.col.f32.bf16.bf16.f32 "
        "{%0,%1,%2,%3}, {%4,%5,%6,%7}, {%8,%9}, {%0,%1,%2,%3};"
        : "+f"(c[0]), "+f"(c[1]), "+f"(c[2]), "+f"(c[3])
        : "r"(a[0]), "r"(a[1]), "r"(a[2]), "r"(a[3]), "r"(b[0]), "r"(b[1]));
}
__device__ __forceinline__ void ldsm4(uint32_t* r, uint32_t addr) {
    asm volatile("ldmatrix.sync.aligned.m8n8.x4.shared.b16 {%0,%1,%2,%3}, [%4];"
                 : "=r"(r[0]), "=r"(r[1]), "=r"(r[2]), "=r"(r[3]) : "r"(addr));
}
__device__ __forceinline__ int sw(int r, int k) {
    int s = ((k >> 3) ^ (r & 3) ^ ((r >> 2) & 1)) & 3;
    return r * 64 + s * 16 + (k & 7) * 2;
}
__device__ __forceinline__ void split2(float x, bf16 &hi, bf16 &lo) {
    hi = __float2bfloat16_rn(x);
    lo = __float2bfloat16_rn(x - __bfloat162float(hi));
}
__device__ __forceinline__ uint32_t pack2(bf16 a, bf16 b) {
    __nv_bfloat162 v(a, b);
    return *reinterpret_cast<uint32_t*>(&v);
}
__device__ __forceinline__ void ffma2(u64 &d, u64 a, u64 b) {
    asm("fma.rn.f32x2 %0, %1, %2, %0;" : "+l"(d) : "l"(a), "l"(b));
}
__device__ __forceinline__ float2 upk2(u64 v) {
    float2 r;
    asm("mov.b64 {%0, %1}, %2;" : "=f"(r.x), "=f"(r.y) : "l"(v));
    return r;
}
__device__ __forceinline__ u64 dup2(float x) {
    u64 r;
    asm("mov.b64 %0, {%1, %1};" : "=l"(r) : "f"(x));
    return r;
}

// ---------------------------------------------------------------------------
// scratch
// ---------------------------------------------------------------------------
__device__ float g_colpart[256 * DD];
__device__ float g_mean[DD];
__device__ float g_mcv[3 * DD];
__device__ float g_covpart[(size_t)NSPLIT * DD * DD];
__device__ float g_sig[DD * DD];
__device__ float g_cov[DD * DD];
__device__ float g_T1[DD * DD];
__device__ float g_M[DD * DD];
__device__ float g_MeffA[DD * DD];
__device__ float g_MeffB[DD * DD];
__device__ float g_P0[DD * DD];
__device__ float g_P1[DD * DD];
__device__ float g_A1[DD * DD];
__device__ float g_A2[DD * DD];
__device__ float g_scal[2];
__device__ unsigned g_barCount;
__device__ unsigned g_barGen;
__device__ bf16 g_sA0[(size_t)NROWS * DD];    // x splits (shared by all out-GEMMs)
__device__ bf16 g_sA1[(size_t)NROWS * DD];
__device__ bf16 g_t0[(size_t)DD * NROWS];     // transposed x splits
__device__ bf16 g_t1[(size_t)DD * NROWS];
__device__ bf16 g_w0[3 * DD * DD];            // per-layer Meff^T splits
__device__ bf16 g_w1[3 * DD * DD];

__constant__ int cTI[10] = {0,0,0,0,1,1,1,2,2,3};
__constant__ int cTJ[10] = {0,1,2,3,1,2,3,2,3,3};

// ---------------------------------------------------------------------------
// Big bf16-split mma.sync GEMM.
// MODE 2: Gram split-K partial ; MODE 3: out = acc - mc[col] (fp32 only)
// ---------------------------------------------------------------------------
#define STAGE_BYTES 32768
#define SMEMSZ (2 * STAGE_BYTES)

template <int MODE>
__global__ __launch_bounds__(256, 2)
void mma_gemm(const bf16* __restrict__ a0g, const bf16* __restrict__ a1g,
              const bf16* __restrict__ b0g, const bf16* __restrict__ b1g,
              float* __restrict__ out, const float* __restrict__ mc) {
    constexpr int LD = (MODE == 2) ? NROWS : DD;

    extern __shared__ __align__(128) char sm[];
    const uint32_t smb = smem_u32(sm);

    const int tid = threadIdx.x;
    const int lane = tid & 31, wid = tid >> 5;
    const int warpRow = wid & 1;
    const int warpCol = wid >> 1;
    const int g = lane >> 2, t4 = lane & 3;
    const int laneRow = lane & 7, grp = lane >> 3;

    int rowBase, colBase, nch;
    size_t kStart;
    float* outp;
    if (MODE == 2) {
        rowBase = cTI[blockIdx.x] * 128;
        colBase = cTJ[blockIdx.x] * 128;
        int c0 = (int)((size_t)blockIdx.z * KCHTOT / NSPLIT);
        int c1 = (int)((size_t)(blockIdx.z + 1) * KCHTOT / NSPLIT);
        kStart = (size_t)c0 * 32;
        nch = c1 - c0;
        outp = out + (size_t)blockIdx.z * DD * DD;
    } else {
        rowBase = blockIdx.y * 128;
        colBase = blockIdx.x * 128;
        kStart = 0;
        nch = DD / 32;
        outp = out;
    }

    float acc[4][4][4];
#pragma unroll
    for (int mi = 0; mi < 4; mi++)
#pragma unroll
        for (int ni = 0; ni < 4; ni++)
#pragma unroll
            for (int q = 0; q < 4; q++) acc[mi][ni][q] = 0.f;

    uint32_t aOff[4], bOff[2];
#pragma unroll
    for (int mi = 0; mi < 4; mi++)
        aOff[mi] = sw(warpRow * 64 + mi * 16 + (grp & 1) * 8 + laneRow, (grp >> 1) * 8);
#pragma unroll
    for (int p = 0; p < 2; p++)
        bOff[p] = sw(warpCol * 32 + p * 16 + (grp >> 1) * 8 + laneRow, (grp & 1) * 8);

    const int lr = tid >> 2;
    const int lseg = tid & 3;

    auto load_chunk = [&](int ch, int stage) {
        const size_t kpos = kStart + (size_t)ch * 32;
        const uint32_t sb = smb + stage * STAGE_BYTES;
#pragma unroll
        for (int i = 0; i < 2; i++) {
            const int r = lr + i * 64;
            const int soff = sw(r, lseg * 8);
            const size_t ga = (size_t)(rowBase + r) * LD + kpos + lseg * 8;
            const size_t gb = (size_t)(colBase + r) * LD + kpos + lseg * 8;
            cp16(sb + soff,         a0g + ga);
            cp16(sb + 8192 + soff,  a1g + ga);
            cp16(sb + 16384 + soff, b0g + gb);
            cp16(sb + 24576 + soff, b1g + gb);
        }
        asm volatile("cp.async.commit_group;" ::: "memory");
    };

    load_chunk(0, 0);

    for (int ch = 0; ch < nch; ch++) {
        if (ch + 1 < nch) {
            load_chunk(ch + 1, (ch + 1) & 1);
            asm volatile("cp.async.wait_group 1;" ::: "memory");
        } else {
            asm volatile("cp.async.wait_group 0;" ::: "memory");
        }
        __syncthreads();

        const uint32_t sA0 = smb + (ch & 1) * STAGE_BYTES;
        const uint32_t sA1 = sA0 + 8192;
        const uint32_t sB0 = sA0 + 16384;
        const uint32_t sB1 = sA0 + 24576;

#pragma unroll
        for (int ks = 0; ks < 2; ks++) {
            const uint32_t kx = ks * 32;
            uint32_t fa0[4][4], fa1[4][4], fb0[2][4], fb1[2][4];
#pragma unroll
            for (int mi = 0; mi < 4; mi++) {
                ldsm4(fa0[mi], sA0 + (aOff[mi] ^ kx));
                ldsm4(fa1[mi], sA1 + (aOff[mi] ^ kx));
            }
#pragma unroll
            for (int p = 0; p < 2; p++) {
                ldsm4(fb0[p], sB0 + (bOff[p] ^ kx));
                ldsm4(fb1[p], sB1 + (bOff[p] ^ kx));
            }
#pragma unroll
            for (int t = 0; t < 3; t++) {
#pragma unroll
                for (int ni = 0; ni < 4; ni++) {
                    const uint32_t* bb =
                        (t == 1) ? &fb1[ni >> 1][(ni & 1) * 2]
                                 : &fb0[ni >> 1][(ni & 1) * 2];
#pragma unroll
                    for (int mi = 0; mi < 4; mi++) {
                        const uint32_t* aa = (t == 2) ? fa1[mi] : fa0[mi];
                        mma16816(acc[mi][ni], aa, bb);
                    }
                }
            }
        }
        __syncthreads();
    }

#pragma unroll
    for (int mi = 0; mi < 4; mi++) {
        const int row0 = rowBase + warpRow * 64 + mi * 16 + g;
#pragma unroll
        for (int ni = 0; ni < 4; ni++) {
            const int col = colBase + warpCol * 32 + ni * 8 + t4 * 2;
            float v0 = acc[mi][ni][0], v1 = acc[mi][ni][1];
            float v2 = acc[mi][ni][2], v3 = acc[mi][ni][3];
            if (MODE == 3) {
                const float m0 = mc[col], m1 = mc[col + 1];
                v0 -= m0; v1 -= m1; v2 -= m0; v3 -= m1;
            }
            *(float2*)(outp + (size_t)row0 * DD + col)       = make_float2(v0, v1);
            *(float2*)(outp + (size_t)(row0 + 8) * DD + col) = make_float2(v2, v3);
        }
    }
}

// ---------------------------------------------------------------------------
// split / transpose / reduction kernels
// ---------------------------------------------------------------------------
__global__ void split_rows2_kernel(const float* __restrict__ in,
                                   bf16* __restrict__ s0, bf16* __restrict__ s1,
                                   int n4) {
    int idx = blockIdx.x * 256 + threadIdx.x;
    if (idx >= n4) return;
    float4 v = ((const float4*)in)[idx];
    bf16 h0, l0, h1, l1, h2, l2, h3, l3;
    split2(v.x, h0, l0); split2(v.y, h1, l1);
    split2(v.z, h2, l2); split2(v.w, h3, l3);
    ((uint2*)s0)[idx] = make_uint2(pack2(h0, h1), pack2(h2, h3));
    ((uint2*)s1)[idx] = make_uint2(pack2(l0, l1), pack2(l2, l3));
}

__global__ void split_trans2_kernel(const float* __restrict__ src,
                                    bf16* __restrict__ t0, bf16* __restrict__ t1,
                                    int ldout) {
    __shared__ float ts[32][33];
    const int tid = threadIdx.x;
    const int n0 = blockIdx.x * 32;
    const int d0 = blockIdx.y * 32;
    int r = tid >> 3, c = (tid & 7) * 4;
    float4 v = *(const float4*)(src + (size_t)(n0 + r) * DD + d0 + c);
    ts[r][c] = v.x; ts[r][c + 1] = v.y; ts[r][c + 2] = v.z; ts[r][c + 3] = v.w;
    __syncthreads();
    int cc = tid >> 3, rr = (tid & 7) * 4;
    bf16 h[4], l[4];
#pragma unroll
    for (int i = 0; i < 4; i++) split2(ts[rr + i][cc], h[i], l[i]);
    size_t off = (size_t)(d0 + cc) * ldout + n0 + rr;
    *(uint2*)(t0 + off) = make_uint2(pack2(h[0], h[1]), pack2(h[2], h[3]));
    *(uint2*)(t1 + off) = make_uint2(pack2(l[0], l[1]), pack2(l[2], l[3]));
}

__global__ void colsum_kernel(const float* __restrict__ H) {
    const int b = blockIdx.x;
    const int t = threadIdx.x;
    const float* p = H + (size_t)b * 256 * DD + t;
    float s = 0.f;
#pragma unroll 8
    for (int r = 0; r < 256; r++) s += p[(size_t)r * DD];
    g_colpart[b * DD + t] = s;
}

__global__ void mean_final_kernel() {
    const int t = threadIdx.x;
    float s = 0.f;
#pragma unroll 8
    for (int b = 0; b < 256; b++) s += g_colpart[b * DD + t];
    g_mean[t] = s * (1.0f / (float)NROWS);
}

__global__ void reduce_sig_kernel() {
    const int idx = blockIdx.x * 1024 + threadIdx.x;
    const int i = idx >> 9, j = idx & (DD - 1);
    const int src = ((i >> 7) <= (j >> 7)) ? (i * DD + j) : (j * DD + i);
    float s = 0.f;
#pragma unroll
    for (int z = 0; z < NSPLIT; z++)
        s += g_covpart[(size_t)z * DD * DD + src];
    g_sig[idx] = s * (1.0f / (float)NROWS) - g_mean[i] * g_mean[j];
}

// ---------------------------------------------------------------------------
// Persistent per-layer chain: cov -> NS -> M -> Meff composition -> splits + v
// ---------------------------------------------------------------------------
__device__ __forceinline__ void gridbar() {
    __syncthreads();
    if (threadIdx.x == 0) {
        unsigned g = atomicAdd(&g_barGen, 0u);
        __threadfence();
        if (atomicAdd(&g_barCount, 1u) == PCTAS - 1) {
            g_barCount = 0;
            __threadfence();
            atomicAdd(&g_barGen, 1u);
        } else {
            while (atomicAdd(&g_barGen, 0u) == g) __nanosleep(64);
        }
    }
    __syncthreads();
    __threadfence();
}

// EPI: 0 = C=acc*sc ; 1 = C=acc+I/temp ; 2 = C=1.5*Pin-0.5*acc ; 3 = C=acc-(kInvTemp*sc)*Pin
__device__ void tile_gemm(float* __restrict__ C, const float* __restrict__ A,
                          const float* __restrict__ B, const float* __restrict__ Pin,
                          float sc, int epi, int ta, int tile,
                          float (*As)[68], float (*Bs)[64]) {
    const int tid = threadIdx.x;
    const int tx = tid & 15;
    const int ty = tid >> 4;
    const int r0 = (tile >> 3) * 64;
    const int c0 = (tile & 7) * 64;

    u64 acc[4][2];
#pragma unroll
    for (int r = 0; r < 4; r++)
#pragma unroll
        for (int j = 0; j < 2; j++) acc[r][j] = 0ull;

    for (int k0 = 0; k0 < DD; k0 += 16) {
        if (ta == 0) {
            int r = tid >> 2, c = (tid & 3) << 2;
            float4 v = *(const float4*)(A + (size_t)(r0 + r) * DD + k0 + c);
            As[c + 0][r] = v.x; As[c + 1][r] = v.y;
            As[c + 2][r] = v.z; As[c + 3][r] = v.w;
        } else {
            int r = tid >> 4, c = (tid & 15) << 2;
            float4 v = *(const float4*)(A + (size_t)(k0 + r) * DD + r0 + c);
            *(float4*)&As[r][c] = v;
        }
        {
            int r = tid >> 4, c = (tid & 15) << 2;
            *(float4*)&Bs[r][c] = *(const float4*)(B + (size_t)(k0 + r) * DD + c0 + c);
        }
        __syncthreads();
#pragma unroll
        for (int kk = 0; kk < 16; kk++) {
            float4 a0 = *(const float4*)&As[kk][ty * 4];
            u64 a2[4];
            a2[0] = dup2(a0.x); a2[1] = dup2(a0.y);
            a2[2] = dup2(a0.z); a2[3] = dup2(a0.w);
            u64 b2[2];
#pragma unroll
            for (int j = 0; j < 2; j++)
                b2[j] = *(const u64*)&Bs[kk][(j * 16 + tx) * 2];
#pragma unroll
            for (int r = 0; r < 4; r++)
#pragma unroll
                for (int j = 0; j < 2; j++) ffma2(acc[r][j], a2[r], b2[j]);
        }
        __syncthreads();
    }
#pragma unroll
    for (int r = 0; r < 4; r++) {
#pragma unroll
        for (int j = 0; j < 2; j++) {
            float2 f = upk2(acc[r][j]);
            const int row = r0 + ty * 4 + r;
            const int col = c0 + (j * 16 + tx) * 2;
            if (epi == 0) {
                f.x *= sc; f.y *= sc;
            } else if (epi == 1) {
                if (row == col)     f.x += kInvTemp;
                if (row == col + 1) f.y += kInvTemp;
            } else if (epi == 2) {
                f.x = 1.5f * Pin[(size_t)row * DD + col]     - 0.5f * f.x;
                f.y = 1.5f * Pin[(size_t)row * DD + col + 1] - 0.5f * f.y;
            } else {
                const float cc2 = kInvTemp * sc;
                f.x -= cc2 * Pin[(size_t)row * DD + col];
                f.y -= cc2 * Pin[(size_t)row * DD + col + 1];
            }
            *(float2*)(C + (size_t)row * DD + col) = f;
        }
    }
}

__global__ __launch_bounds__(256)
void persist_chain(const float* __restrict__ W, bf16* __restrict__ w0,
                   bf16* __restrict__ w1, float* __restrict__ mc,
                   const float* __restrict__ MeffPrev,
                   float* __restrict__ MeffOut, int isL0) {
    __shared__ __align__(16) float As[16][68];
    __shared__ __align__(16) float Bs[16][64];
    __shared__ float red[256];
    float (*tsub)[33] = (float(*)[33])&As[0][0];

    const int tile = blockIdx.x;
    const int tid = threadIdx.x;

    // s0: T1 = Sig @ W
    if (tile < 64) tile_gemm(g_T1, g_sig, W, nullptr, 1.0f, 0, 0, tile, As, Bs);
    gridbar();
    // s1: cov = W^T @ T1 + I/temp
    if (tile < 64) tile_gemm(g_cov, W, g_T1, nullptr, 1.0f, 1, 1, tile, As, Bs);
    gridbar();
    // s2: trace -> scal
    if (tile == 0) {
        float s = g_cov[(size_t)(2 * tid) * (DD + 1)]
                + g_cov[(size_t)(2 * tid + 1) * (DD + 1)];
        red[tid] = s;
        __syncthreads();
        for (int k = 128; k > 0; k >>= 1) {
            if (tid < k) red[tid] += red[tid + k];
            __syncthreads();
        }
        if (tid == 0) {
            float tr = red[0];
            g_scal[0] = 1.0f / tr;
            g_scal[1] = 1.0f / sqrtf(tr);
        }
    }
    gridbar();
    // s3: P0 = 1.5 I - 0.5 cov/tr
    {
        const float s0 = g_scal[0];
#pragma unroll
        for (int q = 0; q < 8; q++) {
            int idx = tile * 2048 + q * 256 + tid;
            int i = idx >> 9, j = idx & (DD - 1);
            g_P0[idx] = ((i == j) ? 1.5f : 0.0f) - 0.5f * g_cov[idx] * s0;
        }
    }
    gridbar();

    float* P = g_P0;
    float* Pn = g_P1;
    for (int it = 1; it < 10; it++) {
        if (tile < 64) tile_gemm(g_A1, P, P, nullptr, 1.0f, 0, 0, tile, As, Bs);
        else           tile_gemm(g_A2, P, g_cov, nullptr, g_scal[0], 0, 0, tile - 64, As, Bs);
        gridbar();
        if (tile < 64) tile_gemm(Pn, g_A1, g_A2, P, 1.0f, 2, 0, tile, As, Bs);
        gridbar();
        float* t = P; P = Pn; Pn = t;
    }

    // f1: A1 = P@P ; A2 = (P@cov)/tr
    if (tile < 64) tile_gemm(g_A1, P, P, nullptr, 1.0f, 0, 0, tile, As, Bs);
    else           tile_gemm(g_A2, P, g_cov, nullptr, g_scal[0], 0, 0, tile - 64, As, Bs);
    gridbar();
    // f2: Sig' = A2@P - (1/(tr*temp)) A1 ; M = (W@P) * 1/sqrt(tr)
    if (tile < 64) tile_gemm(g_sig, g_A2, P, g_A1, g_scal[0], 3, 0, tile, As, Bs);
    else           tile_gemm(g_M, W, P, nullptr, g_scal[1], 0, 0, tile - 64, As, Bs);
    gridbar();
    // f2b: Meff = isL0 ? M : MeffPrev @ M
    if (isL0) {
#pragma unroll
        for (int q = 0; q < 8; q++) {
            int idx = tile * 2048 + q * 256 + tid;
            MeffOut[idx] = g_M[idx];
        }
    } else if (tile < 64) {
        tile_gemm(MeffOut, MeffPrev, g_M, nullptr, 1.0f, 0, 0, tile, As, Bs);
    }
    gridbar();
    // f3: Meff^T split -> w0/w1 (tiles 0-63); v = mean @ Meff -> mc (tiles 64-127)
    if (tile < 64) {
        const int br = tile >> 3, bc = tile & 7;
#pragma unroll
        for (int sj = 0; sj < 2; sj++)
#pragma unroll
            for (int si = 0; si < 2; si++) {
                int r = tid >> 3, c = (tid & 7) * 4;
                float4 v = *(const float4*)(MeffOut + (size_t)(br * 64 + si * 32 + r) * DD
                                            + bc * 64 + sj * 32 + c);
                tsub[r][c] = v.x; tsub[r][c + 1] = v.y;
                tsub[r][c + 2] = v.z; tsub[r][c + 3] = v.w;
                __syncthreads();
                int cc = tid >> 3, rr = (tid & 7) * 4;
                bf16 h[4], l[4];
#pragma unroll
                for (int i = 0; i < 4; i++) split2(tsub[rr + i][cc], h[i], l[i]);
                size_t off = (size_t)(bc * 64 + sj * 32 + cc) * DD + br * 64 + si * 32 + rr;
                *(uint2*)(w0 + off) = make_uint2(pack2(h[0], h[1]), pack2(h[2], h[3]));
                *(uint2*)(w1 + off) = make_uint2(pack2(l[0], l[1]), pack2(l[2], l[3]));
                __syncthreads();
            }
    } else {
        const int col = (tile - 64) * 8 + (tid >> 5);
        const int lane = tid & 31;
        float s = 0.f;
        for (int k = lane; k < DD; k += 32)
            s += g_mean[k] * MeffOut[(size_t)k * DD + col];
#pragma unroll
        for (int o = 16; o > 0; o >>= 1)
            s += __shfl_down_sync(0xffffffffu, s, o);
        if (lane == 0) mc[col] = s;
    }
}

// ---------------------------------------------------------------------------
// orchestration — streams/events created ONCE (first call = correctness run)
// so the capture call performs zero driver allocations.
// ---------------------------------------------------------------------------
static cudaStream_t s2, sO1, sO2;
static cudaEvent_t evRoot, evMean, evSig, evM[3], evO1, evO2;
static bool g_inited = false;

extern "C" void kernel_launch(void* const* d_in, const int* in_sizes, int n_in,
                              void* d_out, int out_size) {
    (void)in_sizes; (void)n_in; (void)out_size;
    const float* x = (const float*)d_in[0];
    const float* W[3] = {(const float*)d_in[1], (const float*)d_in[2],
                         (const float*)d_in[3]};
    float* out = (float*)d_out;

    float *pcovpart, *pmc, *pMA, *pMB;
    bf16 *psA0, *psA1, *pt0, *pt1, *pw0, *pw1;
    cudaGetSymbolAddress((void**)&pcovpart, g_covpart);
    cudaGetSymbolAddress((void**)&pmc, g_mcv);
    cudaGetSymbolAddress((void**)&pMA, g_MeffA);
    cudaGetSymbolAddress((void**)&pMB, g_MeffB);
    cudaGetSymbolAddress((void**)&psA0, g_sA0);
    cudaGetSymbolAddress((void**)&psA1, g_sA1);
    cudaGetSymbolAddress((void**)&pt0, g_t0);
    cudaGetSymbolAddress((void**)&pt1, g_t1);
    cudaGetSymbolAddress((void**)&pw0, g_w0);
    cudaGetSymbolAddress((void**)&pw1, g_w1);

    if (!g_inited) {
        g_inited = true;
        cudaFuncSetAttribute(mma_gemm<2>, cudaFuncAttributeMaxDynamicSharedMemorySize, SMEMSZ);
        cudaFuncSetAttribute(mma_gemm<3>, cudaFuncAttributeMaxDynamicSharedMemorySize, SMEMSZ);
        cudaStreamCreateWithFlags(&s2, cudaStreamNonBlocking);
        cudaStreamCreateWithFlags(&sO1, cudaStreamNonBlocking);
        cudaStreamCreateWithFlags(&sO2, cudaStreamNonBlocking);
        cudaEventCreateWithFlags(&evRoot, cudaEventDisableTiming);
        cudaEventCreateWithFlags(&evMean, cudaEventDisableTiming);
        cudaEventCreateWithFlags(&evSig, cudaEventDisableTiming);
        for (int i = 0; i < 3; i++)
            cudaEventCreateWithFlags(&evM[i], cudaEventDisableTiming);
        cudaEventCreateWithFlags(&evO1, cudaEventDisableTiming);
        cudaEventCreateWithFlags(&evO2, cudaEventDisableTiming);
    }

    const int N4BIG = NROWS * DD / 4;
    const dim3 gact(4, NROWS / 128);
    const dim3 gcov(10, 1, NSPLIT);

    // #1 on origin stream, then fork side streams via evRoot (capture-legal)
    split_trans2_kernel<<<dim3(NROWS / 32, 16), 256>>>(x, pt0, pt1, NROWS);     // #1
    cudaEventRecord(evRoot, 0);
    cudaStreamWaitEvent(s2, evRoot, 0);
    cudaStreamWaitEvent(sO1, evRoot, 0);
    cudaStreamWaitEvent(sO2, evRoot, 0);

    split_rows2_kernel<<<N4BIG / 256, 256, 0, s2>>>(x, psA0, psA1, N4BIG);      // #2
    colsum_kernel<<<256, 512, 0, s2>>>(x);                                      // #3
    mma_gemm<2><<<gcov, 256, SMEMSZ>>>(pt0, pt1, pt0, pt1, pcovpart, nullptr);  // #4 (ncu)
    mean_final_kernel<<<1, 512, 0, s2>>>();                                     // #5
    cudaEventRecord(evMean, s2);

    cudaStreamWaitEvent(0, evMean, 0);
    reduce_sig_kernel<<<256, 1024>>>();                                         // #6
    cudaEventRecord(evSig, 0);

    // ---- stream s2: per-layer persistent chains (sig propagation serial) ----
    cudaStreamWaitEvent(s2, evSig, 0);
    float* MeffPrev = nullptr;
    float* MeffOut = pMA;
    for (int l = 0; l < 3; l++) {
        persist_chain<<<PCTAS, 256, 0, s2>>>(W[l],
                                             pw0 + (size_t)l * DD * DD,
                                             pw1 + (size_t)l * DD * DD,
                                             pmc + l * DD,
                                             MeffPrev, MeffOut, l == 0);
        cudaEventRecord(evM[l], s2);
        MeffPrev = MeffOut;
        MeffOut = (MeffOut == pMA) ? pMB : pMA;
    }

    // ---- out-GEMMs: all read x splits, independent, 3 streams ----
    cudaStreamWaitEvent(0, evM[0], 0);
    mma_gemm<3><<<gact, 256, SMEMSZ>>>(psA0, psA1, pw0, pw1, out, pmc);

    cudaStreamWaitEvent(sO1, evM[1], 0);
    mma_gemm<3><<<gact, 256, SMEMSZ, sO1>>>(psA0, psA1,
                                            pw0 + (size_t)DD * DD,
                                            pw1 + (size_t)DD * DD,
                                            out + (size_t)NROWS * DD, pmc + DD);
    cudaEventRecord(evO1, sO1);

    cudaStreamWaitEvent(sO2, evM[2], 0);
    mma_gemm<3><<<gact, 256, SMEMSZ, sO2>>>(psA0, psA1,
                                            pw0 + (size_t)2 * DD * DD,
                                            pw1 + (size_t)2 * DD * DD,
                                            out + (size_t)2 * NROWS * DD, pmc + 2 * DD);
    cudaEventRecord(evO2, sO2);

    // join all side streams back into the capture origin stream
    cudaStreamWaitEvent(0, evO1, 0);
    cudaStreamWaitEvent(0, evO2, 0);
}

// round 14
// speedup vs baseline: 1.5433x; 1.0263x over previous
#include <cuda_runtime.h>
#include <cuda_bf16.h>
#include <math.h>
#include <stdint.h>

#define NROWS 65536
#define DD    512
#define NSPLIT 29            // 10*29=290 CTAs -> single wave for Gram
#define KCHTOT 2048
#define PCTAS 128            // persistent-chain grid (co-resident)
static __device__ __constant__ float kInvTemp = 0.1f;

typedef unsigned long long u64;
typedef __nv_bfloat16 bf16;

// ---------------------------------------------------------------------------
// helpers
// ---------------------------------------------------------------------------
__device__ __forceinline__ uint32_t smem_u32(const void* p) {
    uint32_t a;
    asm("{ .reg .u64 t; cvta.to.shared.u64 t, %1; cvt.u32.u64 %0, t; }"
        : "=r"(a) : "l"(p));
    return a;
}
__device__ __forceinline__ void cp16(uint32_t dst, const void* src) {
    asm volatile("cp.async.cg.shared.global [%0], [%1], 16;"
                 :: "r"(dst), "l"(src) : "memory");
}
__device__ __forceinline__ void mma16816(float* c, const uint32_t* a,
                                         const uint32_t* b) {
    asm volatile(
        "mma.sync.aligned.m16n8k16.row.col.f32.bf16.bf16.f32 "
        "{%0,%1,%2,%3}, {%4,%5,%6,%7}, {%8,%9}, {%0,%1,%2,%3};"
        : "+f"(c[0]), "+f"(c[1]), "+f"(c[2]), "+f"(c[3])
        : "r"(a[0]), "r"(a[1]), "r"(a[2]), "r"(a[3]), "r"(b[0]), "r"(b[1]));
}
__device__ __forceinline__ void ldsm4(uint32_t* r, uint32_t addr) {
    asm volatile("ldmatrix.sync.aligned.m8n8.x4.shared.b16 {%0,%1,%2,%3}, [%4];"
                 : "=r"(r[0]), "=r"(r[1]), "=r"(r[2]), "=r"(r[3]) : "r"(addr));
}
__device__ __forceinline__ int sw(int r, int k) {
    int s = ((k >> 3) ^ (r & 3) ^ ((r >> 2) & 1)) & 3;
    return r * 64 + s * 16 + (k & 7) * 2;
}
__device__ __forceinline__ void split2(float x, bf16 &hi, bf16 &lo) {
    hi = __float2bfloat16_rn(x);
    lo = __float2bfloat16_rn(x - __bfloat162float(hi));
}
__device__ __forceinline__ uint32_t pack2(bf16 a, bf16 b) {
    __nv_bfloat162 v(a, b);
    return *reinterpret_cast<uint32_t*>(&v);
}
__device__ __forceinline__ void ffma2(u64 &d, u64 a, u64 b) {
    asm("fma.rn.f32x2 %0, %1, %2, %0;" : "+l"(d) : "l"(a), "l"(b));
}
__device__ __forceinline__ float2 upk2(u64 v) {
    float2 r;
    asm("mov.b64 {%0, %1}, %2;" : "=f"(r.x), "=f"(r.y) : "l"(v));
    return r;
}
__device__ __forceinline__ u64 dup2(float x) {
    u64 r;
    asm("mov.b64 %0, {%1, %1};" : "=l"(r) : "f"(x));
    return r;
}

// ---------------------------------------------------------------------------
// scratch
// ---------------------------------------------------------------------------
__device__ float g_colpart[256 * DD];
__device__ float g_mean[DD];
__device__ float g_mcv[3 * DD];
__device__ float g_covpart[(size_t)NSPLIT * DD * DD];
__device__ float g_sig[DD * DD];
__device__ float g_cov[DD * DD];
__device__ float g_T1[DD * DD];
__device__ float g_M[DD * DD];
__device__ float g_MeffA[DD * DD];
__device__ float g_MeffB[DD * DD];
__device__ float g_P0[DD * DD];
__device__ float g_P1[DD * DD];
__device__ float g_A1[DD * DD];
__device__ float g_A2[DD * DD];
__device__ float g_scal[2];
__device__ unsigned g_barCount;
__device__ unsigned g_barGen;
__device__ bf16 g_sA0[(size_t)NROWS * DD];    // x splits (shared by all out-GEMMs)
__device__ bf16 g_sA1[(size_t)NROWS * DD];
__device__ bf16 g_t0[(size_t)DD * NROWS];     // transposed x splits
__device__ bf16 g_t1[(size_t)DD * NROWS];
__device__ bf16 g_w0[3 * DD * DD];            // per-layer Meff^T splits
__device__ bf16 g_w1[3 * DD * DD];

__constant__ int cTI[10] = {0,0,0,0,1,1,1,2,2,3};
__constant__ int cTJ[10] = {0,1,2,3,1,2,3,2,3,3};

// ---------------------------------------------------------------------------
// Big bf16-split mma.sync GEMM.
// MODE 2: Gram split-K partial ; MODE 3: out = acc - mc[col] (fp32 only)
// ---------------------------------------------------------------------------
#define STAGE_BYTES 32768
#define SMEMSZ (2 * STAGE_BYTES)

template <int MODE>
__global__ __launch_bounds__(256, 2)
void mma_gemm(const bf16* __restrict__ a0g, const bf16* __restrict__ a1g,
              const bf16* __restrict__ b0g, const bf16* __restrict__ b1g,
              float* __restrict__ out, const float* __restrict__ mc) {
    constexpr int LD = (MODE == 2) ? NROWS : DD;

    extern __shared__ __align__(128) char sm[];
    const uint32_t smb = smem_u32(sm);

    const int tid = threadIdx.x;
    const int lane = tid & 31, wid = tid >> 5;
    const int warpRow = wid & 1;
    const int warpCol = wid >> 1;
    const int g = lane >> 2, t4 = lane & 3;
    const int laneRow = lane & 7, grp = lane >> 3;

    int rowBase, colBase, nch;
    size_t kStart;
    float* outp;
    if (MODE == 2) {
        rowBase = cTI[blockIdx.x] * 128;
        colBase = cTJ[blockIdx.x] * 128;
        int c0 = (int)((size_t)blockIdx.z * KCHTOT / NSPLIT);
        int c1 = (int)((size_t)(blockIdx.z + 1) * KCHTOT / NSPLIT);
        kStart = (size_t)c0 * 32;
        nch = c1 - c0;
        outp = out + (size_t)blockIdx.z * DD * DD;
    } else {
        rowBase = blockIdx.y * 128;
        colBase = blockIdx.x * 128;
        kStart = 0;
        nch = DD / 32;
        outp = out;
    }

    float acc[4][4][4];
#pragma unroll
    for (int mi = 0; mi < 4; mi++)
#pragma unroll
        for (int ni = 0; ni < 4; ni++)
#pragma unroll
            for (int q = 0; q < 4; q++) acc[mi][ni][q] = 0.f;

    uint32_t aOff[4], bOff[2];
#pragma unroll
    for (int mi = 0; mi < 4; mi++)
        aOff[mi] = sw(warpRow * 64 + mi * 16 + (grp & 1) * 8 + laneRow, (grp >> 1) * 8);
#pragma unroll
    for (int p = 0; p < 2; p++)
        bOff[p] = sw(warpCol * 32 + p * 16 + (grp >> 1) * 8 + laneRow, (grp & 1) * 8);

    const int lr = tid >> 2;
    const int lseg = tid & 3;

    auto load_chunk = [&](int ch, int stage) {
        const size_t kpos = kStart + (size_t)ch * 32;
        const uint32_t sb = smb + stage * STAGE_BYTES;
#pragma unroll
        for (int i = 0; i < 2; i++) {
            const int r = lr + i * 64;
            const int soff = sw(r, lseg * 8);
            const size_t ga = (size_t)(rowBase + r) * LD + kpos + lseg * 8;
            const size_t gb = (size_t)(colBase + r) * LD + kpos + lseg * 8;
            cp16(sb + soff,         a0g + ga);
            cp16(sb + 8192 + soff,  a1g + ga);
            cp16(sb + 16384 + soff, b0g + gb);
            cp16(sb + 24576 + soff, b1g + gb);
        }
        asm volatile("cp.async.commit_group;" ::: "memory");
    };

    load_chunk(0, 0);

    for (int ch = 0; ch < nch; ch++) {
        if (ch + 1 < nch) {
            load_chunk(ch + 1, (ch + 1) & 1);
            asm volatile("cp.async.wait_group 1;" ::: "memory");
        } else {
            asm volatile("cp.async.wait_group 0;" ::: "memory");
        }
        __syncthreads();

        const uint32_t sA0 = smb + (ch & 1) * STAGE_BYTES;
        const uint32_t sA1 = sA0 + 8192;
        const uint32_t sB0 = sA0 + 16384;
        const uint32_t sB1 = sA0 + 24576;

#pragma unroll
        for (int ks = 0; ks < 2; ks++) {
            const uint32_t kx = ks * 32;
            uint32_t fa0[4][4], fa1[4][4], fb0[2][4], fb1[2][4];
#pragma unroll
            for (int mi = 0; mi < 4; mi++) {
                ldsm4(fa0[mi], sA0 + (aOff[mi] ^ kx));
                ldsm4(fa1[mi], sA1 + (aOff[mi] ^ kx));
            }
#pragma unroll
            for (int p = 0; p < 2; p++) {
                ldsm4(fb0[p], sB0 + (bOff[p] ^ kx));
                ldsm4(fb1[p], sB1 + (bOff[p] ^ kx));
            }
#pragma unroll
            for (int t = 0; t < 3; t++) {
#pragma unroll
                for (int ni = 0; ni < 4; ni++) {
                    const uint32_t* bb =
                        (t == 1) ? &fb1[ni >> 1][(ni & 1) * 2]
                                 : &fb0[ni >> 1][(ni & 1) * 2];
#pragma unroll
                    for (int mi = 0; mi < 4; mi++) {
                        const uint32_t* aa = (t == 2) ? fa1[mi] : fa0[mi];
                        mma16816(acc[mi][ni], aa, bb);
                    }
                }
            }
        }
        __syncthreads();
    }

#pragma unroll
    for (int mi = 0; mi < 4; mi++) {
        const int row0 = rowBase + warpRow * 64 + mi * 16 + g;
#pragma unroll
        for (int ni = 0; ni < 4; ni++) {
            const int col = colBase + warpCol * 32 + ni * 8 + t4 * 2;
            float v0 = acc[mi][ni][0], v1 = acc[mi][ni][1];
            float v2 = acc[mi][ni][2], v3 = acc[mi][ni][3];
            if (MODE == 3) {
                const float m0 = mc[col], m1 = mc[col + 1];
                v0 -= m0; v1 -= m1; v2 -= m0; v3 -= m1;
            }
            *(float2*)(outp + (size_t)row0 * DD + col)       = make_float2(v0, v1);
            *(float2*)(outp + (size_t)(row0 + 8) * DD + col) = make_float2(v2, v3);
        }
    }
}

// ---------------------------------------------------------------------------
// split / transpose / reduction kernels
// ---------------------------------------------------------------------------
__global__ void split_rows2_kernel(const float* __restrict__ in,
                                   bf16* __restrict__ s0, bf16* __restrict__ s1,
                                   int n4) {
    int idx = blockIdx.x * 256 + threadIdx.x;
    if (idx >= n4) return;
    float4 v = ((const float4*)in)[idx];
    bf16 h0, l0, h1, l1, h2, l2, h3, l3;
    split2(v.x, h0, l0); split2(v.y, h1, l1);
    split2(v.z, h2, l2); split2(v.w, h3, l3);
    ((uint2*)s0)[idx] = make_uint2(pack2(h0, h1), pack2(h2, h3));
    ((uint2*)s1)[idx] = make_uint2(pack2(l0, l1), pack2(l2, l3));
}

__global__ void split_trans2_kernel(const float* __restrict__ src,
                                    bf16* __restrict__ t0, bf16* __restrict__ t1,
                                    int ldout) {
    __shared__ float ts[32][33];
    const int tid = threadIdx.x;
    const int n0 = blockIdx.x * 32;
    const int d0 = blockIdx.y * 32;
    int r = tid >> 3, c = (tid & 7) * 4;
    float4 v = *(const float4*)(src + (size_t)(n0 + r) * DD + d0 + c);
    ts[r][c] = v.x; ts[r][c + 1] = v.y; ts[r][c + 2] = v.z; ts[r][c + 3] = v.w;
    __syncthreads();
    int cc = tid >> 3, rr = (tid & 7) * 4;
    bf16 h[4], l[4];
#pragma unroll
    for (int i = 0; i < 4; i++) split2(ts[rr + i][cc], h[i], l[i]);
    size_t off = (size_t)(d0 + cc) * ldout + n0 + rr;
    *(uint2*)(t0 + off) = make_uint2(pack2(h[0], h[1]), pack2(h[2], h[3]));
    *(uint2*)(t1 + off) = make_uint2(pack2(l[0], l[1]), pack2(l[2], l[3]));
}

__global__ void colsum_kernel(const float* __restrict__ H) {
    const int b = blockIdx.x;
    const int t = threadIdx.x;
    const float* p = H + (size_t)b * 256 * DD + t;
    float s = 0.f;
#pragma unroll 8
    for (int r = 0; r < 256; r++) s += p[(size_t)r * DD];
    g_colpart[b * DD + t] = s;
}

// ---------------------------------------------------------------------------
// Persistent per-layer chain. L0 also computes mean + Sigma_c(x) first.
// ---------------------------------------------------------------------------
__device__ __forceinline__ void gridbar() {
    __syncthreads();
    if (threadIdx.x == 0) {
        __threadfence();                        // release this CTA's writes
        unsigned g = atomicAdd(&g_barGen, 0u);
        if (atomicAdd(&g_barCount, 1u) == PCTAS - 1) {
            g_barCount = 0;
            __threadfence();
            atomicAdd(&g_barGen, 1u);
        } else {
            while (atomicAdd(&g_barGen, 0u) == g) __nanosleep(64);
        }
        __threadfence();                        // acquire + L1 IVALL (whole SM)
    }
    __syncthreads();
}

// EPI: 0 = C=acc*sc ; 1 = C=acc+I/temp ; 2 = C=1.5*Pin-0.5*acc ;
//      3 = C=acc*sc - (kInvTemp*sc)*Pin
__device__ void tile_gemm(float* __restrict__ C, const float* __restrict__ A,
                          const float* __restrict__ B, const float* __restrict__ Pin,
                          float sc, int epi, int ta, int tile,
                          float (*As)[68], float (*Bs)[64]) {
    const int tid = threadIdx.x;
    const int tx = tid & 15;
    const int ty = tid >> 4;
    const int r0 = (tile >> 3) * 64;
    const int c0 = (tile & 7) * 64;

    u64 acc[4][2];
#pragma unroll
    for (int r = 0; r < 4; r++)
#pragma unroll
        for (int j = 0; j < 2; j++) acc[r][j] = 0ull;

    for (int k0 = 0; k0 < DD; k0 += 16) {
        if (ta == 0) {
            int r = tid >> 2, c = (tid & 3) << 2;
            float4 v = *(const float4*)(A + (size_t)(r0 + r) * DD + k0 + c);
            As[c + 0][r] = v.x; As[c + 1][r] = v.y;
            As[c + 2][r] = v.z; As[c + 3][r] = v.w;
        } else {
            int r = tid >> 4, c = (tid & 15) << 2;
            float4 v = *(const float4*)(A + (size_t)(k0 + r) * DD + r0 + c);
            *(float4*)&As[r][c] = v;
        }
        {
            int r = tid >> 4, c = (tid & 15) << 2;
            *(float4*)&Bs[r][c] = *(const float4*)(B + (size_t)(k0 + r) * DD + c0 + c);
        }
        __syncthreads();
#pragma unroll
        for (int kk = 0; kk < 16; kk++) {
            float4 a0 = *(const float4*)&As[kk][ty * 4];
            u64 a2[4];
            a2[0] = dup2(a0.x); a2[1] = dup2(a0.y);
            a2[2] = dup2(a0.z); a2[3] = dup2(a0.w);
            u64 b2[2];
#pragma unroll
            for (int j = 0; j < 2; j++)
                b2[j] = *(const u64*)&Bs[kk][(j * 16 + tx) * 2];
#pragma unroll
            for (int r = 0; r < 4; r++)
#pragma unroll
                for (int j = 0; j < 2; j++) ffma2(acc[r][j], a2[r], b2[j]);
        }
        __syncthreads();
    }
#pragma unroll
    for (int r = 0; r < 4; r++) {
#pragma unroll
        for (int j = 0; j < 2; j++) {
            float2 f = upk2(acc[r][j]);
            const int row = r0 + ty * 4 + r;
            const int col = c0 + (j * 16 + tx) * 2;
            if (epi == 0) {
                f.x *= sc; f.y *= sc;
            } else if (epi == 1) {
                if (row == col)     f.x += kInvTemp;
                if (row == col + 1) f.y += kInvTemp;
            } else if (epi == 2) {
                f.x = 1.5f * Pin[(size_t)row * DD + col]     - 0.5f * f.x;
                f.y = 1.5f * Pin[(size_t)row * DD + col + 1] - 0.5f * f.y;
            } else {
                const float cc2 = kInvTemp * sc;
                f.x = f.x * sc - cc2 * Pin[(size_t)row * DD + col];
                f.y = f.y * sc - cc2 * Pin[(size_t)row * DD + col + 1];
            }
            *(float2*)(C + (size_t)row * DD + col) = f;
        }
    }
}

__global__ __launch_bounds__(256)
void persist_chain(const float* __restrict__ W, bf16* __restrict__ w0,
                   bf16* __restrict__ w1, float* __restrict__ mc,
                   const float* __restrict__ MeffPrev,
                   float* __restrict__ MeffOut, int isL0) {
    __shared__ __align__(16) float As[16][68];
    __shared__ __align__(16) float Bs[16][64];
    __shared__ float red[256];
    float (*tsub)[33] = (float(*)[33])&As[0][0];

    const int tile = blockIdx.x;
    const int tid = threadIdx.x;
    const int lane = tid & 31;

    if (isL0) {
        // pre-A: mean from colpart (64 CTAs x 8 warps = 512 columns)
        if (tile < 64) {
            const int col = tile * 8 + (tid >> 5);
            float s = 0.f;
            for (int b = lane; b < 256; b += 32) s += g_colpart[b * DD + col];
#pragma unroll
            for (int o = 16; o > 0; o >>= 1)
                s += __shfl_down_sync(0xffffffffu, s, o);
            if (lane == 0) g_mean[col] = s * (1.0f / (float)NROWS);
        }
        gridbar();
        // pre-B: Sig = sum(covpart)/N - mean_i mean_j (mirror upper tiles)
#pragma unroll
        for (int q = 0; q < 8; q++) {
            int idx = tile * 2048 + q * 256 + tid;
            int i = idx >> 9, j = idx & (DD - 1);
            int src = ((i >> 7) <= (j >> 7)) ? (i * DD + j) : (j * DD + i);
            float s = 0.f;
#pragma unroll
            for (int z = 0; z < NSPLIT; z++)
                s += g_covpart[(size_t)z * DD * DD + src];
            g_sig[idx] = s * (1.0f / (float)NROWS) - g_mean[i] * g_mean[j];
        }
        gridbar();
    }

    // s0: T1 = Sig @ W
    if (tile < 64) tile_gemm(g_T1, g_sig, W, nullptr, 1.0f, 0, 0, tile, As, Bs);
    gridbar();
    // s1: cov = W^T @ T1 + I/temp
    if (tile < 64) tile_gemm(g_cov, W, g_T1, nullptr, 1.0f, 1, 1, tile, As, Bs);
    gridbar();
    // s2: trace -> scal
    if (tile == 0) {
        float s = g_cov[(size_t)(2 * tid) * (DD + 1)]
                + g_cov[(size_t)(2 * tid + 1) * (DD + 1)];
        red[tid] = s;
        __syncthreads();
        for (int k = 128; k > 0; k >>= 1) {
            if (tid < k) red[tid] += red[tid + k];
            __syncthreads();
        }
        if (tid == 0) {
            float tr = red[0];
            g_scal[0] = 1.0f / tr;
            g_scal[1] = 1.0f / sqrtf(tr);
        }
    }
    gridbar();
    // s3: P0 = 1.5 I - 0.5 cov/tr
    {
        const float s0 = g_scal[0];
#pragma unroll
        for (int q = 0; q < 8; q++) {
            int idx = tile * 2048 + q * 256 + tid;
            int i = idx >> 9, j = idx & (DD - 1);
            g_P0[idx] = ((i == j) ? 1.5f : 0.0f) - 0.5f * g_cov[idx] * s0;
        }
    }
    gridbar();

    float* P = g_P0;
    float* Pn = g_P1;
    for (int it = 1; it < 10; it++) {
        if (tile < 64) tile_gemm(g_A1, P, P, nullptr, 1.0f, 0, 0, tile, As, Bs);
        else           tile_gemm(g_A2, P, g_cov, nullptr, g_scal[0], 0, 0, tile - 64, As, Bs);
        gridbar();
        if (tile < 64) tile_gemm(Pn, g_A1, g_A2, P, 1.0f, 2, 0, tile, As, Bs);
        gridbar();
        float* t = P; P = Pn; Pn = t;
    }

    // f1: B = (P@cov)*s0 - (kInvTemp*s0)*P  (tiles 0-63, into g_A2)
    //     M = (W@P)*s1                      (tiles 64-127)
    if (tile < 64) tile_gemm(g_A2, P, g_cov, P, g_scal[0], 3, 0, tile, As, Bs);
    else           tile_gemm(g_M, W, P, nullptr, g_scal[1], 0, 0, tile - 64, As, Bs);
    gridbar();
    // f2: Sig' = P@B (tiles 0-63) ; Meff = MeffPrev@M or copy M (tiles 64-127)
    if (tile < 64) {
        tile_gemm(g_sig, P, g_A2, nullptr, 1.0f, 0, 0, tile, As, Bs);
    } else if (isL0) {
#pragma unroll
        for (int q = 0; q < 16; q++) {
            int idx = (tile - 64) * 4096 + q * 256 + tid;
            MeffOut[idx] = g_M[idx];
        }
    } else {
        tile_gemm(MeffOut, MeffPrev, g_M, nullptr, 1.0f, 0, 0, tile - 64, As, Bs);
    }
    gridbar();
    // f3: Meff^T split -> w0/w1 (tiles 0-63); mc = mean@Meff (tiles 64-127)
    if (tile < 64) {
        const int br = tile >> 3, bc = tile & 7;
#pragma unroll
        for (int sj = 0; sj < 2; sj++)
#pragma unroll
            for (int si = 0; si < 2; si++) {
                int r = tid >> 3, c = (tid & 7) * 4;
                float4 v = *(const float4*)(MeffOut + (size_t)(br * 64 + si * 32 + r) * DD
                                            + bc * 64 + sj * 32 + c);
                tsub[r][c] = v.x; tsub[r][c + 1] = v.y;
                tsub[r][c + 2] = v.z; tsub[r][c + 3] = v.w;
                __syncthreads();
                int cc = tid >> 3, rr = (tid & 7) * 4;
                bf16 h[4], l[4];
#pragma unroll
                for (int i = 0; i < 4; i++) split2(tsub[rr + i][cc], h[i], l[i]);
                size_t off = (size_t)(bc * 64 + sj * 32 + cc) * DD + br * 64 + si * 32 + rr;
                *(uint2*)(w0 + off) = make_uint2(pack2(h[0], h[1]), pack2(h[2], h[3]));
                *(uint2*)(w1 + off) = make_uint2(pack2(l[0], l[1]), pack2(l[2], l[3]));
                __syncthreads();
            }
    } else {
        const int col = (tile - 64) * 8 + (tid >> 5);
        float s = 0.f;
        for (int k = lane; k < DD; k += 32)
            s += g_mean[k] * MeffOut[(size_t)k * DD + col];
#pragma unroll
        for (int o = 16; o > 0; o >>= 1)
            s += __shfl_down_sync(0xffffffffu, s, o);
        if (lane == 0) mc[col] = s;
    }
}

// ---------------------------------------------------------------------------
// orchestration — chain L0 is our 4th submitted launch (ncu target).
// Streams/events created once (capture call does zero driver allocations).
// ---------------------------------------------------------------------------
static cudaStream_t s2, sO1, sO2;
static cudaEvent_t evRoot, evGram, evSplit, evM[3], evO1, evO2;
static bool g_inited = false;

extern "C" void kernel_launch(void* const* d_in, const int* in_sizes, int n_in,
                              void* d_out, int out_size) {
    (void)in_sizes; (void)n_in; (void)out_size;
    const float* x = (const float*)d_in[0];
    const float* W[3] = {(const float*)d_in[1], (const float*)d_in[2],
                         (const float*)d_in[3]};
    float* out = (float*)d_out;

    float *pcovpart, *pmc, *pMA, *pMB;
    bf16 *psA0, *psA1, *pt0, *pt1, *pw0, *pw1;
    cudaGetSymbolAddress((void**)&pcovpart, g_covpart);
    cudaGetSymbolAddress((void**)&pmc, g_mcv);
    cudaGetSymbolAddress((void**)&pMA, g_MeffA);
    cudaGetSymbolAddress((void**)&pMB, g_MeffB);
    cudaGetSymbolAddress((void**)&psA0, g_sA0);
    cudaGetSymbolAddress((void**)&psA1, g_sA1);
    cudaGetSymbolAddress((void**)&pt0, g_t0);
    cudaGetSymbolAddress((void**)&pt1, g_t1);
    cudaGetSymbolAddress((void**)&pw0, g_w0);
    cudaGetSymbolAddress((void**)&pw1, g_w1);

    if (!g_inited) {
        g_inited = true;
        cudaFuncSetAttribute(mma_gemm<2>, cudaFuncAttributeMaxDynamicSharedMemorySize, SMEMSZ);
        cudaFuncSetAttribute(mma_gemm<3>, cudaFuncAttributeMaxDynamicSharedMemorySize, SMEMSZ);
        cudaStreamCreateWithFlags(&s2, cudaStreamNonBlocking);
        cudaStreamCreateWithFlags(&sO1, cudaStreamNonBlocking);
        cudaStreamCreateWithFlags(&sO2, cudaStreamNonBlocking);
        cudaEventCreateWithFlags(&evRoot, cudaEventDisableTiming);
        cudaEventCreateWithFlags(&evGram, cudaEventDisableTiming);
        cudaEventCreateWithFlags(&evSplit, cudaEventDisableTiming);
        for (int i = 0; i < 3; i++)
            cudaEventCreateWithFlags(&evM[i], cudaEventDisableTiming);
        cudaEventCreateWithFlags(&evO1, cudaEventDisableTiming);
        cudaEventCreateWithFlags(&evO2, cudaEventDisableTiming);
    }

    const int N4BIG = NROWS * DD / 4;
    const dim3 gact(4, NROWS / 128);
    const dim3 gcov(10, 1, NSPLIT);

    // #1 split_trans on origin stream; fork s2 via evRoot
    split_trans2_kernel<<<dim3(NROWS / 32, 16), 256>>>(x, pt0, pt1, NROWS);     // #1
    cudaEventRecord(evRoot, 0);
    cudaStreamWaitEvent(s2, evRoot, 0);

    colsum_kernel<<<256, 512, 0, s2>>>(x);                                      // #2
    mma_gemm<2><<<gcov, 256, SMEMSZ>>>(pt0, pt1, pt0, pt1, pcovpart, nullptr);  // #3 (Gram)
    cudaEventRecord(evGram, 0);

    // #4 = persist_chain L0 (ncu target). Needs colsum (same stream) + Gram.
    cudaStreamWaitEvent(s2, evGram, 0);
    persist_chain<<<PCTAS, 256, 0, s2>>>(W[0], pw0, pw1, pmc,
                                         nullptr, pMA, 1);                      // #4
    cudaEventRecord(evM[0], s2);

    split_rows2_kernel<<<N4BIG / 256, 256>>>(x, psA0, psA1, N4BIG);             // #5
    cudaEventRecord(evSplit, 0);

    persist_chain<<<PCTAS, 256, 0, s2>>>(W[1], pw0 + (size_t)DD * DD,
                                         pw1 + (size_t)DD * DD, pmc + DD,
                                         pMA, pMB, 0);                          // #6
    cudaEventRecord(evM[1], s2);
    persist_chain<<<PCTAS, 256, 0, s2>>>(W[2], pw0 + (size_t)2 * DD * DD,
                                         pw1 + (size_t)2 * DD * DD, pmc + 2 * DD,
                                         pMB, pMA, 0);                          // #7
    cudaEventRecord(evM[2], s2);

    // out-GEMMs: all read x splits; independent streams
    cudaStreamWaitEvent(0, evM[0], 0);
    mma_gemm<3><<<gact, 256, SMEMSZ>>>(psA0, psA1, pw0, pw1, out, pmc);         // #8

    cudaStreamWaitEvent(sO1, evSplit, 0);
    cudaStreamWaitEvent(sO1, evM[1], 0);
    mma_gemm<3><<<gact, 256, SMEMSZ, sO1>>>(psA0, psA1,
                                            pw0 + (size_t)DD * DD,
                                            pw1 + (size_t)DD * DD,
                                            out + (size_t)NROWS * DD, pmc + DD); // #9
    cudaEventRecord(evO1, sO1);

    cudaStreamWaitEvent(sO2, evSplit, 0);
    cudaStreamWaitEvent(sO2, evM[2], 0);
    mma_gemm<3><<<gact, 256, SMEMSZ, sO2>>>(psA0, psA1,
                                            pw0 + (size_t)2 * DD * DD,
                                            pw1 + (size_t)2 * DD * DD,
                                            out + (size_t)2 * NROWS * DD,
                                            pmc + 2 * DD);                       // #10
    cudaEventRecord(evO2, sO2);

    cudaStreamWaitEvent(0, evO1, 0);
    cudaStreamWaitEvent(0, evO2, 0);
}

// round 15
// speedup vs baseline: 1.9459x; 1.2609x over previous
#include <cuda_runtime.h>
#include <cuda_bf16.h>
#include <math.h>
#include <stdint.h>

#define NROWS 65536
#define DD    512
#define NSPLIT 29
#define KCHTOT 2048
#define PCTAS 128
static __device__ __constant__ float kInvTemp = 0.1f;

typedef unsigned long long u64;
typedef __nv_bfloat16 bf16;

// ---------------------------------------------------------------------------
// helpers
// ---------------------------------------------------------------------------
__device__ __forceinline__ uint32_t smem_u32(const void* p) {
    uint32_t a;
    asm("{ .reg .u64 t; cvta.to.shared.u64 t, %1; cvt.u32.u64 %0, t; }"
        : "=r"(a) : "l"(p));
    return a;
}
__device__ __forceinline__ void cp16(uint32_t dst, const void* src) {
    asm volatile("cp.async.cg.shared.global [%0], [%1], 16;"
                 :: "r"(dst), "l"(src) : "memory");
}
__device__ __forceinline__ void mma16816(float* c, const uint32_t* a,
                                         const uint32_t* b) {
    asm volatile(
        "mma.sync.aligned.m16n8k16.row.col.f32.bf16.bf16.f32 "
        "{%0,%1,%2,%3}, {%4,%5,%6,%7}, {%8,%9}, {%0,%1,%2,%3};"
        : "+f"(c[0]), "+f"(c[1]), "+f"(c[2]), "+f"(c[3])
        : "r"(a[0]), "r"(a[1]), "r"(a[2]), "r"(a[3]), "r"(b[0]), "r"(b[1]));
}
__device__ __forceinline__ void ldsm4(uint32_t* r, uint32_t addr) {
    asm volatile("ldmatrix.sync.aligned.m8n8.x4.shared.b16 {%0,%1,%2,%3}, [%4];"
                 : "=r"(r[0]), "=r"(r[1]), "=r"(r[2]), "=r"(r[3]) : "r"(addr));
}
__device__ __forceinline__ int sw(int r, int k) {
    int s = ((k >> 3) ^ (r & 3) ^ ((r >> 2) & 1)) & 3;
    return r * 64 + s * 16 + (k & 7) * 2;
}
__device__ __forceinline__ void split2(float x, bf16 &hi, bf16 &lo) {
    hi = __float2bfloat16_rn(x);
    lo = __float2bfloat16_rn(x - __bfloat162float(hi));
}
__device__ __forceinline__ uint32_t pack2(bf16 a, bf16 b) {
    __nv_bfloat162 v(a, b);
    return *reinterpret_cast<uint32_t*>(&v);
}
__device__ __forceinline__ void ffma2(u64 &d, u64 a, u64 b) {
    asm("fma.rn.f32x2 %0, %1, %2, %0;" : "+l"(d) : "l"(a), "l"(b));
}
__device__ __forceinline__ float2 upk2(u64 v) {
    float2 r;
    asm("mov.b64 {%0, %1}, %2;" : "=f"(r.x), "=f"(r.y) : "l"(v));
    return r;
}
__device__ __forceinline__ u64 dup2(float x) {
    u64 r;
    asm("mov.b64 %0, {%1, %1};" : "=l"(r) : "f"(x));
    return r;
}

// ---------------------------------------------------------------------------
// scratch
// ---------------------------------------------------------------------------
__device__ float g_colpart[256 * DD];
__device__ float g_mean[DD];
__device__ float g_mcv[3 * DD];
__device__ float g_covpart[(size_t)NSPLIT * DD * DD];
__device__ float g_sig[DD * DD];
__device__ float g_cov[DD * DD];
__device__ float g_T1[DD * DD];
__device__ float g_M[DD * DD];
__device__ float g_MeffA[DD * DD];
__device__ float g_MeffB[DD * DD];
__device__ float g_P0[DD * DD];
__device__ float g_P1[DD * DD];
__device__ float g_A1[DD * DD];
__device__ float g_A2[DD * DD];
__device__ float g_scal[2];
__device__ unsigned g_barCount;
__device__ unsigned g_barGen;
__device__ bf16 g_sA0[(size_t)NROWS * DD];
__device__ bf16 g_sA1[(size_t)NROWS * DD];
__device__ bf16 g_t0[(size_t)DD * NROWS];
__device__ bf16 g_t1[(size_t)DD * NROWS];
__device__ bf16 g_w0[3 * DD * DD];
__device__ bf16 g_w1[3 * DD * DD];

__constant__ int cTI[10] = {0,0,0,0,1,1,1,2,2,3};
__constant__ int cTJ[10] = {0,1,2,3,1,2,3,2,3,3};

// ---------------------------------------------------------------------------
// Big bf16-split mma.sync GEMM (unchanged, round-10 proven)
// ---------------------------------------------------------------------------
#define STAGE_BYTES 32768
#define SMEMSZ (2 * STAGE_BYTES)

template <int MODE>
__global__ __launch_bounds__(256, 2)
void mma_gemm(const bf16* __restrict__ a0g, const bf16* __restrict__ a1g,
              const bf16* __restrict__ b0g, const bf16* __restrict__ b1g,
              float* __restrict__ out, const float* __restrict__ mc) {
    constexpr int LD = (MODE == 2) ? NROWS : DD;

    extern __shared__ __align__(128) char sm[];
    const uint32_t smb = smem_u32(sm);

    const int tid = threadIdx.x;
    const int lane = tid & 31, wid = tid >> 5;
    const int warpRow = wid & 1;
    const int warpCol = wid >> 1;
    const int g = lane >> 2, t4 = lane & 3;
    const int laneRow = lane & 7, grp = lane >> 3;

    int rowBase, colBase, nch;
    size_t kStart;
    float* outp;
    if (MODE == 2) {
        rowBase = cTI[blockIdx.x] * 128;
        colBase = cTJ[blockIdx.x] * 128;
        int c0 = (int)((size_t)blockIdx.z * KCHTOT / NSPLIT);
        int c1 = (int)((size_t)(blockIdx.z + 1) * KCHTOT / NSPLIT);
        kStart = (size_t)c0 * 32;
        nch = c1 - c0;
        outp = out + (size_t)blockIdx.z * DD * DD;
    } else {
        rowBase = blockIdx.y * 128;
        colBase = blockIdx.x * 128;
        kStart = 0;
        nch = DD / 32;
        outp = out;
    }

    float acc[4][4][4];
#pragma unroll
    for (int mi = 0; mi < 4; mi++)
#pragma unroll
        for (int ni = 0; ni < 4; ni++)
#pragma unroll
            for (int q = 0; q < 4; q++) acc[mi][ni][q] = 0.f;

    uint32_t aOff[4], bOff[2];
#pragma unroll
    for (int mi = 0; mi < 4; mi++)
        aOff[mi] = sw(warpRow * 64 + mi * 16 + (grp & 1) * 8 + laneRow, (grp >> 1) * 8);
#pragma unroll
    for (int p = 0; p < 2; p++)
        bOff[p] = sw(warpCol * 32 + p * 16 + (grp >> 1) * 8 + laneRow, (grp & 1) * 8);

    const int lr = tid >> 2;
    const int lseg = tid & 3;

    auto load_chunk = [&](int ch, int stage) {
        const size_t kpos = kStart + (size_t)ch * 32;
        const uint32_t sb = smb + stage * STAGE_BYTES;
#pragma unroll
        for (int i = 0; i < 2; i++) {
            const int r = lr + i * 64;
            const int soff = sw(r, lseg * 8);
            const size_t ga = (size_t)(rowBase + r) * LD + kpos + lseg * 8;
            const size_t gb = (size_t)(colBase + r) * LD + kpos + lseg * 8;
            cp16(sb + soff,         a0g + ga);
            cp16(sb + 8192 + soff,  a1g + ga);
            cp16(sb + 16384 + soff, b0g + gb);
            cp16(sb + 24576 + soff, b1g + gb);
        }
        asm volatile("cp.async.commit_group;" ::: "memory");
    };

    load_chunk(0, 0);

    for (int ch = 0; ch < nch; ch++) {
        if (ch + 1 < nch) {
            load_chunk(ch + 1, (ch + 1) & 1);
            asm volatile("cp.async.wait_group 1;" ::: "memory");
        } else {
            asm volatile("cp.async.wait_group 0;" ::: "memory");
        }
        __syncthreads();

        const uint32_t sA0 = smb + (ch & 1) * STAGE_BYTES;
        const uint32_t sA1 = sA0 + 8192;
        const uint32_t sB0 = sA0 + 16384;
        const uint32_t sB1 = sA0 + 24576;

#pragma unroll
        for (int ks = 0; ks < 2; ks++) {
            const uint32_t kx = ks * 32;
            uint32_t fa0[4][4], fa1[4][4], fb0[2][4], fb1[2][4];
#pragma unroll
            for (int mi = 0; mi < 4; mi++) {
                ldsm4(fa0[mi], sA0 + (aOff[mi] ^ kx));
                ldsm4(fa1[mi], sA1 + (aOff[mi] ^ kx));
            }
#pragma unroll
            for (int p = 0; p < 2; p++) {
                ldsm4(fb0[p], sB0 + (bOff[p] ^ kx));
                ldsm4(fb1[p], sB1 + (bOff[p] ^ kx));
            }
#pragma unroll
            for (int t = 0; t < 3; t++) {
#pragma unroll
                for (int ni = 0; ni < 4; ni++) {
                    const uint32_t* bb =
                        (t == 1) ? &fb1[ni >> 1][(ni & 1) * 2]
                                 : &fb0[ni >> 1][(ni & 1) * 2];
#pragma unroll
                    for (int mi = 0; mi < 4; mi++) {
                        const uint32_t* aa = (t == 2) ? fa1[mi] : fa0[mi];
                        mma16816(acc[mi][ni], aa, bb);
                    }
                }
            }
        }
        __syncthreads();
    }

#pragma unroll
    for (int mi = 0; mi < 4; mi++) {
        const int row0 = rowBase + warpRow * 64 + mi * 16 + g;
#pragma unroll
        for (int ni = 0; ni < 4; ni++) {
            const int col = colBase + warpCol * 32 + ni * 8 + t4 * 2;
            float v0 = acc[mi][ni][0], v1 = acc[mi][ni][1];
            float v2 = acc[mi][ni][2], v3 = acc[mi][ni][3];
            if (MODE == 3) {
                const float m0 = mc[col], m1 = mc[col + 1];
                v0 -= m0; v1 -= m1; v2 -= m0; v3 -= m1;
            }
            *(float2*)(outp + (size_t)row0 * DD + col)       = make_float2(v0, v1);
            *(float2*)(outp + (size_t)(row0 + 8) * DD + col) = make_float2(v2, v3);
        }
    }
}

// ---------------------------------------------------------------------------
// split / transpose / reduction kernels
// ---------------------------------------------------------------------------
__global__ void split_rows2_kernel(const float* __restrict__ in,
                                   bf16* __restrict__ s0, bf16* __restrict__ s1,
                                   int n4) {
    int idx = blockIdx.x * 256 + threadIdx.x;
    if (idx >= n4) return;
    float4 v = ((const float4*)in)[idx];
    bf16 h0, l0, h1, l1, h2, l2, h3, l3;
    split2(v.x, h0, l0); split2(v.y, h1, l1);
    split2(v.z, h2, l2); split2(v.w, h3, l3);
    ((uint2*)s0)[idx] = make_uint2(pack2(h0, h1), pack2(h2, h3));
    ((uint2*)s1)[idx] = make_uint2(pack2(l0, l1), pack2(l2, l3));
}

__global__ void split_trans2_kernel(const float* __restrict__ src,
                                    bf16* __restrict__ t0, bf16* __restrict__ t1,
                                    int ldout) {
    __shared__ float ts[32][33];
    const int tid = threadIdx.x;
    const int n0 = blockIdx.x * 32;
    const int d0 = blockIdx.y * 32;
    int r = tid >> 3, c = (tid & 7) * 4;
    float4 v = *(const float4*)(src + (size_t)(n0 + r) * DD + d0 + c);
    ts[r][c] = v.x; ts[r][c + 1] = v.y; ts[r][c + 2] = v.z; ts[r][c + 3] = v.w;
    __syncthreads();
    int cc = tid >> 3, rr = (tid & 7) * 4;
    bf16 h[4], l[4];
#pragma unroll
    for (int i = 0; i < 4; i++) split2(ts[rr + i][cc], h[i], l[i]);
    size_t off = (size_t)(d0 + cc) * ldout + n0 + rr;
    *(uint2*)(t0 + off) = make_uint2(pack2(h[0], h[1]), pack2(h[2], h[3]));
    *(uint2*)(t1 + off) = make_uint2(pack2(l[0], l[1]), pack2(l[2], l[3]));
}

__global__ void colsum_kernel(const float* __restrict__ H) {
    const int b = blockIdx.x;
    const int t = threadIdx.x;
    const float* p = H + (size_t)b * 256 * DD + t;
    float s = 0.f;
#pragma unroll 8
    for (int r = 0; r < 256; r++) s += p[(size_t)r * DD];
    g_colpart[b * DD + t] = s;
}

// ---------------------------------------------------------------------------
// Persistent per-layer chain with pipelined tile GEMM (BK=32, cp.async B,
// reg-double-buffered A).
// ---------------------------------------------------------------------------
__device__ __forceinline__ void gridbar() {
    __syncthreads();
    if (threadIdx.x == 0) {
        __threadfence();
        unsigned g = atomicAdd(&g_barGen, 0u);
        if (atomicAdd(&g_barCount, 1u) == PCTAS - 1) {
            g_barCount = 0;
            __threadfence();
            atomicAdd(&g_barGen, 1u);
        } else {
            while (atomicAdd(&g_barGen, 0u) == g) __nanosleep(64);
        }
        __threadfence();
    }
    __syncthreads();
}

// Pipelined 64xTN tile GEMM over K=512, BK=32, double-buffered.
// EPI: 0 C=acc*sc ; 1 C=acc+I/temp ; 2 C=1.5*Pin-0.5*acc ; 3 C=acc*sc-(kInvTemp*sc)*Pin
template <int TN>
__device__ void tgemm(float* __restrict__ C, const float* __restrict__ A,
                      const float* __restrict__ B, const float* __restrict__ Pin,
                      float sc, int epi, int ta, int r0, int c0,
                      float (*As)[68], float (*Bs)[64], uint32_t bsAddr) {
    constexpr int NP = TN / 32;          // f32x2 col-pair groups per thread
    const int tid = threadIdx.x;
    const int tx = tid & 15;
    const int ty = tid >> 4;

    u64 acc[4][NP];
#pragma unroll
    for (int r = 0; r < 4; r++)
#pragma unroll
        for (int j = 0; j < NP; j++) acc[r][j] = 0ull;

    float4 areg[2];
    auto loadA = [&](int ch) {
        const int k0 = ch * 32;
        if (ta == 0) {
#pragma unroll
            for (int i = 0; i < 2; i++) {
                int idx = tid * 2 + i;
                int r = idx >> 3, c4 = idx & 7;
                areg[i] = *(const float4*)(A + (size_t)(r0 + r) * DD + k0 + c4 * 4);
            }
        } else {
#pragma unroll
            for (int i = 0; i < 2; i++) {
                int idx = tid * 2 + i;
                int k = idx >> 4, m4 = idx & 15;
                areg[i] = *(const float4*)(A + (size_t)(k0 + k) * DD + r0 + m4 * 4);
            }
        }
    };
    auto storeA = [&](int buf) {
        if (ta == 0) {
#pragma unroll
            for (int i = 0; i < 2; i++) {
                int idx = tid * 2 + i;
                int r = idx >> 3, k = (idx & 7) * 4;
                As[buf * 32 + k + 0][r] = areg[i].x;
                As[buf * 32 + k + 1][r] = areg[i].y;
                As[buf * 32 + k + 2][r] = areg[i].z;
                As[buf * 32 + k + 3][r] = areg[i].w;
            }
        } else {
#pragma unroll
            for (int i = 0; i < 2; i++) {
                int idx = tid * 2 + i;
                int k = idx >> 4, m4 = idx & 15;
                *(float4*)&As[buf * 32 + k][m4 * 4] = areg[i];
            }
        }
    };
    auto loadB = [&](int ch, int buf) {
        const int k0 = ch * 32;
#pragma unroll
        for (int i = 0; i < NP; i++) {
            int idx = tid + i * 256;
            int k, n4;
            if (TN == 64) { k = idx >> 4; n4 = idx & 15; }
            else          { k = idx >> 3; n4 = idx & 7; }
            cp16(bsAddr + (uint32_t)(((buf * 32 + k) * 64 + n4 * 4) * 4),
                 B + (size_t)(k0 + k) * DD + c0 + n4 * 4);
        }
        asm volatile("cp.async.commit_group;" ::: "memory");
    };

    loadA(0);
    loadB(0, 0);

    for (int ch = 0; ch < 16; ch++) {
        const int buf = ch & 1;
        if (ch + 1 < 16) loadB(ch + 1, buf ^ 1);
        storeA(buf);
        if (ch + 1 < 16) loadA(ch + 1);
        if (ch + 1 < 16) asm volatile("cp.async.wait_group 1;" ::: "memory");
        else             asm volatile("cp.async.wait_group 0;" ::: "memory");
        __syncthreads();
#pragma unroll 8
        for (int kk = 0; kk < 32; kk++) {
            float4 a0 = *(const float4*)&As[buf * 32 + kk][ty * 4];
            u64 a2[4];
            a2[0] = dup2(a0.x); a2[1] = dup2(a0.y);
            a2[2] = dup2(a0.z); a2[3] = dup2(a0.w);
            u64 b2[NP];
#pragma unroll
            for (int j = 0; j < NP; j++)
                b2[j] = *(const u64*)&Bs[buf * 32 + kk][(j * 16 + tx) * 2];
#pragma unroll
            for (int r = 0; r < 4; r++)
#pragma unroll
                for (int j = 0; j < NP; j++) ffma2(acc[r][j], a2[r], b2[j]);
        }
        __syncthreads();
    }

#pragma unroll
    for (int r = 0; r < 4; r++) {
#pragma unroll
        for (int j = 0; j < NP; j++) {
            float2 f = upk2(acc[r][j]);
            const int row = r0 + ty * 4 + r;
            const int col = c0 + (j * 16 + tx) * 2;
            if (epi == 0) {
                f.x *= sc; f.y *= sc;
            } else if (epi == 1) {
                if (row == col)     f.x += kInvTemp;
                if (row == col + 1) f.y += kInvTemp;
            } else if (epi == 2) {
                f.x = 1.5f * Pin[(size_t)row * DD + col]     - 0.5f * f.x;
                f.y = 1.5f * Pin[(size_t)row * DD + col + 1] - 0.5f * f.y;
            } else {
                const float cc2 = kInvTemp * sc;
                f.x = f.x * sc - cc2 * Pin[(size_t)row * DD + col];
                f.y = f.y * sc - cc2 * Pin[(size_t)row * DD + col + 1];
            }
            *(float2*)(C + (size_t)row * DD + col) = f;
        }
    }
}

__global__ __launch_bounds__(256)
void persist_chain(const float* __restrict__ W, bf16* __restrict__ w0,
                   bf16* __restrict__ w1, float* __restrict__ mc,
                   const float* __restrict__ MeffPrev,
                   float* __restrict__ MeffOut, int isL0) {
    __shared__ __align__(16) float As[64][68];   // 2 bufs x 32 k
    __shared__ __align__(16) float Bs[64][64];
    __shared__ float red[256];
    float (*tsub)[33] = (float(*)[33])&As[0][0];
    const uint32_t bsAddr = smem_u32(Bs);

    const int tile = blockIdx.x;
    const int tid = threadIdx.x;
    const int lane = tid & 31;

    // 64-wide tile coords (t in 0..63), 32-wide coords (tile in 0..127)
    const int t64 = (tile < 64) ? tile : tile - 64;
    const int r64 = (t64 >> 3) * 64, c64 = (t64 & 7) * 64;
    const int r32 = (tile >> 4) * 64, c32 = (tile & 15) * 32;

    if (isL0) {
        if (tile < 64) {
            const int col = tile * 8 + (tid >> 5);
            float s = 0.f;
            for (int b = lane; b < 256; b += 32) s += g_colpart[b * DD + col];
#pragma unroll
            for (int o = 16; o > 0; o >>= 1)
                s += __shfl_down_sync(0xffffffffu, s, o);
            if (lane == 0) g_mean[col] = s * (1.0f / (float)NROWS);
        }
        gridbar();
#pragma unroll
        for (int q = 0; q < 8; q++) {
            int idx = tile * 2048 + q * 256 + tid;
            int i = idx >> 9, j = idx & (DD - 1);
            int src = ((i >> 7) <= (j >> 7)) ? (i * DD + j) : (j * DD + i);
            float s = 0.f;
#pragma unroll
            for (int z = 0; z < NSPLIT; z++)
                s += g_covpart[(size_t)z * DD * DD + src];
            g_sig[idx] = s * (1.0f / (float)NROWS) - g_mean[i] * g_mean[j];
        }
        gridbar();
    }

    // s0: T1 = Sig @ W  (128 x 32-wide tiles)
    tgemm<32>(g_T1, g_sig, W, nullptr, 1.0f, 0, 0, r32, c32, As, Bs, bsAddr);
    gridbar();
    // s1: cov = W^T @ T1 + I/temp
    tgemm<32>(g_cov, W, g_T1, nullptr, 1.0f, 1, 1, r32, c32, As, Bs, bsAddr);
    gridbar();
    // s2: trace -> scal
    if (tile == 0) {
        float s = g_cov[(size_t)(2 * tid) * (DD + 1)]
                + g_cov[(size_t)(2 * tid + 1) * (DD + 1)];
        red[tid] = s;
        __syncthreads();
        for (int k = 128; k > 0; k >>= 1) {
            if (tid < k) red[tid] += red[tid + k];
            __syncthreads();
        }
        if (tid == 0) {
            float tr = red[0];
            g_scal[0] = 1.0f / tr;
            g_scal[1] = 1.0f / sqrtf(tr);
        }
    }
    gridbar();
    // s3: P0 = 1.5 I - 0.5 cov/tr
    {
        const float s0 = g_scal[0];
#pragma unroll
        for (int q = 0; q < 8; q++) {
            int idx = tile * 2048 + q * 256 + tid;
            int i = idx >> 9, j = idx & (DD - 1);
            g_P0[idx] = ((i == j) ? 1.5f : 0.0f) - 0.5f * g_cov[idx] * s0;
        }
    }
    gridbar();

    float* P = g_P0;
    float* Pn = g_P1;
    for (int it = 1; it < 10; it++) {
        if (tile < 64)
            tgemm<64>(g_A1, P, P, nullptr, 1.0f, 0, 0, r64, c64, As, Bs, bsAddr);
        else
            tgemm<64>(g_A2, P, g_cov, nullptr, g_scal[0], 0, 0, r64, c64, As, Bs, bsAddr);
        gridbar();
        tgemm<32>(Pn, g_A1, g_A2, P, 1.0f, 2, 0, r32, c32, As, Bs, bsAddr);
        gridbar();
        float* t = P; P = Pn; Pn = t;
    }

    // f1: B = (P@cov)*s0 - (kInvTemp*s0)*P (tiles 0-63) ; M = (W@P)*s1 (64-127)
    if (tile < 64)
        tgemm<64>(g_A2, P, g_cov, P, g_scal[0], 3, 0, r64, c64, As, Bs, bsAddr);
    else
        tgemm<64>(g_M, W, P, nullptr, g_scal[1], 0, 0, r64, c64, As, Bs, bsAddr);
    gridbar();
    // f2: Sig' = P@B (0-63) ; Meff = MeffPrev@M or copy (64-127)
    if (tile < 64) {
        tgemm<64>(g_sig, P, g_A2, nullptr, 1.0f, 0, 0, r64, c64, As, Bs, bsAddr);
    } else if (isL0) {
#pragma unroll
        for (int q = 0; q < 16; q++) {
            int idx = (tile - 64) * 4096 + q * 256 + tid;
            MeffOut[idx] = g_M[idx];
        }
    } else {
        tgemm<64>(MeffOut, MeffPrev, g_M, nullptr, 1.0f, 0, 0, r64, c64, As, Bs, bsAddr);
    }
    gridbar();
    // f3: Meff^T split -> w0/w1 (0-63) ; mc = mean@Meff (64-127)
    if (tile < 64) {
        const int br = t64 >> 3, bc = t64 & 7;
#pragma unroll
        for (int sj = 0; sj < 2; sj++)
#pragma unroll
            for (int si = 0; si < 2; si++) {
                int r = tid >> 3, c = (tid & 7) * 4;
                float4 v = *(const float4*)(MeffOut + (size_t)(br * 64 + si * 32 + r) * DD
                                            + bc * 64 + sj * 32 + c);
                tsub[r][c] = v.x; tsub[r][c + 1] = v.y;
                tsub[r][c + 2] = v.z; tsub[r][c + 3] = v.w;
                __syncthreads();
                int cc = tid >> 3, rr = (tid & 7) * 4;
                bf16 h[4], l[4];
#pragma unroll
                for (int i = 0; i < 4; i++) split2(tsub[rr + i][cc], h[i], l[i]);
                size_t off = (size_t)(bc * 64 + sj * 32 + cc) * DD + br * 64 + si * 32 + rr;
                *(uint2*)(w0 + off) = make_uint2(pack2(h[0], h[1]), pack2(h[2], h[3]));
                *(uint2*)(w1 + off) = make_uint2(pack2(l[0], l[1]), pack2(l[2], l[3]));
                __syncthreads();
            }
    } else {
        const int col = (tile - 64) * 8 + (tid >> 5);
        float s = 0.f;
        for (int k = lane; k < DD; k += 32)
            s += g_mean[k] * MeffOut[(size_t)k * DD + col];
#pragma unroll
        for (int o = 16; o > 0; o >>= 1)
            s += __shfl_down_sync(0xffffffffu, s, o);
        if (lane == 0) mc[col] = s;
    }
}

// ---------------------------------------------------------------------------
// orchestration (round-14 structure; chain L0 = our 4th launch for ncu)
// ---------------------------------------------------------------------------
static cudaStream_t s2, sO1, sO2;
static cudaEvent_t evRoot, evGram, evSplit, evM[3], evO1, evO2;
static bool g_inited = false;

extern "C" void kernel_launch(void* const* d_in, const int* in_sizes, int n_in,
                              void* d_out, int out_size) {
    (void)in_sizes; (void)n_in; (void)out_size;
    const float* x = (const float*)d_in[0];
    const float* W[3] = {(const float*)d_in[1], (const float*)d_in[2],
                         (const float*)d_in[3]};
    float* out = (float*)d_out;

    float *pcovpart, *pmc, *pMA, *pMB;
    bf16 *psA0, *psA1, *pt0, *pt1, *pw0, *pw1;
    cudaGetSymbolAddress((void**)&pcovpart, g_covpart);
    cudaGetSymbolAddress((void**)&pmc, g_mcv);
    cudaGetSymbolAddress((void**)&pMA, g_MeffA);
    cudaGetSymbolAddress((void**)&pMB, g_MeffB);
    cudaGetSymbolAddress((void**)&psA0, g_sA0);
    cudaGetSymbolAddress((void**)&psA1, g_sA1);
    cudaGetSymbolAddress((void**)&pt0, g_t0);
    cudaGetSymbolAddress((void**)&pt1, g_t1);
    cudaGetSymbolAddress((void**)&pw0, g_w0);
    cudaGetSymbolAddress((void**)&pw1, g_w1);

    if (!g_inited) {
        g_inited = true;
        cudaFuncSetAttribute(mma_gemm<2>, cudaFuncAttributeMaxDynamicSharedMemorySize, SMEMSZ);
        cudaFuncSetAttribute(mma_gemm<3>, cudaFuncAttributeMaxDynamicSharedMemorySize, SMEMSZ);
        cudaStreamCreateWithFlags(&s2, cudaStreamNonBlocking);
        cudaStreamCreateWithFlags(&sO1, cudaStreamNonBlocking);
        cudaStreamCreateWithFlags(&sO2, cudaStreamNonBlocking);
        cudaEventCreateWithFlags(&evRoot, cudaEventDisableTiming);
        cudaEventCreateWithFlags(&evGram, cudaEventDisableTiming);
        cudaEventCreateWithFlags(&evSplit, cudaEventDisableTiming);
        for (int i = 0; i < 3; i++)
            cudaEventCreateWithFlags(&evM[i], cudaEventDisableTiming);
        cudaEventCreateWithFlags(&evO1, cudaEventDisableTiming);
        cudaEventCreateWithFlags(&evO2, cudaEventDisableTiming);
    }

    const int N4BIG = NROWS * DD / 4;
    const dim3 gact(4, NROWS / 128);
    const dim3 gcov(10, 1, NSPLIT);

    split_trans2_kernel<<<dim3(NROWS / 32, 16), 256>>>(x, pt0, pt1, NROWS);     // #1
    cudaEventRecord(evRoot, 0);
    cudaStreamWaitEvent(s2, evRoot, 0);

    colsum_kernel<<<256, 512, 0, s2>>>(x);                                      // #2
    mma_gemm<2><<<gcov, 256, SMEMSZ>>>(pt0, pt1, pt0, pt1, pcovpart, nullptr);  // #3
    cudaEventRecord(evGram, 0);

    cudaStreamWaitEvent(s2, evGram, 0);
    persist_chain<<<PCTAS, 256, 0, s2>>>(W[0], pw0, pw1, pmc,
                                         nullptr, pMA, 1);                      // #4 (ncu)
    cudaEventRecord(evM[0], s2);

    split_rows2_kernel<<<N4BIG / 256, 256>>>(x, psA0, psA1, N4BIG);             // #5
    cudaEventRecord(evSplit, 0);

    persist_chain<<<PCTAS, 256, 0, s2>>>(W[1], pw0 + (size_t)DD * DD,
                                         pw1 + (size_t)DD * DD, pmc + DD,
                                         pMA, pMB, 0);                          // #6
    cudaEventRecord(evM[1], s2);
    persist_chain<<<PCTAS, 256, 0, s2>>>(W[2], pw0 + (size_t)2 * DD * DD,
                                         pw1 + (size_t)2 * DD * DD, pmc + 2 * DD,
                                         pMB, pMA, 0);                          // #7
    cudaEventRecord(evM[2], s2);

    cudaStreamWaitEvent(0, evM[0], 0);
    mma_gemm<3><<<gact, 256, SMEMSZ>>>(psA0, psA1, pw0, pw1, out, pmc);         // #8

    cudaStreamWaitEvent(sO1, evSplit, 0);
    cudaStreamWaitEvent(sO1, evM[1], 0);
    mma_gemm<3><<<gact, 256, SMEMSZ, sO1>>>(psA0, psA1,
                                            pw0 + (size_t)DD * DD,
                                            pw1 + (size_t)DD * DD,
                                            out + (size_t)NROWS * DD, pmc + DD); // #9
    cudaEventRecord(evO1, sO1);

    cudaStreamWaitEvent(sO2, evSplit, 0);
    cudaStreamWaitEvent(sO2, evM[2], 0);
    mma_gemm<3><<<gact, 256, SMEMSZ, sO2>>>(psA0, psA1,
                                            pw0 + (size_t)2 * DD * DD,
                                            pw1 + (size_t)2 * DD * DD,
                                            out + (size_t)2 * NROWS * DD,
                                            pmc + 2 * DD);                       // #10
    cudaEventRecord(evO2, sO2);

    cudaStreamWaitEvent(0, evO1, 0);
    cudaStreamWaitEvent(0, evO2, 0);
}